// round 1
// baseline (speedup 1.0000x reference)
#include <cuda_runtime.h>
#include <math.h>

#define BATCH   2
#define SEQ     2048
#define DIM     2048
#define D_INNER 4096
#define D_STATE 128
#define N_HEADS 32
#define HEADDIM 128
#define D_CONV  4
#define CHUNK   256
#define NCHUNK  (SEQ/CHUNK)                       /* 8  */
#define CONV_DIM (D_INNER + 2*D_STATE)            /* 4352 */
#define D_IN_PROJ (2*D_INNER + 2*D_STATE + N_HEADS) /* 8480 */
#define EPS 1e-5f

// ---------------- scratch (device globals, no allocation) ----------------
__device__ float g_zxbcdt[(size_t)BATCH*SEQ*D_IN_PROJ];          // in_proj output
__device__ float g_xBC  [(size_t)BATCH*SEQ*CONV_DIM];            // conv+silu output
__device__ float g_dt   [(size_t)BATCH*SEQ*N_HEADS];             // softplus dt
__device__ float g_dAcum[(size_t)BATCH*N_HEADS*SEQ];             // chunk-local inclusive cumsum of A*dt
__device__ float g_G    [(size_t)BATCH*NCHUNK*CHUNK*CHUNK];      // C @ B^T per (b,c)
__device__ float g_states   [(size_t)BATCH*NCHUNK*N_HEADS*HEADDIM*D_STATE];
__device__ float g_states_in[(size_t)BATCH*NCHUNK*N_HEADS*HEADDIM*D_STATE];
__device__ float g_y    [(size_t)BATCH*SEQ*D_INNER];             // scan output / normed

// ---------------- generic batched NT GEMM: C = A(MxK) * W(NxK)^T + bias --
// A row-major lda, W row-major ldb (both K contiguous), C row-major ldc.
__global__ __launch_bounds__(256)
void gemm_nt(const float* __restrict__ A, long lda, long sA,
             const float* __restrict__ W, long ldb, long sB,
             float* __restrict__ C, long ldc, long sC,
             int M, int N, int K, const float* __restrict__ bias)
{
    __shared__ float As[16][68];
    __shared__ float Bs[16][68];
    int bz = blockIdx.z;
    const float* Ab = A + (long)bz * sA;
    const float* Wb = W + (long)bz * sB;
    float*       Cb = C + (long)bz * sC;
    int bm = blockIdx.y * 64, bn = blockIdx.x * 64;
    int tid = threadIdx.x;
    int tx = tid % 16, ty = tid / 16;
    float acc[4][4] = {};
    for (int k0 = 0; k0 < K; k0 += 16) {
        for (int i = tid; i < 64*16; i += 256) {
            int m = i / 16, k = i % 16;
            int gm = bm + m;
            As[k][m] = (gm < M) ? Ab[(long)gm*lda + k0 + k] : 0.f;
        }
        for (int i = tid; i < 64*16; i += 256) {
            int n = i / 16, k = i % 16;
            int gn = bn + n;
            Bs[k][n] = (gn < N) ? Wb[(long)gn*ldb + k0 + k] : 0.f;
        }
        __syncthreads();
        #pragma unroll
        for (int k = 0; k < 16; k++) {
            float a[4], b[4];
            #pragma unroll
            for (int i = 0; i < 4; i++) a[i] = As[k][ty*4+i];
            #pragma unroll
            for (int j = 0; j < 4; j++) b[j] = Bs[k][tx*4+j];
            #pragma unroll
            for (int i = 0; i < 4; i++)
                #pragma unroll
                for (int j = 0; j < 4; j++)
                    acc[i][j] = fmaf(a[i], b[j], acc[i][j]);
        }
        __syncthreads();
    }
    #pragma unroll
    for (int i = 0; i < 4; i++)
        #pragma unroll
        for (int j = 0; j < 4; j++) {
            int m = bm + ty*4 + i, n = bn + tx*4 + j;
            if (m < M && n < N)
                Cb[(long)m*ldc + n] = acc[i][j] + (bias ? bias[n] : 0.f);
        }
}

// ---------------- dt = softplus(dt_raw + dt_bias) -------------------------
__global__ __launch_bounds__(256)
void k_dt(const float* __restrict__ dt_bias)
{
    int i = blockIdx.x * 256 + threadIdx.x;
    if (i >= BATCH*SEQ*N_HEADS) return;
    int h = i % N_HEADS; long bs = i / N_HEADS;
    float x = g_zxbcdt[bs*D_IN_PROJ + D_INNER + CONV_DIM + h] + dt_bias[h];
    g_dt[i] = (x > 20.f) ? x : log1pf(expf(x));
}

// ---------------- causal depthwise conv + SiLU ----------------------------
__global__ __launch_bounds__(256)
void k_conv(const float* __restrict__ conv_w, const float* __restrict__ conv_b)
{
    long i = (long)blockIdx.x * 256 + threadIdx.x;
    if (i >= (long)BATCH*SEQ*CONV_DIM) return;
    int c = (int)(i % CONV_DIM);
    long bs = i / CONV_DIM;
    int s = (int)(bs % SEQ);
    int b = (int)(bs / SEQ);
    float acc = conv_b[c];
    #pragma unroll
    for (int k = 0; k < D_CONV; k++) {
        int sp = s - (D_CONV-1) + k;
        if (sp >= 0)
            acc = fmaf(g_zxbcdt[((long)b*SEQ + sp)*D_IN_PROJ + D_INNER + c],
                       conv_w[c*D_CONV + k], acc);
    }
    g_xBC[i] = acc / (1.f + expf(-acc));   // silu
}

// ---------------- chunk-local inclusive cumsum of A*dt --------------------
__global__ __launch_bounds__(CHUNK)
void k_cumsum(const float* __restrict__ A_log)
{
    int bz = blockIdx.x;                // (b*N_HEADS+h)*NCHUNK + c
    int c = bz % NCHUNK; int bh = bz / NCHUNK;
    int h = bh % N_HEADS; int b = bh / N_HEADS;
    int l = threadIdx.x;
    int sg = c*CHUNK + l;
    float A = -expf(A_log[h]);
    float val = A * g_dt[((long)b*SEQ + sg)*N_HEADS + h];
    __shared__ float buf[CHUNK];
    buf[l] = val; __syncthreads();
    for (int off = 1; off < CHUNK; off <<= 1) {
        float t = (l >= off) ? buf[l-off] : 0.f;
        __syncthreads();
        buf[l] += t;
        __syncthreads();
    }
    g_dAcum[((long)b*N_HEADS + h)*SEQ + sg] = buf[l];
}

// ---------------- Y_diag = (L*G) @ X + D*x --------------------------------
// per (b,c,h): out 256x128.  grid: (128/64, 256/64, B*NCHUNK*N_HEADS)
__global__ __launch_bounds__(256)
void k_ydiag(const float* __restrict__ Dv)
{
    int bz = blockIdx.z;
    int h = bz % N_HEADS; int bc = bz / N_HEADS;
    int c = bc % NCHUNK;  int b  = bc / NCHUNK;
    int bl = blockIdx.y * 64;   // l tile
    int bp = blockIdx.x * 64;   // p tile
    int tid = threadIdx.x;
    int tx = tid % 16, ty = tid / 16;
    const float* cum = g_dAcum + ((long)b*N_HEADS + h)*SEQ + (long)c*CHUNK;
    const float* Gm  = g_G + (long)bc*CHUNK*CHUNK;
    __shared__ float Ls[16][68];
    __shared__ float Xs[16][68];
    __shared__ float cum_l[64];
    if (tid < 64) cum_l[tid] = cum[bl + tid];
    float acc[4][4] = {};
    for (int k0 = 0; k0 < CHUNK; k0 += 16) {
        if (k0 > bl + 63) break;   // upper-triangular tiles are all zero (uniform)
        __syncthreads();
        for (int i = tid; i < 64*16; i += 256) {      // L tile: [s][l]
            int m = i / 16, k = i % 16;
            int gl = bl + m, gs = k0 + k;
            float v = 0.f;
            if (gs <= gl) v = Gm[(long)gl*CHUNK + gs] * expf(cum_l[m] - cum[gs]);
            Ls[k][m] = v;
        }
        for (int i = tid; i < 64*16; i += 256) {      // X tile: [s][p], X = x*dt
            int k = i / 64, n = i % 64;
            int gs = k0 + k; int gp = bp + n;
            long sg = (long)b*SEQ + c*CHUNK + gs;
            float xv = g_xBC[sg*CONV_DIM + h*HEADDIM + gp];
            Xs[k][n] = xv * g_dt[sg*N_HEADS + h];
        }
        __syncthreads();
        #pragma unroll
        for (int k = 0; k < 16; k++) {
            float a[4], bb[4];
            #pragma unroll
            for (int i = 0; i < 4; i++) a[i]  = Ls[k][ty*4+i];
            #pragma unroll
            for (int j = 0; j < 4; j++) bb[j] = Xs[k][tx*4+j];
            #pragma unroll
            for (int i = 0; i < 4; i++)
                #pragma unroll
                for (int j = 0; j < 4; j++)
                    acc[i][j] = fmaf(a[i], bb[j], acc[i][j]);
        }
    }
    float Dh = Dv[h];
    #pragma unroll
    for (int i = 0; i < 4; i++)
        #pragma unroll
        for (int j = 0; j < 4; j++) {
            int gl = bl + ty*4 + i, gp = bp + tx*4 + j;
            long sg = (long)b*SEQ + c*CHUNK + gl;
            float xraw = g_xBC[sg*CONV_DIM + h*HEADDIM + gp];
            g_y[sg*D_INNER + h*HEADDIM + gp] = acc[i][j] + Dh * xraw;
        }
}

// ---------------- chunk states: state[p,n] = sum_l X[l,p]*decay[l]*B[l,n] -
// grid: (128/64, 128/64, B*NCHUNK*N_HEADS)
__global__ __launch_bounds__(256)
void k_states()
{
    int bz = blockIdx.z;
    int h = bz % N_HEADS; int bc = bz / N_HEADS;
    int c = bc % NCHUNK;  int b  = bc / NCHUNK;
    int bp = blockIdx.y * 64;   // p tile
    int bn = blockIdx.x * 64;   // n tile
    int tid = threadIdx.x;
    int tx = tid % 16, ty = tid / 16;
    const float* cum = g_dAcum + ((long)b*N_HEADS + h)*SEQ + (long)c*CHUNK;
    float cum_last = cum[CHUNK-1];
    __shared__ float Xs[16][68];   // [l][p]
    __shared__ float Bs[16][68];   // [l][n]
    float acc[4][4] = {};
    for (int k0 = 0; k0 < CHUNK; k0 += 16) {
        for (int i = tid; i < 64*16; i += 256) {
            int k = i / 64, m = i % 64;
            int gl = k0 + k;
            long sg = (long)b*SEQ + c*CHUNK + gl;
            float scale = g_dt[sg*N_HEADS + h] * expf(cum_last - cum[gl]);
            Xs[k][m] = g_xBC[sg*CONV_DIM + h*HEADDIM + bp + m] * scale;
        }
        for (int i = tid; i < 64*16; i += 256) {
            int k = i / 64, m = i % 64;
            int gl = k0 + k;
            long sg = (long)b*SEQ + c*CHUNK + gl;
            Bs[k][m] = g_xBC[sg*CONV_DIM + D_INNER + bn + m];
        }
        __syncthreads();
        #pragma unroll
        for (int k = 0; k < 16; k++) {
            float a[4], bb[4];
            #pragma unroll
            for (int i = 0; i < 4; i++) a[i]  = Xs[k][ty*4+i];
            #pragma unroll
            for (int j = 0; j < 4; j++) bb[j] = Bs[k][tx*4+j];
            #pragma unroll
            for (int i = 0; i < 4; i++)
                #pragma unroll
                for (int j = 0; j < 4; j++)
                    acc[i][j] = fmaf(a[i], bb[j], acc[i][j]);
        }
        __syncthreads();
    }
    long base = ((long)bc*N_HEADS + h)*HEADDIM*D_STATE;
    #pragma unroll
    for (int i = 0; i < 4; i++)
        #pragma unroll
        for (int j = 0; j < 4; j++) {
            int gp = bp + ty*4 + i, gn = bn + tx*4 + j;
            g_states[base + (long)gp*D_STATE + gn] = acc[i][j];
        }
}

// ---------------- sequential inter-chunk state recurrence -----------------
__global__ __launch_bounds__(256)
void k_chunkrec()
{
    int bh = blockIdx.x;         // b*N_HEADS + h
    int h = bh % N_HEADS; int b = bh / N_HEADS;
    const float* cum = g_dAcum + (long)bh*SEQ;
    float csum[NCHUNK];
    #pragma unroll
    for (int c = 0; c < NCHUNK; c++) csum[c] = expf(cum[c*CHUNK + CHUNK-1]);
    for (int pn = threadIdx.x; pn < HEADDIM*D_STATE; pn += 256) {
        float carry = 0.f;
        #pragma unroll
        for (int c = 0; c < NCHUNK; c++) {
            long idx = (((long)b*NCHUNK + c)*N_HEADS + h)*HEADDIM*D_STATE + pn;
            g_states_in[idx] = carry;
            carry = carry * csum[c] + g_states[idx];
        }
    }
}

// ---------------- Y_off[l,p] = exp(cum[l]) * sum_n C[l,n]*Sin[p,n] --------
// grid: (128/64, 256/64, B*NCHUNK*N_HEADS)
__global__ __launch_bounds__(256)
void k_yoff()
{
    int bz = blockIdx.z;
    int h = bz % N_HEADS; int bc = bz / N_HEADS;
    int c = bc % NCHUNK;  int b  = bc / NCHUNK;
    int bl = blockIdx.y * 64;   // l tile
    int bp = blockIdx.x * 64;   // p tile
    int tid = threadIdx.x;
    int tx = tid % 16, ty = tid / 16;
    const float* cum = g_dAcum + ((long)b*N_HEADS + h)*SEQ + (long)c*CHUNK;
    const float* Sin = g_states_in + ((long)bc*N_HEADS + h)*HEADDIM*D_STATE;
    __shared__ float Cs[16][68];   // [n][l]
    __shared__ float Ss[16][68];   // [n][p]
    float acc[4][4] = {};
    for (int k0 = 0; k0 < D_STATE; k0 += 16) {
        for (int i = tid; i < 64*16; i += 256) {
            int m = i / 16, k = i % 16;
            long sg = (long)b*SEQ + c*CHUNK + bl + m;
            Cs[k][m] = g_xBC[sg*CONV_DIM + D_INNER + D_STATE + k0 + k];
        }
        for (int i = tid; i < 64*16; i += 256) {
            int m = i / 16, k = i % 16;
            Ss[k][m] = Sin[(long)(bp + m)*D_STATE + k0 + k];
        }
        __syncthreads();
        #pragma unroll
        for (int k = 0; k < 16; k++) {
            float a[4], bb[4];
            #pragma unroll
            for (int i = 0; i < 4; i++) a[i]  = Cs[k][ty*4+i];
            #pragma unroll
            for (int j = 0; j < 4; j++) bb[j] = Ss[k][tx*4+j];
            #pragma unroll
            for (int i = 0; i < 4; i++)
                #pragma unroll
                for (int j = 0; j < 4; j++)
                    acc[i][j] = fmaf(a[i], bb[j], acc[i][j]);
        }
        __syncthreads();
    }
    #pragma unroll
    for (int i = 0; i < 4; i++) {
        int gl = bl + ty*4 + i;
        float sc = expf(cum[gl]);
        long sg = (long)b*SEQ + c*CHUNK + gl;
        #pragma unroll
        for (int j = 0; j < 4; j++) {
            int gp = bp + tx*4 + j;
            g_y[sg*D_INNER + h*HEADDIM + gp] += sc * acc[i][j];
        }
    }
}

// ---------------- gate (y * silu(z)) + RMSNorm ----------------------------
__global__ __launch_bounds__(256)
void k_gatenorm(const float* __restrict__ norm_w)
{
    long row = blockIdx.x;                 // b*SEQ + s
    const float* zrow = g_zxbcdt + row*D_IN_PROJ;
    float* yrow = g_y + row*D_INNER;
    float vals[16];
    float local = 0.f;
    #pragma unroll
    for (int i = 0; i < 16; i++) {
        int d = threadIdx.x + i*256;
        float z = zrow[d];
        float v = yrow[d] * (z / (1.f + expf(-z)));
        vals[i] = v;
        local += v * v;
    }
    __shared__ float red[256];
    red[threadIdx.x] = local; __syncthreads();
    for (int off = 128; off > 0; off >>= 1) {
        if (threadIdx.x < off) red[threadIdx.x] += red[threadIdx.x + off];
        __syncthreads();
    }
    float scale = rsqrtf(red[0] / D_INNER + EPS);
    #pragma unroll
    for (int i = 0; i < 16; i++) {
        int d = threadIdx.x + i*256;
        yrow[d] = vals[i] * scale * norm_w[d];
    }
}

// --------------------------------------------------------------------------
extern "C" void kernel_launch(void* const* d_in, const int* in_sizes, int n_in,
                              void* d_out, int out_size)
{
    const float* inputs     = (const float*)d_in[0];
    const float* in_proj_w  = (const float*)d_in[1];
    const float* in_proj_b  = (const float*)d_in[2];
    const float* out_proj_w = (const float*)d_in[3];
    const float* out_proj_b = (const float*)d_in[4];
    const float* conv_w     = (const float*)d_in[5];
    const float* conv_b     = (const float*)d_in[6];
    const float* dt_bias    = (const float*)d_in[7];
    const float* A_log      = (const float*)d_in[8];
    const float* Dv         = (const float*)d_in[9];
    const float* norm_w     = (const float*)d_in[10];
    float* out = (float*)d_out;

    float *zx, *xbc, *Gp;
    cudaGetSymbolAddress((void**)&zx,  g_zxbcdt);
    cudaGetSymbolAddress((void**)&xbc, g_xBC);
    cudaGetSymbolAddress((void**)&Gp,  g_G);
    float *yp;
    cudaGetSymbolAddress((void**)&yp, g_y);

    const int M = BATCH * SEQ;     // 4096

    // 1) in_proj: zxbcdt = inputs @ in_proj_w^T + b
    {
        dim3 grid((D_IN_PROJ + 63)/64, M/64, 1);
        gemm_nt<<<grid, 256>>>(inputs, DIM, 0, in_proj_w, DIM, 0,
                               zx, D_IN_PROJ, 0, M, D_IN_PROJ, DIM, in_proj_b);
    }
    // 2) dt softplus
    k_dt<<<(BATCH*SEQ*N_HEADS + 255)/256, 256>>>(dt_bias);
    // 3) conv + silu
    k_conv<<<(int)(((long)BATCH*SEQ*CONV_DIM + 255)/256), 256>>>(conv_w, conv_b);
    // 4) chunk-local cumsum of A*dt
    k_cumsum<<<BATCH*N_HEADS*NCHUNK, CHUNK>>>(A_log);
    // 5) G = C @ B^T per (b,c)
    {
        dim3 grid(CHUNK/64, CHUNK/64, BATCH*NCHUNK);
        gemm_nt<<<grid, 256>>>(xbc + D_INNER + D_STATE, CONV_DIM, (long)CHUNK*CONV_DIM,
                               xbc + D_INNER,           CONV_DIM, (long)CHUNK*CONV_DIM,
                               Gp, CHUNK, (long)CHUNK*CHUNK,
                               CHUNK, CHUNK, D_STATE, nullptr);
    }
    // 6) Y_diag + D*x
    {
        dim3 grid(HEADDIM/64, CHUNK/64, BATCH*NCHUNK*N_HEADS);
        k_ydiag<<<grid, 256>>>(Dv);
    }
    // 7) per-chunk states
    {
        dim3 grid(D_STATE/64, HEADDIM/64, BATCH*NCHUNK*N_HEADS);
        k_states<<<grid, 256>>>();
    }
    // 8) inter-chunk recurrence
    k_chunkrec<<<BATCH*N_HEADS, 256>>>();
    // 9) Y_off +=
    {
        dim3 grid(HEADDIM/64, CHUNK/64, BATCH*NCHUNK*N_HEADS);
        k_yoff<<<grid, 256>>>();
    }
    // 10) gate + RMSNorm
    k_gatenorm<<<BATCH*SEQ, 256>>>(norm_w);
    // 11) out_proj
    {
        dim3 grid(DIM/64, M/64, 1);
        gemm_nt<<<grid, 256>>>(yp, D_INNER, 0, out_proj_w, D_INNER, 0,
                               out, DIM, 0, M, DIM, D_INNER, out_proj_b);
    }
}

// round 3
// speedup vs baseline: 3.2828x; 3.2828x over previous
#include <cuda_runtime.h>
#include <math.h>
#include <stdint.h>

#define BATCH   2
#define SEQ     2048
#define DIM     2048
#define D_INNER 4096
#define D_STATE 128
#define N_HEADS 32
#define HEADDIM 128
#define D_CONV  4
#define CHUNK   256
#define NCHUNK  (SEQ/CHUNK)                       /* 8  */
#define CONV_DIM (D_INNER + 2*D_STATE)            /* 4352 */
#define D_IN_PROJ (2*D_INNER + 2*D_STATE + N_HEADS) /* 8480 */
#define EPS 1e-5f

// ---------------- scratch (device globals, no allocation) ----------------
__device__ float g_zxbcdt[(size_t)BATCH*SEQ*D_IN_PROJ];          // in_proj output
__device__ float g_xBC  [(size_t)BATCH*SEQ*CONV_DIM];            // conv+silu output
__device__ float g_dt   [(size_t)BATCH*SEQ*N_HEADS];             // softplus dt (exact fp32)
__device__ float g_dAcum[(size_t)BATCH*N_HEADS*SEQ];             // chunk-local inclusive cumsum of A*dt
__device__ float g_G    [(size_t)BATCH*NCHUNK*CHUNK*CHUNK];      // C @ B^T per (b,c)
__device__ float g_states   [(size_t)BATCH*NCHUNK*N_HEADS*HEADDIM*D_STATE];
__device__ float g_states_in[(size_t)BATCH*NCHUNK*N_HEADS*HEADDIM*D_STATE];
__device__ float g_y    [(size_t)BATCH*SEQ*D_INNER];             // scan output / normed

// ================== tf32 tensor-core batched NT GEMM ======================
// C = A(MxK) * W(NxK)^T + bias.  Row-major, K contiguous in both operands.
// Block tile 128x128x16, 8 warps (2x4), warp tile 64x32, mma.m16n8k8.tf32.
__device__ __forceinline__ uint32_t f2tf32(float x) {
    uint32_t r;
    asm("cvt.rna.tf32.f32 %0, %1;" : "=r"(r) : "f"(x));
    return r;
}

__global__ __launch_bounds__(256)
void gemm_tf32(const float* __restrict__ A, long lda, long sA,
               const float* __restrict__ W, long ldb, long sB,
               float* __restrict__ C, long ldc, long sC,
               int M, int N, int K, const float* __restrict__ bias)
{
    __shared__ float As[128][20];   // [m][k], pad 20 -> conflict-free frag reads
    __shared__ float Bs[128][20];   // [n][k]
    int bz = blockIdx.z;
    const float* Ab = A + (long)bz * sA;
    const float* Wb = W + (long)bz * sB;
    float*       Cb = C + (long)bz * sC;
    int bm = blockIdx.y * 128, bn = blockIdx.x * 128;
    int tid  = threadIdx.x;
    int warp = tid >> 5, lane = tid & 31;
    int wm = warp >> 2, wn = warp & 3;          // warp grid 2x4
    int g  = lane >> 2, t4 = lane & 3;          // quad layout

    float acc[4][4][4];
    #pragma unroll
    for (int i = 0; i < 4; i++)
        #pragma unroll
        for (int j = 0; j < 4; j++)
            #pragma unroll
            for (int q = 0; q < 4; q++) acc[i][j][q] = 0.f;

    for (int k0 = 0; k0 < K; k0 += 16) {
        // stage A tile: 128x16, 2 float4 per thread
        #pragma unroll
        for (int it = 0; it < 2; it++) {
            int idx = tid + it*256;
            int row = idx >> 2, c4 = (idx & 3) * 4;
            float4 v = *reinterpret_cast<const float4*>(&Ab[(long)(bm+row)*lda + k0 + c4]);
            As[row][c4+0] = __uint_as_float(f2tf32(v.x));
            As[row][c4+1] = __uint_as_float(f2tf32(v.y));
            As[row][c4+2] = __uint_as_float(f2tf32(v.z));
            As[row][c4+3] = __uint_as_float(f2tf32(v.w));
        }
        // stage B tile: 128x16 (rows of W), guard N edge
        #pragma unroll
        for (int it = 0; it < 2; it++) {
            int idx = tid + it*256;
            int row = idx >> 2, c4 = (idx & 3) * 4;
            int gn = bn + row;
            float4 v = make_float4(0.f,0.f,0.f,0.f);
            if (gn < N)
                v = *reinterpret_cast<const float4*>(&Wb[(long)gn*ldb + k0 + c4]);
            Bs[row][c4+0] = __uint_as_float(f2tf32(v.x));
            Bs[row][c4+1] = __uint_as_float(f2tf32(v.y));
            Bs[row][c4+2] = __uint_as_float(f2tf32(v.z));
            Bs[row][c4+3] = __uint_as_float(f2tf32(v.w));
        }
        __syncthreads();
        #pragma unroll
        for (int ks = 0; ks < 2; ks++) {
            int kb = ks * 8;
            uint32_t af[4][4], bf[4][2];
            #pragma unroll
            for (int mt = 0; mt < 4; mt++) {
                int r0 = wm*64 + mt*16 + g;
                af[mt][0] = __float_as_uint(As[r0  ][kb+t4  ]);
                af[mt][1] = __float_as_uint(As[r0+8][kb+t4  ]);
                af[mt][2] = __float_as_uint(As[r0  ][kb+t4+4]);
                af[mt][3] = __float_as_uint(As[r0+8][kb+t4+4]);
            }
            #pragma unroll
            for (int nt = 0; nt < 4; nt++) {
                int cc = wn*32 + nt*8 + g;
                bf[nt][0] = __float_as_uint(Bs[cc][kb+t4  ]);
                bf[nt][1] = __float_as_uint(Bs[cc][kb+t4+4]);
            }
            #pragma unroll
            for (int mt = 0; mt < 4; mt++)
                #pragma unroll
                for (int nt = 0; nt < 4; nt++) {
                    asm volatile(
                        "mma.sync.aligned.m16n8k8.row.col.f32.tf32.tf32.f32 "
                        "{%0,%1,%2,%3}, {%4,%5,%6,%7}, {%8,%9}, {%0,%1,%2,%3};"
                        : "+f"(acc[mt][nt][0]), "+f"(acc[mt][nt][1]),
                          "+f"(acc[mt][nt][2]), "+f"(acc[mt][nt][3])
                        : "r"(af[mt][0]), "r"(af[mt][1]), "r"(af[mt][2]), "r"(af[mt][3]),
                          "r"(bf[nt][0]), "r"(bf[nt][1]));
                }
        }
        __syncthreads();
    }
    // epilogue
    #pragma unroll
    for (int mt = 0; mt < 4; mt++) {
        int row0 = bm + wm*64 + mt*16 + g;
        #pragma unroll
        for (int nt = 0; nt < 4; nt++) {
            int col0 = bn + wn*32 + nt*8 + 2*t4;
            if (col0 < N) {
                float b0 = bias ? bias[col0] : 0.f;
                Cb[(long)row0*ldc + col0] = acc[mt][nt][0] + b0;
                Cb[(long)(row0+8)*ldc + col0] = acc[mt][nt][2] + b0;
            }
            if (col0+1 < N) {
                float b1 = bias ? bias[col0+1] : 0.f;
                Cb[(long)row0*ldc + col0+1] = acc[mt][nt][1] + b1;
                Cb[(long)(row0+8)*ldc + col0+1] = acc[mt][nt][3] + b1;
            }
        }
    }
}

// ---------------- exact fp32 dt projection + softplus ---------------------
// dt[row][h] = softplus(inputs[row,:] . W_dt[h,:] + b_dt[h] + dt_bias[h])
__global__ __launch_bounds__(256)
void k_dtproj(const float* __restrict__ inputs,
              const float* __restrict__ in_proj_w,
              const float* __restrict__ in_proj_b,
              const float* __restrict__ dt_bias)
{
    long row = blockIdx.x;                     // b*SEQ + s
    __shared__ float xs[DIM];
    for (int k = threadIdx.x; k < DIM; k += 256)
        xs[k] = inputs[row*DIM + k];
    __syncthreads();
    int warp = threadIdx.x >> 5, lane = threadIdx.x & 31;
    const float* Wdt = in_proj_w + (size_t)(D_INNER + CONV_DIM) * DIM;
    #pragma unroll
    for (int j = 0; j < 4; j++) {
        int h = warp*4 + j;
        const float* wr = Wdt + (size_t)h * DIM;
        float acc = 0.f;
        for (int k = lane; k < DIM; k += 32)
            acc = fmaf(xs[k], wr[k], acc);
        #pragma unroll
        for (int off = 16; off > 0; off >>= 1)
            acc += __shfl_down_sync(0xffffffff, acc, off);
        if (lane == 0) {
            float x = acc + in_proj_b[D_INNER + CONV_DIM + h] + dt_bias[h];
            g_dt[row*N_HEADS + h] = (x > 20.f) ? x : log1pf(expf(x));
        }
    }
}

// ---------------- causal depthwise conv + SiLU ----------------------------
__global__ __launch_bounds__(256)
void k_conv(const float* __restrict__ conv_w, const float* __restrict__ conv_b)
{
    long i = (long)blockIdx.x * 256 + threadIdx.x;
    if (i >= (long)BATCH*SEQ*CONV_DIM) return;
    int c = (int)(i % CONV_DIM);
    long bs = i / CONV_DIM;
    int s = (int)(bs % SEQ);
    int b = (int)(bs / SEQ);
    float acc = conv_b[c];
    #pragma unroll
    for (int k = 0; k < D_CONV; k++) {
        int sp = s - (D_CONV-1) + k;
        if (sp >= 0)
            acc = fmaf(g_zxbcdt[((long)b*SEQ + sp)*D_IN_PROJ + D_INNER + c],
                       conv_w[c*D_CONV + k], acc);
    }
    g_xBC[i] = acc / (1.f + expf(-acc));   // silu
}

// ---------------- chunk-local inclusive cumsum of A*dt --------------------
__global__ __launch_bounds__(CHUNK)
void k_cumsum(const float* __restrict__ A_log)
{
    int bz = blockIdx.x;                // (b*N_HEADS+h)*NCHUNK + c
    int c = bz % NCHUNK; int bh = bz / NCHUNK;
    int h = bh % N_HEADS; int b = bh / N_HEADS;
    int l = threadIdx.x;
    int sg = c*CHUNK + l;
    float A = -expf(A_log[h]);
    float val = A * g_dt[((long)b*SEQ + sg)*N_HEADS + h];
    __shared__ float buf[CHUNK];
    buf[l] = val; __syncthreads();
    for (int off = 1; off < CHUNK; off <<= 1) {
        float t = (l >= off) ? buf[l-off] : 0.f;
        __syncthreads();
        buf[l] += t;
        __syncthreads();
    }
    g_dAcum[((long)b*N_HEADS + h)*SEQ + sg] = buf[l];
}

// ---------------- Y_diag = (L*G) @ X + D*x --------------------------------
__global__ __launch_bounds__(256)
void k_ydiag(const float* __restrict__ Dv)
{
    int bz = blockIdx.z;
    int h = bz % N_HEADS; int bc = bz / N_HEADS;
    int c = bc % NCHUNK;  int b  = bc / NCHUNK;
    int bl = blockIdx.y * 64;   // l tile
    int bp = blockIdx.x * 64;   // p tile
    int tid = threadIdx.x;
    int tx = tid % 16, ty = tid / 16;
    const float* cum = g_dAcum + ((long)b*N_HEADS + h)*SEQ + (long)c*CHUNK;
    const float* Gm  = g_G + (long)bc*CHUNK*CHUNK;
    __shared__ float Ls[16][68];
    __shared__ float Xs[16][68];
    __shared__ float cum_l[64];
    if (tid < 64) cum_l[tid] = cum[bl + tid];
    float acc[4][4] = {};
    for (int k0 = 0; k0 < CHUNK; k0 += 16) {
        if (k0 > bl + 63) break;   // upper-triangular tiles are all zero (uniform)
        __syncthreads();
        for (int i = tid; i < 64*16; i += 256) {      // L tile: [s][l]
            int m = i / 16, k = i % 16;
            int gl = bl + m, gs = k0 + k;
            float v = 0.f;
            if (gs <= gl) v = Gm[(long)gl*CHUNK + gs] * expf(cum_l[m] - cum[gs]);
            Ls[k][m] = v;
        }
        for (int i = tid; i < 64*16; i += 256) {      // X tile: [s][p], X = x*dt
            int k = i / 64, n = i % 64;
            int gs = k0 + k; int gp = bp + n;
            long sg = (long)b*SEQ + c*CHUNK + gs;
            float xv = g_xBC[sg*CONV_DIM + h*HEADDIM + gp];
            Xs[k][n] = xv * g_dt[sg*N_HEADS + h];
        }
        __syncthreads();
        #pragma unroll
        for (int k = 0; k < 16; k++) {
            float a[4], bb[4];
            #pragma unroll
            for (int i = 0; i < 4; i++) a[i]  = Ls[k][ty*4+i];
            #pragma unroll
            for (int j = 0; j < 4; j++) bb[j] = Xs[k][tx*4+j];
            #pragma unroll
            for (int i = 0; i < 4; i++)
                #pragma unroll
                for (int j = 0; j < 4; j++)
                    acc[i][j] = fmaf(a[i], bb[j], acc[i][j]);
        }
    }
    float Dh = Dv[h];
    #pragma unroll
    for (int i = 0; i < 4; i++)
        #pragma unroll
        for (int j = 0; j < 4; j++) {
            int gl = bl + ty*4 + i, gp = bp + tx*4 + j;
            long sg = (long)b*SEQ + c*CHUNK + gl;
            float xraw = g_xBC[sg*CONV_DIM + h*HEADDIM + gp];
            g_y[sg*D_INNER + h*HEADDIM + gp] = acc[i][j] + Dh * xraw;
        }
}

// ---------------- chunk states: state[p,n] = sum_l X[l,p]*decay[l]*B[l,n] -
__global__ __launch_bounds__(256)
void k_states()
{
    int bz = blockIdx.z;
    int h = bz % N_HEADS; int bc = bz / N_HEADS;
    int c = bc % NCHUNK;  int b  = bc / NCHUNK;
    int bp = blockIdx.y * 64;   // p tile
    int bn = blockIdx.x * 64;   // n tile
    int tid = threadIdx.x;
    int tx = tid % 16, ty = tid / 16;
    const float* cum = g_dAcum + ((long)b*N_HEADS + h)*SEQ + (long)c*CHUNK;
    float cum_last = cum[CHUNK-1];
    __shared__ float Xs[16][68];   // [l][p]
    __shared__ float Bs[16][68];   // [l][n]
    float acc[4][4] = {};
    for (int k0 = 0; k0 < CHUNK; k0 += 16) {
        for (int i = tid; i < 64*16; i += 256) {
            int k = i / 64, m = i % 64;
            int gl = k0 + k;
            long sg = (long)b*SEQ + c*CHUNK + gl;
            float scale = g_dt[sg*N_HEADS + h] * expf(cum_last - cum[gl]);
            Xs[k][m] = g_xBC[sg*CONV_DIM + h*HEADDIM + bp + m] * scale;
        }
        for (int i = tid; i < 64*16; i += 256) {
            int k = i / 64, m = i % 64;
            int gl = k0 + k;
            long sg = (long)b*SEQ + c*CHUNK + gl;
            Bs[k][m] = g_xBC[sg*CONV_DIM + D_INNER + bn + m];
        }
        __syncthreads();
        #pragma unroll
        for (int k = 0; k < 16; k++) {
            float a[4], bb[4];
            #pragma unroll
            for (int i = 0; i < 4; i++) a[i]  = Xs[k][ty*4+i];
            #pragma unroll
            for (int j = 0; j < 4; j++) bb[j] = Bs[k][tx*4+j];
            #pragma unroll
            for (int i = 0; i < 4; i++)
                #pragma unroll
                for (int j = 0; j < 4; j++)
                    acc[i][j] = fmaf(a[i], bb[j], acc[i][j]);
        }
        __syncthreads();
    }
    long base = ((long)bc*N_HEADS + h)*HEADDIM*D_STATE;
    #pragma unroll
    for (int i = 0; i < 4; i++)
        #pragma unroll
        for (int j = 0; j < 4; j++) {
            int gp = bp + ty*4 + i, gn = bn + tx*4 + j;
            g_states[base + (long)gp*D_STATE + gn] = acc[i][j];
        }
}

// ---------------- sequential inter-chunk state recurrence -----------------
__global__ __launch_bounds__(256)
void k_chunkrec()
{
    int bh = blockIdx.x;         // b*N_HEADS + h
    int h = bh % N_HEADS; int b = bh / N_HEADS;
    const float* cum = g_dAcum + (long)bh*SEQ;
    float csum[NCHUNK];
    #pragma unroll
    for (int c = 0; c < NCHUNK; c++) csum[c] = expf(cum[c*CHUNK + CHUNK-1]);
    for (int pn = threadIdx.x; pn < HEADDIM*D_STATE; pn += 256) {
        float carry = 0.f;
        #pragma unroll
        for (int c = 0; c < NCHUNK; c++) {
            long idx = (((long)b*NCHUNK + c)*N_HEADS + h)*HEADDIM*D_STATE + pn;
            g_states_in[idx] = carry;
            carry = carry * csum[c] + g_states[idx];
        }
    }
}

// ---------------- Y_off[l,p] += exp(cum[l]) * sum_n C[l,n]*Sin[p,n] -------
__global__ __launch_bounds__(256)
void k_yoff()
{
    int bz = blockIdx.z;
    int h = bz % N_HEADS; int bc = bz / N_HEADS;
    int c = bc % NCHUNK;  int b  = bc / NCHUNK;
    int bl = blockIdx.y * 64;   // l tile
    int bp = blockIdx.x * 64;   // p tile
    int tid = threadIdx.x;
    int tx = tid % 16, ty = tid / 16;
    const float* cum = g_dAcum + ((long)b*N_HEADS + h)*SEQ + (long)c*CHUNK;
    const float* Sin = g_states_in + ((long)bc*N_HEADS + h)*HEADDIM*D_STATE;
    __shared__ float Cs[16][68];   // [n][l]
    __shared__ float Ss[16][68];   // [n][p]
    float acc[4][4] = {};
    for (int k0 = 0; k0 < D_STATE; k0 += 16) {
        for (int i = tid; i < 64*16; i += 256) {
            int m = i / 16, k = i % 16;
            long sg = (long)b*SEQ + c*CHUNK + bl + m;
            Cs[k][m] = g_xBC[sg*CONV_DIM + D_INNER + D_STATE + k0 + k];
        }
        for (int i = tid; i < 64*16; i += 256) {
            int m = i / 16, k = i % 16;
            Ss[k][m] = Sin[(long)(bp + m)*D_STATE + k0 + k];
        }
        __syncthreads();
        #pragma unroll
        for (int k = 0; k < 16; k++) {
            float a[4], bb[4];
            #pragma unroll
            for (int i = 0; i < 4; i++) a[i]  = Cs[k][ty*4+i];
            #pragma unroll
            for (int j = 0; j < 4; j++) bb[j] = Ss[k][tx*4+j];
            #pragma unroll
            for (int i = 0; i < 4; i++)
                #pragma unroll
                for (int j = 0; j < 4; j++)
                    acc[i][j] = fmaf(a[i], bb[j], acc[i][j]);
        }
        __syncthreads();
    }
    #pragma unroll
    for (int i = 0; i < 4; i++) {
        int gl = bl + ty*4 + i;
        float sc = expf(cum[gl]);
        long sg = (long)b*SEQ + c*CHUNK + gl;
        #pragma unroll
        for (int j = 0; j < 4; j++) {
            int gp = bp + tx*4 + j;
            g_y[sg*D_INNER + h*HEADDIM + gp] += sc * acc[i][j];
        }
    }
}

// ---------------- gate (y * silu(z)) + RMSNorm ----------------------------
__global__ __launch_bounds__(256)
void k_gatenorm(const float* __restrict__ norm_w)
{
    long row = blockIdx.x;                 // b*SEQ + s
    const float* zrow = g_zxbcdt + row*D_IN_PROJ;
    float* yrow = g_y + row*D_INNER;
    float vals[16];
    float local = 0.f;
    #pragma unroll
    for (int i = 0; i < 16; i++) {
        int d = threadIdx.x + i*256;
        float z = zrow[d];
        float v = yrow[d] * (z / (1.f + expf(-z)));
        vals[i] = v;
        local += v * v;
    }
    __shared__ float red[256];
    red[threadIdx.x] = local; __syncthreads();
    for (int off = 128; off > 0; off >>= 1) {
        if (threadIdx.x < off) red[threadIdx.x] += red[threadIdx.x + off];
        __syncthreads();
    }
    float scale = rsqrtf(red[0] / D_INNER + EPS);
    #pragma unroll
    for (int i = 0; i < 16; i++) {
        int d = threadIdx.x + i*256;
        yrow[d] = vals[i] * scale * norm_w[d];
    }
}

// --------------------------------------------------------------------------
extern "C" void kernel_launch(void* const* d_in, const int* in_sizes, int n_in,
                              void* d_out, int out_size)
{
    const float* inputs     = (const float*)d_in[0];
    const float* in_proj_w  = (const float*)d_in[1];
    const float* in_proj_b  = (const float*)d_in[2];
    const float* out_proj_w = (const float*)d_in[3];
    const float* out_proj_b = (const float*)d_in[4];
    const float* conv_w     = (const float*)d_in[5];
    const float* conv_b     = (const float*)d_in[6];
    const float* dt_bias    = (const float*)d_in[7];
    const float* A_log      = (const float*)d_in[8];
    const float* Dv         = (const float*)d_in[9];
    const float* norm_w     = (const float*)d_in[10];
    float* out = (float*)d_out;

    float *zx, *xbc, *Gp, *yp;
    cudaGetSymbolAddress((void**)&zx,  g_zxbcdt);
    cudaGetSymbolAddress((void**)&xbc, g_xBC);
    cudaGetSymbolAddress((void**)&Gp,  g_G);
    cudaGetSymbolAddress((void**)&yp,  g_y);

    const int M = BATCH * SEQ;     // 4096

    // 1) in_proj (tf32 tensor cores): zxbcdt = inputs @ in_proj_w^T + b
    {
        dim3 grid((D_IN_PROJ + 127)/128, M/128, 1);
        gemm_tf32<<<grid, 256>>>(inputs, DIM, 0, in_proj_w, DIM, 0,
                                 zx, D_IN_PROJ, 0, M, D_IN_PROJ, DIM, in_proj_b);
    }
    // 2) exact fp32 dt projection + softplus (avoids tf32 error in exponents)
    k_dtproj<<<M, 256>>>(inputs, in_proj_w, in_proj_b, dt_bias);
    // 3) conv + silu
    k_conv<<<(int)(((long)BATCH*SEQ*CONV_DIM + 255)/256), 256>>>(conv_w, conv_b);
    // 4) chunk-local cumsum of A*dt
    k_cumsum<<<BATCH*N_HEADS*NCHUNK, CHUNK>>>(A_log);
    // 5) G = C @ B^T per (b,c)  (tf32)
    {
        dim3 grid(CHUNK/128, CHUNK/128, BATCH*NCHUNK);
        gemm_tf32<<<grid, 256>>>(xbc + D_INNER + D_STATE, CONV_DIM, (long)CHUNK*CONV_DIM,
                                 xbc + D_INNER,           CONV_DIM, (long)CHUNK*CONV_DIM,
                                 Gp, CHUNK, (long)CHUNK*CHUNK,
                                 CHUNK, CHUNK, D_STATE, nullptr);
    }
    // 6) Y_diag + D*x
    {
        dim3 grid(HEADDIM/64, CHUNK/64, BATCH*NCHUNK*N_HEADS);
        k_ydiag<<<grid, 256>>>(Dv);
    }
    // 7) per-chunk states
    {
        dim3 grid(D_STATE/64, HEADDIM/64, BATCH*NCHUNK*N_HEADS);
        k_states<<<grid, 256>>>();
    }
    // 8) inter-chunk recurrence
    k_chunkrec<<<BATCH*N_HEADS, 256>>>();
    // 9) Y_off +=
    {
        dim3 grid(HEADDIM/64, CHUNK/64, BATCH*NCHUNK*N_HEADS);
        k_yoff<<<grid, 256>>>();
    }
    // 10) gate + RMSNorm
    k_gatenorm<<<BATCH*SEQ, 256>>>(norm_w);
    // 11) out_proj (tf32 tensor cores)
    {
        dim3 grid(DIM/128, M/128, 1);
        gemm_tf32<<<grid, 256>>>(yp, D_INNER, 0, out_proj_w, D_INNER, 0,
                                 out, DIM, 0, M, DIM, D_INNER, out_proj_b);
    }
}

// round 5
// speedup vs baseline: 3.5665x; 1.0864x over previous
#include <cuda_runtime.h>
#include <math.h>
#include <stdint.h>

#define BATCH   2
#define SEQ     2048
#define DIM     2048
#define D_INNER 4096
#define D_STATE 128
#define N_HEADS 32
#define HEADDIM 128
#define D_CONV  4
#define CHUNK   256
#define NCHUNK  (SEQ/CHUNK)                       /* 8  */
#define CONV_DIM (D_INNER + 2*D_STATE)            /* 4352 */
#define D_IN_PROJ (2*D_INNER + 2*D_STATE + N_HEADS) /* 8480 */
#define EPS 1e-5f

// ---------------- scratch (device globals, no allocation) ----------------
__device__ float g_zxbcdt[(size_t)BATCH*SEQ*D_IN_PROJ];
__device__ float g_xBC  [(size_t)BATCH*SEQ*CONV_DIM];
__device__ float g_dt   [(size_t)BATCH*SEQ*N_HEADS];
__device__ float g_dAcum[(size_t)BATCH*N_HEADS*SEQ];
__device__ float g_G    [(size_t)BATCH*NCHUNK*CHUNK*CHUNK];
__device__ float g_states   [(size_t)BATCH*NCHUNK*N_HEADS*HEADDIM*D_STATE];
__device__ float g_states_in[(size_t)BATCH*NCHUNK*N_HEADS*HEADDIM*D_STATE];
__device__ float g_y    [(size_t)BATCH*SEQ*D_INNER];

__device__ __forceinline__ uint32_t f2tf32(float x) {
    uint32_t r;
    asm("cvt.rna.tf32.f32 %0, %1;" : "=r"(r) : "f"(x));
    return r;
}
__device__ __forceinline__ void cp16(uint32_t dst, const float* src, bool pred) {
    asm volatile("cp.async.ca.shared.global [%0], [%1], 16, %2;"
                 :: "r"(dst), "l"(src), "r"(pred ? 16 : 0));
}

// ================== pipelined tf32 tensor-core batched NT GEMM ============
// C = A(MxK) * W(NxK)^T + bias. Row-major, K contiguous. M%128==0, K%16==0.
// Block tile 128x128x16, cp.async 2-stage double buffer, 8 warps, m16n8k8.
__global__ __launch_bounds__(256)
void gemm_tf32(const float* __restrict__ A, long lda, long sA,
               const float* __restrict__ W, long ldb, long sB,
               float* __restrict__ C, long ldc, long sC,
               int M, int N, int K, const float* __restrict__ bias)
{
    __shared__ float As[2][128][20];   // row = 80B (16B aligned), conflict-free frags
    __shared__ float Bs[2][128][20];
    int bz = blockIdx.z;
    const float* Ab = A + (long)bz * sA;
    const float* Wb = W + (long)bz * sB;
    float*       Cb = C + (long)bz * sC;
    int bm = blockIdx.y * 128, bn = blockIdx.x * 128;
    int tid  = threadIdx.x;
    int warp = tid >> 5, lane = tid & 31;
    int wm = warp >> 2, wn = warp & 3;
    int g  = lane >> 2, t4 = lane & 3;

    uint32_t sAu = (uint32_t)__cvta_generic_to_shared(&As[0][0][0]);
    uint32_t sBu = (uint32_t)__cvta_generic_to_shared(&Bs[0][0][0]);
    const uint32_t STG = 128*20*4;     // bytes per stage

    float acc[4][4][4];
    #pragma unroll
    for (int i = 0; i < 4; i++)
        #pragma unroll
        for (int j = 0; j < 4; j++)
            #pragma unroll
            for (int q = 0; q < 4; q++) acc[i][j][q] = 0.f;

    const int KT = K / 16;

    // ---- tile loader: 128x16 floats per operand, 2 x 16B per thread each
    #define LOADTILE(st, k0)                                                 \
    do {                                                                     \
        _Pragma("unroll")                                                    \
        for (int it = 0; it < 2; it++) {                                     \
            int idx = tid + it*256;                                          \
            int row = idx >> 2, c4 = (idx & 3) * 4;                          \
            cp16(sAu + (st)*STG + (row*20 + c4)*4,                           \
                 &Ab[(long)(bm+row)*lda + (k0) + c4], true);                 \
        }                                                                    \
        _Pragma("unroll")                                                    \
        for (int it = 0; it < 2; it++) {                                     \
            int idx = tid + it*256;                                          \
            int row = idx >> 2, c4 = (idx & 3) * 4;                          \
            int gn = bn + row; bool p = gn < N;                              \
            cp16(sBu + (st)*STG + (row*20 + c4)*4,                           \
                 &Wb[(long)(p ? gn : 0)*ldb + (k0) + c4], p);                \
        }                                                                    \
    } while (0)

    LOADTILE(0, 0);
    asm volatile("cp.async.commit_group;");

    for (int kt = 0; kt < KT; kt++) {
        asm volatile("cp.async.wait_group 0;" ::: "memory");
        __syncthreads();
        if (kt + 1 < KT) LOADTILE((kt+1) & 1, (kt+1)*16);
        asm volatile("cp.async.commit_group;");

        int st = kt & 1;
        #pragma unroll
        for (int ks = 0; ks < 2; ks++) {
            int kb = ks * 8;
            uint32_t af[4][4], bf[4][2];
            #pragma unroll
            for (int mt = 0; mt < 4; mt++) {
                int r0 = wm*64 + mt*16 + g;
                af[mt][0] = f2tf32(As[st][r0  ][kb+t4  ]);
                af[mt][1] = f2tf32(As[st][r0+8][kb+t4  ]);
                af[mt][2] = f2tf32(As[st][r0  ][kb+t4+4]);
                af[mt][3] = f2tf32(As[st][r0+8][kb+t4+4]);
            }
            #pragma unroll
            for (int nt = 0; nt < 4; nt++) {
                int cc = wn*32 + nt*8 + g;
                bf[nt][0] = f2tf32(Bs[st][cc][kb+t4  ]);
                bf[nt][1] = f2tf32(Bs[st][cc][kb+t4+4]);
            }
            #pragma unroll
            for (int mt = 0; mt < 4; mt++)
                #pragma unroll
                for (int nt = 0; nt < 4; nt++) {
                    asm volatile(
                        "mma.sync.aligned.m16n8k8.row.col.f32.tf32.tf32.f32 "
                        "{%0,%1,%2,%3}, {%4,%5,%6,%7}, {%8,%9}, {%0,%1,%2,%3};"
                        : "+f"(acc[mt][nt][0]), "+f"(acc[mt][nt][1]),
                          "+f"(acc[mt][nt][2]), "+f"(acc[mt][nt][3])
                        : "r"(af[mt][0]), "r"(af[mt][1]), "r"(af[mt][2]), "r"(af[mt][3]),
                          "r"(bf[nt][0]), "r"(bf[nt][1]));
                }
        }
    }
    #undef LOADTILE

    // epilogue
    #pragma unroll
    for (int mt = 0; mt < 4; mt++) {
        int row0 = bm + wm*64 + mt*16 + g;
        #pragma unroll
        for (int nt = 0; nt < 4; nt++) {
            int col0 = bn + wn*32 + nt*8 + 2*t4;
            if (col0 < N) {
                float b0 = bias ? bias[col0] : 0.f;
                Cb[(long)row0*ldc + col0] = acc[mt][nt][0] + b0;
                Cb[(long)(row0+8)*ldc + col0] = acc[mt][nt][2] + b0;
            }
            if (col0+1 < N) {
                float b1 = bias ? bias[col0+1] : 0.f;
                Cb[(long)row0*ldc + col0+1] = acc[mt][nt][1] + b1;
                Cb[(long)(row0+8)*ldc + col0+1] = acc[mt][nt][3] + b1;
            }
        }
    }
}

// ---------------- exact fp32 dt projection + softplus (tiled) -------------
// block = 32 rows; thread t -> row t/8, heads (t%8)*4 .. +3
__global__ __launch_bounds__(256)
void k_dtproj(const float* __restrict__ inputs,
              const float* __restrict__ in_proj_w,
              const float* __restrict__ in_proj_b,
              const float* __restrict__ dt_bias)
{
    __shared__ float xs[32][133];
    __shared__ float ws[32][133];
    int t = threadIdx.x;
    long r0 = (long)blockIdx.x * 32;
    int r = t >> 3;
    int hb = (t & 7) * 4;
    const float* Wdt = in_proj_w + (size_t)(D_INNER + CONV_DIM) * DIM;
    float acc[4] = {0.f, 0.f, 0.f, 0.f};
    for (int k0 = 0; k0 < DIM; k0 += 128) {
        #pragma unroll
        for (int i = 0; i < 4; i++) {
            int idx = t + i*256;              // 1024 float4 total
            int row = idx >> 5, c4 = (idx & 31) * 4;
            float4 v = *reinterpret_cast<const float4*>(&inputs[(r0+row)*DIM + k0 + c4]);
            xs[row][c4] = v.x; xs[row][c4+1] = v.y; xs[row][c4+2] = v.z; xs[row][c4+3] = v.w;
            float4 w = *reinterpret_cast<const float4*>(&Wdt[(size_t)row*DIM + k0 + c4]);
            ws[row][c4] = w.x; ws[row][c4+1] = w.y; ws[row][c4+2] = w.z; ws[row][c4+3] = w.w;
        }
        __syncthreads();
        #pragma unroll 8
        for (int k = 0; k < 128; k++) {
            float xv = xs[r][k];
            #pragma unroll
            for (int j = 0; j < 4; j++)
                acc[j] = fmaf(xv, ws[hb+j][k], acc[j]);
        }
        __syncthreads();
    }
    #pragma unroll
    for (int j = 0; j < 4; j++) {
        int h = hb + j;
        float x = acc[j] + in_proj_b[D_INNER + CONV_DIM + h] + dt_bias[h];
        g_dt[(r0 + r)*N_HEADS + h] = (x > 20.f) ? x : log1pf(expf(x));
    }
}

// ---------------- causal depthwise conv + SiLU ----------------------------
__global__ __launch_bounds__(256)
void k_conv(const float* __restrict__ conv_w, const float* __restrict__ conv_b)
{
    long i = (long)blockIdx.x * 256 + threadIdx.x;
    if (i >= (long)BATCH*SEQ*CONV_DIM) return;
    int c = (int)(i % CONV_DIM);
    long bs = i / CONV_DIM;
    int s = (int)(bs % SEQ);
    int b = (int)(bs / SEQ);
    float acc = conv_b[c];
    #pragma unroll
    for (int k = 0; k < D_CONV; k++) {
        int sp = s - (D_CONV-1) + k;
        if (sp >= 0)
            acc = fmaf(g_zxbcdt[((long)b*SEQ + sp)*D_IN_PROJ + D_INNER + c],
                       conv_w[c*D_CONV + k], acc);
    }
    g_xBC[i] = acc / (1.f + expf(-acc));
}

// ---------------- chunk-local inclusive cumsum of A*dt --------------------
__global__ __launch_bounds__(CHUNK)
void k_cumsum(const float* __restrict__ A_log)
{
    int bz = blockIdx.x;
    int c = bz % NCHUNK; int bh = bz / NCHUNK;
    int h = bh % N_HEADS; int b = bh / N_HEADS;
    int l = threadIdx.x;
    int sg = c*CHUNK + l;
    float A = -expf(A_log[h]);
    float val = A * g_dt[((long)b*SEQ + sg)*N_HEADS + h];
    __shared__ float buf[CHUNK];
    buf[l] = val; __syncthreads();
    for (int off = 1; off < CHUNK; off <<= 1) {
        float t = (l >= off) ? buf[l-off] : 0.f;
        __syncthreads();
        buf[l] += t;
        __syncthreads();
    }
    g_dAcum[((long)b*N_HEADS + h)*SEQ + sg] = buf[l];
}

// ---------------- Y_diag = (L*G) @ X + D*x --------------------------------
__global__ __launch_bounds__(256)
void k_ydiag(const float* __restrict__ Dv)
{
    int bz = blockIdx.z;
    int h = bz % N_HEADS; int bc = bz / N_HEADS;
    int c = bc % NCHUNK;  int b  = bc / NCHUNK;
    int bl = blockIdx.y * 64;
    int bp = blockIdx.x * 64;
    int tid = threadIdx.x;
    int tx = tid % 16, ty = tid / 16;
    const float* cum = g_dAcum + ((long)b*N_HEADS + h)*SEQ + (long)c*CHUNK;
    const float* Gm  = g_G + (long)bc*CHUNK*CHUNK;
    __shared__ float Ls[16][68];
    __shared__ float Xs[16][68];
    __shared__ float cum_l[64];
    if (tid < 64) cum_l[tid] = cum[bl + tid];
    float acc[4][4] = {};
    for (int k0 = 0; k0 < CHUNK; k0 += 16) {
        if (k0 > bl + 63) break;
        __syncthreads();
        for (int i = tid; i < 64*16; i += 256) {
            int m = i / 16, k = i % 16;
            int gl = bl + m, gs = k0 + k;
            float v = 0.f;
            if (gs <= gl) v = Gm[(long)gl*CHUNK + gs] * expf(cum_l[m] - cum[gs]);
            Ls[k][m] = v;
        }
        for (int i = tid; i < 64*16; i += 256) {
            int k = i / 64, n = i % 64;
            int gs = k0 + k; int gp = bp + n;
            long sg = (long)b*SEQ + c*CHUNK + gs;
            float xv = g_xBC[sg*CONV_DIM + h*HEADDIM + gp];
            Xs[k][n] = xv * g_dt[sg*N_HEADS + h];
        }
        __syncthreads();
        #pragma unroll
        for (int k = 0; k < 16; k++) {
            float a[4], bb[4];
            #pragma unroll
            for (int i = 0; i < 4; i++) a[i]  = Ls[k][ty*4+i];
            #pragma unroll
            for (int j = 0; j < 4; j++) bb[j] = Xs[k][tx*4+j];
            #pragma unroll
            for (int i = 0; i < 4; i++)
                #pragma unroll
                for (int j = 0; j < 4; j++)
                    acc[i][j] = fmaf(a[i], bb[j], acc[i][j]);
        }
    }
    float Dh = Dv[h];
    #pragma unroll
    for (int i = 0; i < 4; i++)
        #pragma unroll
        for (int j = 0; j < 4; j++) {
            int gl = bl + ty*4 + i, gp = bp + tx*4 + j;
            long sg = (long)b*SEQ + c*CHUNK + gl;
            float xraw = g_xBC[sg*CONV_DIM + h*HEADDIM + gp];
            g_y[sg*D_INNER + h*HEADDIM + gp] = acc[i][j] + Dh * xraw;
        }
}

// ---------------- chunk states ------------------------------------------
__global__ __launch_bounds__(256)
void k_states()
{
    int bz = blockIdx.z;
    int h = bz % N_HEADS; int bc = bz / N_HEADS;
    int c = bc % NCHUNK;  int b  = bc / NCHUNK;
    int bp = blockIdx.y * 64;
    int bn = blockIdx.x * 64;
    int tid = threadIdx.x;
    int tx = tid % 16, ty = tid / 16;
    const float* cum = g_dAcum + ((long)b*N_HEADS + h)*SEQ + (long)c*CHUNK;
    float cum_last = cum[CHUNK-1];
    __shared__ float Xs[16][68];
    __shared__ float Bs[16][68];
    float acc[4][4] = {};
    for (int k0 = 0; k0 < CHUNK; k0 += 16) {
        for (int i = tid; i < 64*16; i += 256) {
            int k = i / 64, m = i % 64;
            int gl = k0 + k;
            long sg = (long)b*SEQ + c*CHUNK + gl;
            float scale = g_dt[sg*N_HEADS + h] * expf(cum_last - cum[gl]);
            Xs[k][m] = g_xBC[sg*CONV_DIM + h*HEADDIM + bp + m] * scale;
        }
        for (int i = tid; i < 64*16; i += 256) {
            int k = i / 64, m = i % 64;
            int gl = k0 + k;
            long sg = (long)b*SEQ + c*CHUNK + gl;
            Bs[k][m] = g_xBC[sg*CONV_DIM + D_INNER + bn + m];
        }
        __syncthreads();
        #pragma unroll
        for (int k = 0; k < 16; k++) {
            float a[4], bb[4];
            #pragma unroll
            for (int i = 0; i < 4; i++) a[i]  = Xs[k][ty*4+i];
            #pragma unroll
            for (int j = 0; j < 4; j++) bb[j] = Bs[k][tx*4+j];
            #pragma unroll
            for (int i = 0; i < 4; i++)
                #pragma unroll
                for (int j = 0; j < 4; j++)
                    acc[i][j] = fmaf(a[i], bb[j], acc[i][j]);
        }
        __syncthreads();
    }
    long base = ((long)bc*N_HEADS + h)*HEADDIM*D_STATE;
    #pragma unroll
    for (int i = 0; i < 4; i++)
        #pragma unroll
        for (int j = 0; j < 4; j++) {
            int gp = bp + ty*4 + i, gn = bn + tx*4 + j;
            g_states[base + (long)gp*D_STATE + gn] = acc[i][j];
        }
}

// ---------------- sequential inter-chunk state recurrence -----------------
__global__ __launch_bounds__(256)
void k_chunkrec()
{
    int bh = blockIdx.x;
    int h = bh % N_HEADS; int b = bh / N_HEADS;
    const float* cum = g_dAcum + (long)bh*SEQ;
    float csum[NCHUNK];
    #pragma unroll
    for (int c = 0; c < NCHUNK; c++) csum[c] = expf(cum[c*CHUNK + CHUNK-1]);
    for (int pn = threadIdx.x; pn < HEADDIM*D_STATE; pn += 256) {
        float carry = 0.f;
        #pragma unroll
        for (int c = 0; c < NCHUNK; c++) {
            long idx = (((long)b*NCHUNK + c)*N_HEADS + h)*HEADDIM*D_STATE + pn;
            g_states_in[idx] = carry;
            carry = carry * csum[c] + g_states[idx];
        }
    }
}

// ---------------- Y_off ---------------------------------------------------
__global__ __launch_bounds__(256)
void k_yoff()
{
    int bz = blockIdx.z;
    int h = bz % N_HEADS; int bc = bz / N_HEADS;
    int c = bc % NCHUNK;  int b  = bc / NCHUNK;
    int bl = blockIdx.y * 64;
    int bp = blockIdx.x * 64;
    int tid = threadIdx.x;
    int tx = tid % 16, ty = tid / 16;
    const float* cum = g_dAcum + ((long)b*N_HEADS + h)*SEQ + (long)c*CHUNK;
    const float* Sin = g_states_in + ((long)bc*N_HEADS + h)*HEADDIM*D_STATE;
    __shared__ float Cs[16][68];
    __shared__ float Ss[16][68];
    float acc[4][4] = {};
    for (int k0 = 0; k0 < D_STATE; k0 += 16) {
        for (int i = tid; i < 64*16; i += 256) {
            int m = i / 16, k = i % 16;
            long sg = (long)b*SEQ + c*CHUNK + bl + m;
            Cs[k][m] = g_xBC[sg*CONV_DIM + D_INNER + D_STATE + k0 + k];
        }
        for (int i = tid; i < 64*16; i += 256) {
            int m = i / 16, k = i % 16;
            Ss[k][m] = Sin[(long)(bp + m)*D_STATE + k0 + k];
        }
        __syncthreads();
        #pragma unroll
        for (int k = 0; k < 16; k++) {
            float a[4], bb[4];
            #pragma unroll
            for (int i = 0; i < 4; i++) a[i]  = Cs[k][ty*4+i];
            #pragma unroll
            for (int j = 0; j < 4; j++) bb[j] = Ss[k][tx*4+j];
            #pragma unroll
            for (int i = 0; i < 4; i++)
                #pragma unroll
                for (int j = 0; j < 4; j++)
                    acc[i][j] = fmaf(a[i], bb[j], acc[i][j]);
        }
        __syncthreads();
    }
    #pragma unroll
    for (int i = 0; i < 4; i++) {
        int gl = bl + ty*4 + i;
        float sc = expf(cum[gl]);
        long sg = (long)b*SEQ + c*CHUNK + gl;
        #pragma unroll
        for (int j = 0; j < 4; j++) {
            int gp = bp + tx*4 + j;
            g_y[sg*D_INNER + h*HEADDIM + gp] += sc * acc[i][j];
        }
    }
}

// ---------------- gate (y * silu(z)) + RMSNorm ----------------------------
__global__ __launch_bounds__(256)
void k_gatenorm(const float* __restrict__ norm_w)
{
    long row = blockIdx.x;
    const float* zrow = g_zxbcdt + row*D_IN_PROJ;
    float* yrow = g_y + row*D_INNER;
    float vals[16];
    float local = 0.f;
    #pragma unroll
    for (int i = 0; i < 16; i++) {
        int d = threadIdx.x + i*256;
        float z = zrow[d];
        float v = yrow[d] * (z / (1.f + expf(-z)));
        vals[i] = v;
        local += v * v;
    }
    __shared__ float red[256];
    red[threadIdx.x] = local; __syncthreads();
    for (int off = 128; off > 0; off >>= 1) {
        if (threadIdx.x < off) red[threadIdx.x] += red[threadIdx.x + off];
        __syncthreads();
    }
    float scale = rsqrtf(red[0] / D_INNER + EPS);
    #pragma unroll
    for (int i = 0; i < 16; i++) {
        int d = threadIdx.x + i*256;
        yrow[d] = vals[i] * scale * norm_w[d];
    }
}

// --------------------------------------------------------------------------
extern "C" void kernel_launch(void* const* d_in, const int* in_sizes, int n_in,
                              void* d_out, int out_size)
{
    const float* inputs     = (const float*)d_in[0];
    const float* in_proj_w  = (const float*)d_in[1];
    const float* in_proj_b  = (const float*)d_in[2];
    const float* out_proj_w = (const float*)d_in[3];
    const float* out_proj_b = (const float*)d_in[4];
    const float* conv_w     = (const float*)d_in[5];
    const float* conv_b     = (const float*)d_in[6];
    const float* dt_bias    = (const float*)d_in[7];
    const float* A_log      = (const float*)d_in[8];
    const float* Dv         = (const float*)d_in[9];
    const float* norm_w     = (const float*)d_in[10];
    float* out = (float*)d_out;

    float *zx, *xbc, *Gp, *yp;
    cudaGetSymbolAddress((void**)&zx,  g_zxbcdt);
    cudaGetSymbolAddress((void**)&xbc, g_xBC);
    cudaGetSymbolAddress((void**)&Gp,  g_G);
    cudaGetSymbolAddress((void**)&yp,  g_y);

    const int M = BATCH * SEQ;     // 4096

    // 1) in_proj (pipelined tf32)
    {
        dim3 grid((D_IN_PROJ + 127)/128, M/128, 1);
        gemm_tf32<<<grid, 256>>>(inputs, DIM, 0, in_proj_w, DIM, 0,
                                 zx, D_IN_PROJ, 0, M, D_IN_PROJ, DIM, in_proj_b);
    }
    // 2) exact fp32 dt projection + softplus
    k_dtproj<<<M/32, 256>>>(inputs, in_proj_w, in_proj_b, dt_bias);
    // 3) conv + silu
    k_conv<<<(int)(((long)BATCH*SEQ*CONV_DIM + 255)/256), 256>>>(conv_w, conv_b);
    // 4) chunk-local cumsum of A*dt
    k_cumsum<<<BATCH*N_HEADS*NCHUNK, CHUNK>>>(A_log);
    // 5) G = C @ B^T per (b,c)
    {
        dim3 grid(CHUNK/128, CHUNK/128, BATCH*NCHUNK);
        gemm_tf32<<<grid, 256>>>(xbc + D_INNER + D_STATE, CONV_DIM, (long)CHUNK*CONV_DIM,
                                 xbc + D_INNER,           CONV_DIM, (long)CHUNK*CONV_DIM,
                                 Gp, CHUNK, (long)CHUNK*CHUNK,
                                 CHUNK, CHUNK, D_STATE, nullptr);
    }
    // 6) Y_diag + D*x
    {
        dim3 grid(HEADDIM/64, CHUNK/64, BATCH*NCHUNK*N_HEADS);
        k_ydiag<<<grid, 256>>>(Dv);
    }
    // 7) per-chunk states
    {
        dim3 grid(D_STATE/64, HEADDIM/64, BATCH*NCHUNK*N_HEADS);
        k_states<<<grid, 256>>>();
    }
    // 8) inter-chunk recurrence
    k_chunkrec<<<BATCH*N_HEADS, 256>>>();
    // 9) Y_off +=
    {
        dim3 grid(HEADDIM/64, CHUNK/64, BATCH*NCHUNK*N_HEADS);
        k_yoff<<<grid, 256>>>();
    }
    // 10) gate + RMSNorm
    k_gatenorm<<<BATCH*SEQ, 256>>>(norm_w);
    // 11) out_proj (pipelined tf32)
    {
        dim3 grid(DIM/128, M/128, 1);
        gemm_tf32<<<grid, 256>>>(yp, D_INNER, 0, out_proj_w, D_INNER, 0,
                                 out, DIM, 0, M, DIM, D_INNER, out_proj_b);
    }
}

// round 7
// speedup vs baseline: 5.2925x; 1.4839x over previous
#include <cuda_runtime.h>
#include <cuda_fp16.h>
#include <math.h>
#include <stdint.h>

#define BATCH   2
#define SEQ     2048
#define DIM     2048
#define D_INNER 4096
#define D_STATE 128
#define N_HEADS 32
#define HEADDIM 128
#define D_CONV  4
#define CHUNK   256
#define NCHUNK  (SEQ/CHUNK)                       /* 8  */
#define CONV_DIM (D_INNER + 2*D_STATE)            /* 4352 */
#define D_IN_PROJ (2*D_INNER + 2*D_STATE + N_HEADS) /* 8480 */
#define EPS 1e-5f

// ---------------- scratch (device globals, no allocation) ----------------
__device__ float g_zxbcdt[(size_t)BATCH*SEQ*D_IN_PROJ];
__device__ float g_xBC  [(size_t)BATCH*SEQ*CONV_DIM];
__device__ float g_dt   [(size_t)BATCH*SEQ*N_HEADS];
__device__ float g_dAcum[(size_t)BATCH*N_HEADS*SEQ];
__device__ float g_G    [(size_t)BATCH*NCHUNK*CHUNK*CHUNK];
__device__ float g_states   [(size_t)BATCH*NCHUNK*N_HEADS*HEADDIM*D_STATE];
__device__ float g_states_in[(size_t)BATCH*NCHUNK*N_HEADS*HEADDIM*D_STATE];
__device__ float g_y    [(size_t)BATCH*SEQ*D_INNER];
// fp16 operand mirrors for mma.sync GEMMs
__device__ __half g_in_h  [(size_t)BATCH*SEQ*DIM];
__device__ __half g_win_h [(size_t)D_IN_PROJ*DIM];
__device__ __half g_wout_h[(size_t)DIM*D_INNER];
__device__ __half g_y_h   [(size_t)BATCH*SEQ*D_INNER];
__device__ __half g_bc_h  [(size_t)BATCH*SEQ*2*D_STATE];   // [bs][0:128]=B, [128:256]=C

__device__ __forceinline__ void cp16(uint32_t dst, const void* src, bool pred) {
    asm volatile("cp.async.cg.shared.global [%0], [%1], 16, %2;"
                 :: "r"(dst), "l"(src), "r"(pred ? 16 : 0));
}

// ================== fp16 mma.sync batched NT GEMM =========================
// C = A(MxK) * W(NxK)^T + bias. A,W fp16 row-major (K contig), C fp32.
// Block 128x128, BK=32, 2-stage cp.async, 8 warps (2x4), m16n8k16.
#define HS 40   /* smem row stride in halves: 32 + 8 pad (80B, conflict-free) */
__global__ __launch_bounds__(256)
void gemm_h(const __half* __restrict__ A, long lda, long sA,
            const __half* __restrict__ W, long ldb, long sB,
            float* __restrict__ C, long ldc, long sC,
            int M, int N, int K, const float* __restrict__ bias)
{
    __shared__ __half As[2][128][HS];
    __shared__ __half Bs[2][128][HS];
    int bz = blockIdx.z;
    const __half* Ab = A + (long)bz * sA;
    const __half* Wb = W + (long)bz * sB;
    float*        Cb = C + (long)bz * sC;
    int bm = blockIdx.y * 128, bn = blockIdx.x * 128;
    int tid  = threadIdx.x;
    int warp = tid >> 5, lane = tid & 31;
    int wm = warp >> 2, wn = warp & 3;
    int g  = lane >> 2, t4 = lane & 3;

    uint32_t sAu = (uint32_t)__cvta_generic_to_shared(&As[0][0][0]);
    uint32_t sBu = (uint32_t)__cvta_generic_to_shared(&Bs[0][0][0]);
    const uint32_t STG = 128*HS*2;

    float acc[4][4][4];
    #pragma unroll
    for (int i = 0; i < 4; i++)
        #pragma unroll
        for (int j = 0; j < 4; j++)
            #pragma unroll
            for (int q = 0; q < 4; q++) acc[i][j][q] = 0.f;

    const int KT = K / 32;

    // loader: per operand 128 rows x 32 halves = 512 x 8-half chunks
    #define LOADTILE(st, k0)                                                  \
    do {                                                                      \
        _Pragma("unroll")                                                     \
        for (int it = 0; it < 2; it++) {                                      \
            int idx = tid + it*256;                                           \
            int row = idx >> 2, c8 = (idx & 3) * 8;                           \
            cp16(sAu + (st)*STG + (row*HS + c8)*2,                            \
                 &Ab[(long)(bm+row)*lda + (k0) + c8], true);                  \
        }                                                                     \
        _Pragma("unroll")                                                     \
        for (int it = 0; it < 2; it++) {                                      \
            int idx = tid + it*256;                                           \
            int row = idx >> 2, c8 = (idx & 3) * 8;                           \
            int gn = bn + row; bool p = gn < N;                               \
            cp16(sBu + (st)*STG + (row*HS + c8)*2,                            \
                 &Wb[(long)(p ? gn : 0)*ldb + (k0) + c8], p);                 \
        }                                                                     \
    } while (0)

    LOADTILE(0, 0);
    asm volatile("cp.async.commit_group;");

    for (int kt = 0; kt < KT; kt++) {
        asm volatile("cp.async.wait_group 0;" ::: "memory");
        __syncthreads();
        if (kt + 1 < KT) LOADTILE((kt+1) & 1, (kt+1)*32);
        asm volatile("cp.async.commit_group;");

        int st = kt & 1;
        #pragma unroll
        for (int ks = 0; ks < 2; ks++) {
            int kb = ks * 16;
            uint32_t af[4][4], bf[4][2];
            #pragma unroll
            for (int mt = 0; mt < 4; mt++) {
                int r0 = wm*64 + mt*16 + g;
                af[mt][0] = *(const uint32_t*)&As[st][r0  ][kb + t4*2    ];
                af[mt][1] = *(const uint32_t*)&As[st][r0+8][kb + t4*2    ];
                af[mt][2] = *(const uint32_t*)&As[st][r0  ][kb + t4*2 + 8];
                af[mt][3] = *(const uint32_t*)&As[st][r0+8][kb + t4*2 + 8];
            }
            #pragma unroll
            for (int nt = 0; nt < 4; nt++) {
                int cc = wn*32 + nt*8 + g;
                bf[nt][0] = *(const uint32_t*)&Bs[st][cc][kb + t4*2    ];
                bf[nt][1] = *(const uint32_t*)&Bs[st][cc][kb + t4*2 + 8];
            }
            #pragma unroll
            for (int mt = 0; mt < 4; mt++)
                #pragma unroll
                for (int nt = 0; nt < 4; nt++) {
                    asm volatile(
                        "mma.sync.aligned.m16n8k16.row.col.f32.f16.f16.f32 "
                        "{%0,%1,%2,%3}, {%4,%5,%6,%7}, {%8,%9}, {%0,%1,%2,%3};"
                        : "+f"(acc[mt][nt][0]), "+f"(acc[mt][nt][1]),
                          "+f"(acc[mt][nt][2]), "+f"(acc[mt][nt][3])
                        : "r"(af[mt][0]), "r"(af[mt][1]), "r"(af[mt][2]), "r"(af[mt][3]),
                          "r"(bf[nt][0]), "r"(bf[nt][1]));
                }
        }
    }
    #undef LOADTILE

    // epilogue (same m16n8 layout as tf32 path)
    #pragma unroll
    for (int mt = 0; mt < 4; mt++) {
        int row0 = bm + wm*64 + mt*16 + g;
        #pragma unroll
        for (int nt = 0; nt < 4; nt++) {
            int col0 = bn + wn*32 + nt*8 + 2*t4;
            if (col0 < N) {
                float b0 = bias ? bias[col0] : 0.f;
                Cb[(long)row0*ldc + col0] = acc[mt][nt][0] + b0;
                Cb[(long)(row0+8)*ldc + col0] = acc[mt][nt][2] + b0;
            }
            if (col0+1 < N) {
                float b1 = bias ? bias[col0+1] : 0.f;
                Cb[(long)row0*ldc + col0+1] = acc[mt][nt][1] + b1;
                Cb[(long)(row0+8)*ldc + col0+1] = acc[mt][nt][3] + b1;
            }
        }
    }
}

// ---------------- fp32 -> fp16 conversion (vectorized) --------------------
__global__ __launch_bounds__(256)
void k_tohalf(const float* __restrict__ src, __half* __restrict__ dst, long n2)
{
    long i = (long)blockIdx.x * 256 + threadIdx.x;
    long stride = (long)gridDim.x * 256;
    for (; i < n2; i += stride) {
        float2 v = *reinterpret_cast<const float2*>(src + i*2);
        *reinterpret_cast<__half2*>(dst + i*2) = __floats2half2_rn(v.x, v.y);
    }
}

// ---------------- exact fp32 dt projection + softplus (tiled) -------------
__global__ __launch_bounds__(256)
void k_dtproj(const float* __restrict__ inputs,
              const float* __restrict__ in_proj_w,
              const float* __restrict__ in_proj_b,
              const float* __restrict__ dt_bias)
{
    __shared__ float xs[32][133];
    __shared__ float ws[32][133];
    int t = threadIdx.x;
    long r0 = (long)blockIdx.x * 32;
    int r = t >> 3;
    int hb = (t & 7) * 4;
    const float* Wdt = in_proj_w + (size_t)(D_INNER + CONV_DIM) * DIM;
    float acc[4] = {0.f, 0.f, 0.f, 0.f};
    for (int k0 = 0; k0 < DIM; k0 += 128) {
        #pragma unroll
        for (int i = 0; i < 4; i++) {
            int idx = t + i*256;
            int row = idx >> 5, c4 = (idx & 31) * 4;
            float4 v = *reinterpret_cast<const float4*>(&inputs[(r0+row)*DIM + k0 + c4]);
            xs[row][c4] = v.x; xs[row][c4+1] = v.y; xs[row][c4+2] = v.z; xs[row][c4+3] = v.w;
            float4 w = *reinterpret_cast<const float4*>(&Wdt[(size_t)row*DIM + k0 + c4]);
            ws[row][c4] = w.x; ws[row][c4+1] = w.y; ws[row][c4+2] = w.z; ws[row][c4+3] = w.w;
        }
        __syncthreads();
        #pragma unroll 8
        for (int k = 0; k < 128; k++) {
            float xv = xs[r][k];
            #pragma unroll
            for (int j = 0; j < 4; j++)
                acc[j] = fmaf(xv, ws[hb+j][k], acc[j]);
        }
        __syncthreads();
    }
    #pragma unroll
    for (int j = 0; j < 4; j++) {
        int h = hb + j;
        float x = acc[j] + in_proj_b[D_INNER + CONV_DIM + h] + dt_bias[h];
        g_dt[(r0 + r)*N_HEADS + h] = (x > 20.f) ? x : log1pf(expf(x));
    }
}

// ---------------- causal depthwise conv + SiLU (+ fp16 BC mirror) ---------
__global__ __launch_bounds__(256)
void k_conv(const float* __restrict__ conv_w, const float* __restrict__ conv_b)
{
    long i = (long)blockIdx.x * 256 + threadIdx.x;
    if (i >= (long)BATCH*SEQ*CONV_DIM) return;
    int c = (int)(i % CONV_DIM);
    long bs = i / CONV_DIM;
    int s = (int)(bs % SEQ);
    int b = (int)(bs / SEQ);
    float acc = conv_b[c];
    #pragma unroll
    for (int k = 0; k < D_CONV; k++) {
        int sp = s - (D_CONV-1) + k;
        if (sp >= 0)
            acc = fmaf(g_zxbcdt[((long)b*SEQ + sp)*D_IN_PROJ + D_INNER + c],
                       conv_w[c*D_CONV + k], acc);
    }
    float v = acc / (1.f + expf(-acc));
    g_xBC[i] = v;
    if (c >= D_INNER)
        g_bc_h[bs*(2*D_STATE) + (c - D_INNER)] = __float2half_rn(v);
}

// ---------------- chunk-local inclusive cumsum of A*dt --------------------
__global__ __launch_bounds__(CHUNK)
void k_cumsum(const float* __restrict__ A_log)
{
    int bz = blockIdx.x;
    int c = bz % NCHUNK; int bh = bz / NCHUNK;
    int h = bh % N_HEADS; int b = bh / N_HEADS;
    int l = threadIdx.x;
    int sg = c*CHUNK + l;
    float A = -expf(A_log[h]);
    float val = A * g_dt[((long)b*SEQ + sg)*N_HEADS + h];
    __shared__ float buf[CHUNK];
    buf[l] = val; __syncthreads();
    for (int off = 1; off < CHUNK; off <<= 1) {
        float t = (l >= off) ? buf[l-off] : 0.f;
        __syncthreads();
        buf[l] += t;
        __syncthreads();
    }
    g_dAcum[((long)b*N_HEADS + h)*SEQ + sg] = buf[l];
}

// ---------------- Y_diag = (L*G) @ X + D*x --------------------------------
__global__ __launch_bounds__(256)
void k_ydiag(const float* __restrict__ Dv)
{
    int bz = blockIdx.z;
    int h = bz % N_HEADS; int bc = bz / N_HEADS;
    int c = bc % NCHUNK;  int b  = bc / NCHUNK;
    int bl = blockIdx.y * 64;
    int bp = blockIdx.x * 64;
    int tid = threadIdx.x;
    int tx = tid % 16, ty = tid / 16;
    const float* cum = g_dAcum + ((long)b*N_HEADS + h)*SEQ + (long)c*CHUNK;
    const float* Gm  = g_G + (long)bc*CHUNK*CHUNK;
    __shared__ float Ls[16][68];
    __shared__ float Xs[16][68];
    __shared__ float cum_l[64];
    if (tid < 64) cum_l[tid] = cum[bl + tid];
    float acc[4][4] = {};
    for (int k0 = 0; k0 < CHUNK; k0 += 16) {
        if (k0 > bl + 63) break;
        __syncthreads();
        for (int i = tid; i < 64*16; i += 256) {
            int m = i / 16, k = i % 16;
            int gl = bl + m, gs = k0 + k;
            float v = 0.f;
            if (gs <= gl) v = Gm[(long)gl*CHUNK + gs] * expf(cum_l[m] - cum[gs]);
            Ls[k][m] = v;
        }
        for (int i = tid; i < 64*16; i += 256) {
            int k = i / 64, n = i % 64;
            int gs = k0 + k; int gp = bp + n;
            long sg = (long)b*SEQ + c*CHUNK + gs;
            float xv = g_xBC[sg*CONV_DIM + h*HEADDIM + gp];
            Xs[k][n] = xv * g_dt[sg*N_HEADS + h];
        }
        __syncthreads();
        #pragma unroll
        for (int k = 0; k < 16; k++) {
            float a[4], bb[4];
            #pragma unroll
            for (int i = 0; i < 4; i++) a[i]  = Ls[k][ty*4+i];
            #pragma unroll
            for (int j = 0; j < 4; j++) bb[j] = Xs[k][tx*4+j];
            #pragma unroll
            for (int i = 0; i < 4; i++)
                #pragma unroll
                for (int j = 0; j < 4; j++)
                    acc[i][j] = fmaf(a[i], bb[j], acc[i][j]);
        }
    }
    float Dh = Dv[h];
    #pragma unroll
    for (int i = 0; i < 4; i++)
        #pragma unroll
        for (int j = 0; j < 4; j++) {
            int gl = bl + ty*4 + i, gp = bp + tx*4 + j;
            long sg = (long)b*SEQ + c*CHUNK + gl;
            float xraw = g_xBC[sg*CONV_DIM + h*HEADDIM + gp];
            g_y[sg*D_INNER + h*HEADDIM + gp] = acc[i][j] + Dh * xraw;
        }
}

// ---------------- chunk states ------------------------------------------
__global__ __launch_bounds__(256)
void k_states()
{
    int bz = blockIdx.z;
    int h = bz % N_HEADS; int bc = bz / N_HEADS;
    int c = bc % NCHUNK;  int b  = bc / NCHUNK;
    int bp = blockIdx.y * 64;
    int bn = blockIdx.x * 64;
    int tid = threadIdx.x;
    int tx = tid % 16, ty = tid / 16;
    const float* cum = g_dAcum + ((long)b*N_HEADS + h)*SEQ + (long)c*CHUNK;
    float cum_last = cum[CHUNK-1];
    __shared__ float Xs[16][68];
    __shared__ float Bs[16][68];
    float acc[4][4] = {};
    for (int k0 = 0; k0 < CHUNK; k0 += 16) {
        for (int i = tid; i < 64*16; i += 256) {
            int k = i / 64, m = i % 64;
            int gl = k0 + k;
            long sg = (long)b*SEQ + c*CHUNK + gl;
            float scale = g_dt[sg*N_HEADS + h] * expf(cum_last - cum[gl]);
            Xs[k][m] = g_xBC[sg*CONV_DIM + h*HEADDIM + bp + m] * scale;
        }
        for (int i = tid; i < 64*16; i += 256) {
            int k = i / 64, m = i % 64;
            int gl = k0 + k;
            long sg = (long)b*SEQ + c*CHUNK + gl;
            Bs[k][m] = g_xBC[sg*CONV_DIM + D_INNER + bn + m];
        }
        __syncthreads();
        #pragma unroll
        for (int k = 0; k < 16; k++) {
            float a[4], bb[4];
            #pragma unroll
            for (int i = 0; i < 4; i++) a[i]  = Xs[k][ty*4+i];
            #pragma unroll
            for (int j = 0; j < 4; j++) bb[j] = Bs[k][tx*4+j];
            #pragma unroll
            for (int i = 0; i < 4; i++)
                #pragma unroll
                for (int j = 0; j < 4; j++)
                    acc[i][j] = fmaf(a[i], bb[j], acc[i][j]);
        }
        __syncthreads();
    }
    long base = ((long)bc*N_HEADS + h)*HEADDIM*D_STATE;
    #pragma unroll
    for (int i = 0; i < 4; i++)
        #pragma unroll
        for (int j = 0; j < 4; j++) {
            int gp = bp + ty*4 + i, gn = bn + tx*4 + j;
            g_states[base + (long)gp*D_STATE + gn] = acc[i][j];
        }
}

// ---------------- sequential inter-chunk state recurrence -----------------
__global__ __launch_bounds__(256)
void k_chunkrec()
{
    int bh = blockIdx.x;
    int h = bh % N_HEADS; int b = bh / N_HEADS;
    const float* cum = g_dAcum + (long)bh*SEQ;
    float csum[NCHUNK];
    #pragma unroll
    for (int c = 0; c < NCHUNK; c++) csum[c] = expf(cum[c*CHUNK + CHUNK-1]);
    for (int pn = threadIdx.x; pn < HEADDIM*D_STATE; pn += 256) {
        float carry = 0.f;
        #pragma unroll
        for (int c = 0; c < NCHUNK; c++) {
            long idx = (((long)b*NCHUNK + c)*N_HEADS + h)*HEADDIM*D_STATE + pn;
            g_states_in[idx] = carry;
            carry = carry * csum[c] + g_states[idx];
        }
    }
}

// ---------------- Y_off ---------------------------------------------------
__global__ __launch_bounds__(256)
void k_yoff()
{
    int bz = blockIdx.z;
    int h = bz % N_HEADS; int bc = bz / N_HEADS;
    int c = bc % NCHUNK;  int b  = bc / NCHUNK;
    int bl = blockIdx.y * 64;
    int bp = blockIdx.x * 64;
    int tid = threadIdx.x;
    int tx = tid % 16, ty = tid / 16;
    const float* cum = g_dAcum + ((long)b*N_HEADS + h)*SEQ + (long)c*CHUNK;
    const float* Sin = g_states_in + ((long)bc*N_HEADS + h)*HEADDIM*D_STATE;
    __shared__ float Cs[16][68];
    __shared__ float Ss[16][68];
    float acc[4][4] = {};
    for (int k0 = 0; k0 < D_STATE; k0 += 16) {
        for (int i = tid; i < 64*16; i += 256) {
            int m = i / 16, k = i % 16;
            long sg = (long)b*SEQ + c*CHUNK + bl + m;
            Cs[k][m] = g_xBC[sg*CONV_DIM + D_INNER + D_STATE + k0 + k];
        }
        for (int i = tid; i < 64*16; i += 256) {
            int m = i / 16, k = i % 16;
            Ss[k][m] = Sin[(long)(bp + m)*D_STATE + k0 + k];
        }
        __syncthreads();
        #pragma unroll
        for (int k = 0; k < 16; k++) {
            float a[4], bb[4];
            #pragma unroll
            for (int i = 0; i < 4; i++) a[i]  = Cs[k][ty*4+i];
            #pragma unroll
            for (int j = 0; j < 4; j++) bb[j] = Ss[k][tx*4+j];
            #pragma unroll
            for (int i = 0; i < 4; i++)
                #pragma unroll
                for (int j = 0; j < 4; j++)
                    acc[i][j] = fmaf(a[i], bb[j], acc[i][j]);
        }
        __syncthreads();
    }
    #pragma unroll
    for (int i = 0; i < 4; i++) {
        int gl = bl + ty*4 + i;
        float sc = expf(cum[gl]);
        long sg = (long)b*SEQ + c*CHUNK + gl;
        #pragma unroll
        for (int j = 0; j < 4; j++) {
            int gp = bp + tx*4 + j;
            g_y[sg*D_INNER + h*HEADDIM + gp] += sc * acc[i][j];
        }
    }
}

// ---------------- gate + RMSNorm -> fp16 y --------------------------------
__global__ __launch_bounds__(256)
void k_gatenorm(const float* __restrict__ norm_w)
{
    long row = blockIdx.x;
    const float* zrow = g_zxbcdt + row*D_IN_PROJ;
    float* yrow = g_y + row*D_INNER;
    __half* yh = g_y_h + row*D_INNER;
    float vals[16];
    float local = 0.f;
    #pragma unroll
    for (int i = 0; i < 16; i++) {
        int d = threadIdx.x + i*256;
        float z = zrow[d];
        float v = yrow[d] * (z / (1.f + expf(-z)));
        vals[i] = v;
        local += v * v;
    }
    __shared__ float red[256];
    red[threadIdx.x] = local; __syncthreads();
    for (int off = 128; off > 0; off >>= 1) {
        if (threadIdx.x < off) red[threadIdx.x] += red[threadIdx.x + off];
        __syncthreads();
    }
    float scale = rsqrtf(red[0] / D_INNER + EPS);
    #pragma unroll
    for (int i = 0; i < 16; i++) {
        int d = threadIdx.x + i*256;
        yh[d] = __float2half_rn(vals[i] * scale * norm_w[d]);
    }
}

// --------------------------------------------------------------------------
extern "C" void kernel_launch(void* const* d_in, const int* in_sizes, int n_in,
                              void* d_out, int out_size)
{
    const float* inputs     = (const float*)d_in[0];
    const float* in_proj_w  = (const float*)d_in[1];
    const float* in_proj_b  = (const float*)d_in[2];
    const float* out_proj_w = (const float*)d_in[3];
    const float* out_proj_b = (const float*)d_in[4];
    const float* conv_w     = (const float*)d_in[5];
    const float* conv_b     = (const float*)d_in[6];
    const float* dt_bias    = (const float*)d_in[7];
    const float* A_log      = (const float*)d_in[8];
    const float* Dv         = (const float*)d_in[9];
    const float* norm_w     = (const float*)d_in[10];
    float* out = (float*)d_out;

    float *zx, *Gp;
    __half *inh, *winh, *wouth, *yh, *bch;
    cudaGetSymbolAddress((void**)&zx,    g_zxbcdt);
    cudaGetSymbolAddress((void**)&Gp,    g_G);
    cudaGetSymbolAddress((void**)&inh,   g_in_h);
    cudaGetSymbolAddress((void**)&winh,  g_win_h);
    cudaGetSymbolAddress((void**)&wouth, g_wout_h);
    cudaGetSymbolAddress((void**)&yh,    g_y_h);
    cudaGetSymbolAddress((void**)&bch,   g_bc_h);

    const int M = BATCH * SEQ;     // 4096

    // 0) fp16 mirrors of GEMM operands
    k_tohalf<<<2048, 256>>>(inputs,     inh,   (long)M*DIM/2);
    k_tohalf<<<2048, 256>>>(in_proj_w,  winh,  (long)D_IN_PROJ*DIM/2);
    k_tohalf<<<2048, 256>>>(out_proj_w, wouth, (long)DIM*D_INNER/2);

    // 1) in_proj (fp16 mma.sync)
    {
        dim3 grid((D_IN_PROJ + 127)/128, M/128, 1);
        gemm_h<<<grid, 256>>>(inh, DIM, 0, winh, DIM, 0,
                              zx, D_IN_PROJ, 0, M, D_IN_PROJ, DIM, in_proj_b);
    }
    // 2) exact fp32 dt projection + softplus
    k_dtproj<<<M/32, 256>>>(inputs, in_proj_w, in_proj_b, dt_bias);
    // 3) conv + silu (also writes fp16 BC mirror)
    k_conv<<<(int)(((long)BATCH*SEQ*CONV_DIM + 255)/256), 256>>>(conv_w, conv_b);
    // 4) chunk-local cumsum of A*dt
    k_cumsum<<<BATCH*N_HEADS*NCHUNK, CHUNK>>>(A_log);
    // 5) G = C @ B^T per (b,c)  (fp16 mma.sync)
    {
        dim3 grid(CHUNK/128, CHUNK/128, BATCH*NCHUNK);
        gemm_h<<<grid, 256>>>(bch + D_STATE, 2*D_STATE, (long)CHUNK*2*D_STATE,
                              bch,           2*D_STATE, (long)CHUNK*2*D_STATE,
                              Gp, CHUNK, (long)CHUNK*CHUNK,
                              CHUNK, CHUNK, D_STATE, nullptr);
    }
    // 6) Y_diag + D*x
    {
        dim3 grid(HEADDIM/64, CHUNK/64, BATCH*NCHUNK*N_HEADS);
        k_ydiag<<<grid, 256>>>(Dv);
    }
    // 7) per-chunk states
    {
        dim3 grid(D_STATE/64, HEADDIM/64, BATCH*NCHUNK*N_HEADS);
        k_states<<<grid, 256>>>();
    }
    // 8) inter-chunk recurrence
    k_chunkrec<<<BATCH*N_HEADS, 256>>>();
    // 9) Y_off +=
    {
        dim3 grid(HEADDIM/64, CHUNK/64, BATCH*NCHUNK*N_HEADS);
        k_yoff<<<grid, 256>>>();
    }
    // 10) gate + RMSNorm -> fp16 y
    k_gatenorm<<<BATCH*SEQ, 256>>>(norm_w);
    // 11) out_proj (fp16 mma.sync)
    {
        dim3 grid(DIM/128, M/128, 1);
        gemm_h<<<grid, 256>>>(yh, D_INNER, 0, wouth, D_INNER, 0,
                              out, DIM, 0, M, DIM, D_INNER, out_proj_b);
    }
}

// round 8
// speedup vs baseline: 6.6555x; 1.2575x over previous
#include <cuda_runtime.h>
#include <cuda_fp16.h>
#include <math.h>
#include <stdint.h>

#define BATCH   2
#define SEQ     2048
#define DIM     2048
#define D_INNER 4096
#define D_STATE 128
#define N_HEADS 32
#define HEADDIM 128
#define D_CONV  4
#define CHUNK   256
#define NCHUNK  (SEQ/CHUNK)                       /* 8  */
#define NBCH    (BATCH*NCHUNK*N_HEADS)            /* 512 */
#define CONV_DIM (D_INNER + 2*D_STATE)            /* 4352 */
#define D_IN_PROJ (2*D_INNER + 2*D_STATE + N_HEADS) /* 8480 */
#define EPS 1e-5f

// ---------------- scratch (device globals, no allocation) ----------------
__device__ float g_zxbcdt[(size_t)BATCH*SEQ*D_IN_PROJ];
__device__ float g_xBC  [(size_t)BATCH*SEQ*CONV_DIM];
__device__ float g_dt   [(size_t)BATCH*SEQ*N_HEADS];
__device__ float g_dAcum[(size_t)BATCH*N_HEADS*SEQ];
__device__ float g_G    [(size_t)BATCH*NCHUNK*CHUNK*CHUNK];
__device__ float g_states[(size_t)NBCH*HEADDIM*D_STATE];
__device__ float g_y    [(size_t)BATCH*SEQ*D_INNER];
// fp16 operand mirrors
__device__ __half g_in_h  [(size_t)BATCH*SEQ*DIM];
__device__ __half g_win_h [(size_t)D_IN_PROJ*DIM];
__device__ __half g_wout_h[(size_t)DIM*D_INNER];
__device__ __half g_y_h   [(size_t)BATCH*SEQ*D_INNER];
__device__ __half g_bc_h  [(size_t)BATCH*SEQ*2*D_STATE];
// fp16 scan operands
__device__ __half g_xdt_h [(size_t)BATCH*SEQ*D_INNER];
__device__ __half g_LG    [(size_t)NBCH*CHUNK*CHUNK];
__device__ __half g_Bdec  [(size_t)NBCH*CHUNK*D_STATE];
__device__ __half g_Cexp  [(size_t)NBCH*CHUNK*D_STATE];
__device__ __half g_sin_h [(size_t)NBCH*HEADDIM*D_STATE];

__device__ __forceinline__ void cp16(uint32_t dst, const void* src, bool pred) {
    asm volatile("cp.async.cg.shared.global [%0], [%1], 16, %2;"
                 :: "r"(dst), "l"(src), "r"(pred ? 16 : 0));
}
// fast exp on FMA pipe: exp(x) for x<=0, flush to 0 below ~ -17
__device__ __forceinline__ float fexp(float x) {
    float t = x * 1.4426950408889634f;
    t = fmaxf(t, -25.f);
    float fi = floorf(t);
    float f = t - fi;
    float p = 1.f + f*(0.69314718f + f*(0.24022651f + f*(0.05550411f
            + f*(0.00961813f + f*0.00133336f))));
    return p * __int_as_float(((int)fi + 127) << 23);
}

#define MMA16(acc, af, bf)                                                   \
    asm volatile(                                                            \
        "mma.sync.aligned.m16n8k16.row.col.f32.f16.f16.f32 "                 \
        "{%0,%1,%2,%3}, {%4,%5,%6,%7}, {%8,%9}, {%0,%1,%2,%3};"              \
        : "+f"(acc[0]), "+f"(acc[1]), "+f"(acc[2]), "+f"(acc[3])             \
        : "r"(af[0]), "r"(af[1]), "r"(af[2]), "r"(af[3]),                    \
          "r"(bf[0]), "r"(bf[1]))

// ================== fp16 mma.sync batched NT GEMM (projections) ===========
#define HS 40
__global__ __launch_bounds__(256)
void gemm_h(const __half* __restrict__ A, long lda, long sA,
            const __half* __restrict__ W, long ldb, long sB,
            float* __restrict__ C, long ldc, long sC,
            int M, int N, int K, const float* __restrict__ bias)
{
    __shared__ __half As[2][128][HS];
    __shared__ __half Bs[2][128][HS];
    int bz = blockIdx.z;
    const __half* Ab = A + (long)bz * sA;
    const __half* Wb = W + (long)bz * sB;
    float*        Cb = C + (long)bz * sC;
    int bm = blockIdx.y * 128, bn = blockIdx.x * 128;
    int tid  = threadIdx.x;
    int warp = tid >> 5, lane = tid & 31;
    int wm = warp >> 2, wn = warp & 3;
    int g  = lane >> 2, t4 = lane & 3;

    uint32_t sAu = (uint32_t)__cvta_generic_to_shared(&As[0][0][0]);
    uint32_t sBu = (uint32_t)__cvta_generic_to_shared(&Bs[0][0][0]);
    const uint32_t STG = 128*HS*2;

    float acc[4][4][4];
    #pragma unroll
    for (int i = 0; i < 4; i++)
        #pragma unroll
        for (int j = 0; j < 4; j++)
            #pragma unroll
            for (int q = 0; q < 4; q++) acc[i][j][q] = 0.f;

    const int KT = K / 32;

    #define LOADTILE(st, k0)                                                  \
    do {                                                                      \
        _Pragma("unroll")                                                     \
        for (int it = 0; it < 2; it++) {                                      \
            int idx = tid + it*256;                                           \
            int row = idx >> 2, c8 = (idx & 3) * 8;                           \
            cp16(sAu + (st)*STG + (row*HS + c8)*2,                            \
                 &Ab[(long)(bm+row)*lda + (k0) + c8], true);                  \
        }                                                                     \
        _Pragma("unroll")                                                     \
        for (int it = 0; it < 2; it++) {                                      \
            int idx = tid + it*256;                                           \
            int row = idx >> 2, c8 = (idx & 3) * 8;                           \
            int gn = bn + row; bool p = gn < N;                               \
            cp16(sBu + (st)*STG + (row*HS + c8)*2,                            \
                 &Wb[(long)(p ? gn : 0)*ldb + (k0) + c8], p);                 \
        }                                                                     \
    } while (0)

    LOADTILE(0, 0);
    asm volatile("cp.async.commit_group;");

    for (int kt = 0; kt < KT; kt++) {
        asm volatile("cp.async.wait_group 0;" ::: "memory");
        __syncthreads();
        if (kt + 1 < KT) LOADTILE((kt+1) & 1, (kt+1)*32);
        asm volatile("cp.async.commit_group;");

        int st = kt & 1;
        #pragma unroll
        for (int ks = 0; ks < 2; ks++) {
            int kb = ks * 16;
            uint32_t af[4][4], bf[4][2];
            #pragma unroll
            for (int mt = 0; mt < 4; mt++) {
                int r0 = wm*64 + mt*16 + g;
                af[mt][0] = *(const uint32_t*)&As[st][r0  ][kb + t4*2    ];
                af[mt][1] = *(const uint32_t*)&As[st][r0+8][kb + t4*2    ];
                af[mt][2] = *(const uint32_t*)&As[st][r0  ][kb + t4*2 + 8];
                af[mt][3] = *(const uint32_t*)&As[st][r0+8][kb + t4*2 + 8];
            }
            #pragma unroll
            for (int nt = 0; nt < 4; nt++) {
                int cc = wn*32 + nt*8 + g;
                bf[nt][0] = *(const uint32_t*)&Bs[st][cc][kb + t4*2    ];
                bf[nt][1] = *(const uint32_t*)&Bs[st][cc][kb + t4*2 + 8];
            }
            #pragma unroll
            for (int mt = 0; mt < 4; mt++)
                #pragma unroll
                for (int nt = 0; nt < 4; nt++)
                    MMA16(acc[mt][nt], af[mt], bf[nt]);
        }
    }
    #undef LOADTILE

    #pragma unroll
    for (int mt = 0; mt < 4; mt++) {
        int row0 = bm + wm*64 + mt*16 + g;
        #pragma unroll
        for (int nt = 0; nt < 4; nt++) {
            int col0 = bn + wn*32 + nt*8 + 2*t4;
            if (col0 < N) {
                float b0 = bias ? bias[col0] : 0.f;
                Cb[(long)row0*ldc + col0] = acc[mt][nt][0] + b0;
                Cb[(long)(row0+8)*ldc + col0] = acc[mt][nt][2] + b0;
            }
            if (col0+1 < N) {
                float b1 = bias ? bias[col0+1] : 0.f;
                Cb[(long)row0*ldc + col0+1] = acc[mt][nt][1] + b1;
                Cb[(long)(row0+8)*ldc + col0+1] = acc[mt][nt][3] + b1;
            }
        }
    }
}

// =============== scan GEMMs: 128x128 tile, K-step 32, fp16 ================
#define SS 42   /* smem row stride (halves) for scan kernels */

// helpers shared by scan kernels ------------------------------------------
struct ZIdx { int b, c, h; };
__device__ __forceinline__ ZIdx zdec(int z) {
    ZIdx r; r.h = z % N_HEADS; int bc = z / N_HEADS;
    r.c = bc % NCHUNK; r.b = bc / NCHUNK; return r;
}

// ---- Y_diag = LG @ xdt  (A: [m][k] k-contig, B: [k][n] n-contig) ---------
__global__ __launch_bounds__(256)
void k_ydiag_mma()
{
    __shared__ __half As[128][SS];
    __shared__ __half Bs[128][SS];
    int z = blockIdx.x;
    int bm = blockIdx.y * 128;              // l-tile base within chunk
    ZIdx zi = zdec(z);
    long brow = (long)zi.b*SEQ + zi.c*CHUNK;
    const __half* Ag = g_LG + (long)z*CHUNK*CHUNK + (long)bm*CHUNK;
    const __half* Bg = g_xdt_h + brow*D_INNER + zi.h*HEADDIM;
    int tid = threadIdx.x;
    int warp = tid >> 5, lane = tid & 31;
    int wm = warp >> 2, wn = warp & 3;
    int g = lane >> 2, t4 = lane & 3;

    float acc[2][4][4];
    #pragma unroll
    for (int i = 0; i < 2; i++)
        #pragma unroll
        for (int j = 0; j < 4; j++)
            #pragma unroll
            for (int q = 0; q < 4; q++) acc[i][j][q] = 0.f;

    const int KT = (bm + 128) / 32;         // triangular: skip zero K-tiles
    for (int kt = 0; kt < KT; kt++) {
        int k0 = kt * 32;
        // A: 128 rows x 32 halves, direct
        #pragma unroll
        for (int i = 0; i < 8; i++) {
            int idx = tid + i*256;
            int row = idx >> 4, c2 = (idx & 15) * 2;
            *(__half2*)&As[row][c2] = *(const __half2*)&Ag[(long)row*CHUNK + k0 + c2];
        }
        // B: 32 k-rows x 128 n, transpose into Bs[n][k]
        #pragma unroll
        for (int i = 0; i < 8; i++) {
            int idx = tid + i*256;
            int k = idx >> 6, n2 = (idx & 63) * 2;
            __half2 v = *(const __half2*)&Bg[(long)(k0+k)*D_INNER + n2];
            Bs[n2  ][k] = __low2half(v);
            Bs[n2+1][k] = __high2half(v);
        }
        __syncthreads();
        #pragma unroll
        for (int ks = 0; ks < 2; ks++) {
            int kb = ks * 16;
            uint32_t af[2][4], bf[4][2];
            #pragma unroll
            for (int mt = 0; mt < 2; mt++) {
                int r0 = wm*64 + mt*32 + g;     // 2 mt of 32 rows => m 0..63
                af[mt][0] = *(const uint32_t*)&As[r0   ][kb + t4*2    ];
                af[mt][1] = *(const uint32_t*)&As[r0+ 8][kb + t4*2    ];
                af[mt][2] = *(const uint32_t*)&As[r0   ][kb + t4*2 + 8];
                af[mt][3] = *(const uint32_t*)&As[r0+ 8][kb + t4*2 + 8];
            }
            uint32_t af2[2][4];
            #pragma unroll
            for (int mt = 0; mt < 2; mt++) {
                int r0 = wm*64 + mt*32 + 16 + g;
                af2[mt][0] = *(const uint32_t*)&As[r0   ][kb + t4*2    ];
                af2[mt][1] = *(const uint32_t*)&As[r0+ 8][kb + t4*2    ];
                af2[mt][2] = *(const uint32_t*)&As[r0   ][kb + t4*2 + 8];
                af2[mt][3] = *(const uint32_t*)&As[r0+ 8][kb + t4*2 + 8];
            }
            #pragma unroll
            for (int nt = 0; nt < 4; nt++) {
                int cc = wn*32 + nt*8 + g;
                bf[nt][0] = *(const uint32_t*)&Bs[cc][kb + t4*2    ];
                bf[nt][1] = *(const uint32_t*)&Bs[cc][kb + t4*2 + 8];
            }
            // mt order: (0: rows +0/+8), (1: +16/+24) per 32-row pair, 2 pairs
            #pragma unroll
            for (int nt = 0; nt < 4; nt++) {
                MMA16(acc[0][nt], af[0], bf[nt]);
            }
            #pragma unroll
            for (int nt = 0; nt < 4; nt++) {
                MMA16(acc[1][nt], af2[0], bf[nt]);
            }
            // second 32-row pair accumulates into same acc? NO — need 4 mt.
            // (handled below by remapping: we use 2 pairs x 2 sub => see store)
            #pragma unroll
            for (int nt = 0; nt < 4; nt++) {
                MMA16(acc[0][nt], af[1], bf[nt]);   // placeholder removed
            }
            break;  // unreachable marker
        }
        __syncthreads();
    }
}

// NOTE: k_ydiag_mma above is structurally wrong; real implementation below.
// (kept out of launch path)

// ---- generic scan GEMM core: does A(128xK) @ B -> writes/accum C ---------
// modes: stageA 0=direct(k-contig) 1=transposed(m-contig), same for B;
// out: 0=store to g_y-style ptr, 1=store fp32 plain, 2=accumulate
template<int STAGEA, int STAGEB, int OUTMODE>
__device__ __forceinline__ void scan_gemm_core(
    const __half* Ag, long lda,
    const __half* Bg, long ldb,
    float* Cg, long ldc,
    int KT)
{
    __shared__ __half As[128][SS];
    __shared__ __half Bs[128][SS];
    int tid = threadIdx.x;
    int warp = tid >> 5, lane = tid & 31;
    int wm = warp >> 2, wn = warp & 3;
    int g = lane >> 2, t4 = lane & 3;

    float acc[4][4][4];
    #pragma unroll
    for (int i = 0; i < 4; i++)
        #pragma unroll
        for (int j = 0; j < 4; j++)
            #pragma unroll
            for (int q = 0; q < 4; q++) acc[i][j][q] = 0.f;

    for (int kt = 0; kt < KT; kt++) {
        int k0 = kt * 32;
        if (STAGEA == 0) {
            #pragma unroll
            for (int i = 0; i < 8; i++) {
                int idx = tid + i*256;
                int row = idx >> 4, c2 = (idx & 15) * 2;
                *(__half2*)&As[row][c2] = *(const __half2*)&Ag[(long)row*lda + k0 + c2];
            }
        } else {
            #pragma unroll
            for (int i = 0; i < 8; i++) {
                int idx = tid + i*256;
                int k = idx >> 6, m2 = (idx & 63) * 2;
                __half2 v = *(const __half2*)&Ag[(long)(k0+k)*lda + m2];
                As[m2  ][k] = __low2half(v);
                As[m2+1][k] = __high2half(v);
            }
        }
        if (STAGEB == 0) {
            #pragma unroll
            for (int i = 0; i < 8; i++) {
                int idx = tid + i*256;
                int row = idx >> 4, c2 = (idx & 15) * 2;
                *(__half2*)&Bs[row][c2] = *(const __half2*)&Bg[(long)row*ldb + k0 + c2];
            }
        } else {
            #pragma unroll
            for (int i = 0; i < 8; i++) {
                int idx = tid + i*256;
                int k = idx >> 6, n2 = (idx & 63) * 2;
                __half2 v = *(const __half2*)&Bg[(long)(k0+k)*ldb + n2];
                Bs[n2  ][k] = __low2half(v);
                Bs[n2+1][k] = __high2half(v);
            }
        }
        __syncthreads();
        #pragma unroll
        for (int ks = 0; ks < 2; ks++) {
            int kb = ks * 16;
            uint32_t af[4][4], bf[4][2];
            #pragma unroll
            for (int mt = 0; mt < 4; mt++) {
                int r0 = wm*64 + mt*16 + g;
                af[mt][0] = *(const uint32_t*)&As[r0  ][kb + t4*2    ];
                af[mt][1] = *(const uint32_t*)&As[r0+8][kb + t4*2    ];
                af[mt][2] = *(const uint32_t*)&As[r0  ][kb + t4*2 + 8];
                af[mt][3] = *(const uint32_t*)&As[r0+8][kb + t4*2 + 8];
            }
            #pragma unroll
            for (int nt = 0; nt < 4; nt++) {
                int cc = wn*32 + nt*8 + g;
                bf[nt][0] = *(const uint32_t*)&Bs[cc][kb + t4*2    ];
                bf[nt][1] = *(const uint32_t*)&Bs[cc][kb + t4*2 + 8];
            }
            #pragma unroll
            for (int mt = 0; mt < 4; mt++)
                #pragma unroll
                for (int nt = 0; nt < 4; nt++)
                    MMA16(acc[mt][nt], af[mt], bf[nt]);
        }
        __syncthreads();
    }
    // epilogue
    #pragma unroll
    for (int mt = 0; mt < 4; mt++) {
        int row0 = wm*64 + mt*16 + g;
        #pragma unroll
        for (int nt = 0; nt < 4; nt++) {
            int col0 = wn*32 + nt*8 + 2*t4;
            if (OUTMODE == 2) {
                Cg[(long)row0*ldc + col0  ] += acc[mt][nt][0];
                Cg[(long)row0*ldc + col0+1] += acc[mt][nt][1];
                Cg[(long)(row0+8)*ldc + col0  ] += acc[mt][nt][2];
                Cg[(long)(row0+8)*ldc + col0+1] += acc[mt][nt][3];
            } else {
                Cg[(long)row0*ldc + col0  ] = acc[mt][nt][0];
                Cg[(long)row0*ldc + col0+1] = acc[mt][nt][1];
                Cg[(long)(row0+8)*ldc + col0  ] = acc[mt][nt][2];
                Cg[(long)(row0+8)*ldc + col0+1] = acc[mt][nt][3];
            }
        }
    }
}

// Y_diag: per (z, mtile): C[l][p] = sum_s LG[l][s] * xdt[s][p]
__global__ __launch_bounds__(256)
void k_ydiag2()
{
    int z = blockIdx.x, bm = blockIdx.y * 128;
    ZIdx zi = zdec(z);
    long brow = (long)zi.b*SEQ + zi.c*CHUNK;
    const __half* Ag = g_LG + (long)z*CHUNK*CHUNK + (long)bm*CHUNK;
    const __half* Bg = g_xdt_h + brow*D_INNER + zi.h*HEADDIM;
    float* Cg = g_y + (brow + bm)*D_INNER + zi.h*HEADDIM;
    int KT = (bm + 128) / 32;
    scan_gemm_core<0,1,0>(Ag, CHUNK, Bg, D_INNER, Cg, D_INNER, KT);
}

// states: C[p][n] = sum_l xdt[l][p] * Bdec[l][n]
__global__ __launch_bounds__(256)
void k_states2()
{
    int z = blockIdx.x;
    ZIdx zi = zdec(z);
    long brow = (long)zi.b*SEQ + zi.c*CHUNK;
    const __half* Ag = g_xdt_h + brow*D_INNER + zi.h*HEADDIM;   // [l][p]
    const __half* Bg = g_Bdec + (long)z*CHUNK*D_STATE;          // [l][n]
    float* Cg = g_states + (long)z*HEADDIM*D_STATE;
    scan_gemm_core<1,1,1>(Ag, D_INNER, Bg, D_STATE, Cg, D_STATE, CHUNK/32);
}

// Y_off: C[l][p] += sum_n Cexp[l][n] * Sin[p][n]
__global__ __launch_bounds__(256)
void k_yoff2()
{
    int z = blockIdx.x, bm = blockIdx.y * 128;
    ZIdx zi = zdec(z);
    long brow = (long)zi.b*SEQ + zi.c*CHUNK;
    const __half* Ag = g_Cexp + (long)z*CHUNK*D_STATE + (long)bm*D_STATE;
    const __half* Bg = g_sin_h + (long)z*HEADDIM*D_STATE;       // [p][n]
    float* Cg = g_y + (brow + bm)*D_INNER + zi.h*HEADDIM;
    scan_gemm_core<0,0,2>(Ag, D_STATE, Bg, D_STATE, Cg, D_INNER, D_STATE/32);
}

// ---------------- prep kernels --------------------------------------------
// xdt[bs][d] = x * dt
__global__ __launch_bounds__(256)
void k_prep_xdt()
{
    long i = (long)blockIdx.x * 256 + threadIdx.x;
    long n2 = (long)BATCH*SEQ*D_INNER/2;
    long stride = (long)gridDim.x * 256;
    for (; i < n2; i += stride) {
        long d2 = i % (D_INNER/2);
        long bs = i / (D_INNER/2);
        int d = (int)d2 * 2;
        int h = d >> 7;
        float dt = g_dt[bs*N_HEADS + h];
        float v0 = g_xBC[bs*CONV_DIM + d]     * dt;
        float v1 = g_xBC[bs*CONV_DIM + d + 1] * dt;
        *(__half2*)&g_xdt_h[bs*D_INNER + d] = __floats2half2_rn(v0, v1);
    }
}

// LG[z][l][s] = s<=l ? G[bc][l][s]*exp(cum_l-cum_s) : 0
__global__ __launch_bounds__(256)
void k_prep_lg()
{
    int z = blockIdx.x, lt = blockIdx.y;
    ZIdx zi = zdec(z);
    int bc = z / N_HEADS;
    const float* cum = g_dAcum + ((long)zi.b*N_HEADS + zi.h)*SEQ + zi.c*CHUNK;
    __shared__ float cs[CHUNK];
    if (threadIdx.x < CHUNK) cs[threadIdx.x] = cum[threadIdx.x];
    __syncthreads();
    const float* G = g_G + (long)bc*CHUNK*CHUNK;
    __half* LG = g_LG + (long)z*CHUNK*CHUNK;
    int tid = threadIdx.x;
    #pragma unroll 4
    for (int j = 0; j < 64; j++) {
        int lin = tid + j*256;
        int l = lt*64 + (lin >> 8);
        int s = lin & 255;
        float v = 0.f;
        if (s <= l) v = G[l*CHUNK + s] * fexp(cs[l] - cs[s]);
        LG[l*CHUNK + s] = __float2half_rn(v);
    }
}

// Bdec[z][l][n] = B*exp(cum_last-cum_l);  Cexp[z][l][n] = C*exp(cum_l)
__global__ __launch_bounds__(256)
void k_prep_bc()
{
    int z = blockIdx.x;
    ZIdx zi = zdec(z);
    const float* cum = g_dAcum + ((long)zi.b*N_HEADS + zi.h)*SEQ + zi.c*CHUNK;
    __shared__ float fb[CHUNK], fc[CHUNK];
    if (threadIdx.x < CHUNK) {
        float cl = cum[threadIdx.x];
        fb[threadIdx.x] = fexp(cum[CHUNK-1] - cl);
        fc[threadIdx.x] = fexp(cl);
    }
    __syncthreads();
    long brow = (long)zi.b*SEQ + zi.c*CHUNK;
    __half* Bd = g_Bdec + (long)z*CHUNK*D_STATE;
    __half* Ce = g_Cexp + (long)z*CHUNK*D_STATE;
    int tid = threadIdx.x;
    #pragma unroll 4
    for (int j = 0; j < 128; j++) {
        int lin = tid + j*256;
        int l = lin >> 7, n = lin & 127;
        long bs = brow + l;
        float Bv = __half2float(g_bc_h[bs*(2*D_STATE) + n]);
        float Cv = __half2float(g_bc_h[bs*(2*D_STATE) + D_STATE + n]);
        Bd[lin] = __float2half_rn(Bv * fb[l]);
        Ce[lin] = __float2half_rn(Cv * fc[l]);
    }
}

// ---------------- fp32 -> fp16 conversion ---------------------------------
__global__ __launch_bounds__(256)
void k_tohalf(const float* __restrict__ src, __half* __restrict__ dst, long n2)
{
    long i = (long)blockIdx.x * 256 + threadIdx.x;
    long stride = (long)gridDim.x * 256;
    for (; i < n2; i += stride) {
        float2 v = *reinterpret_cast<const float2*>(src + i*2);
        *reinterpret_cast<__half2*>(dst + i*2) = __floats2half2_rn(v.x, v.y);
    }
}

// ---------------- exact fp32 dt projection + softplus ---------------------
__global__ __launch_bounds__(256)
void k_dtproj(const float* __restrict__ inputs,
              const float* __restrict__ in_proj_w,
              const float* __restrict__ in_proj_b,
              const float* __restrict__ dt_bias)
{
    __shared__ float xs[32][133];
    __shared__ float ws[32][133];
    int t = threadIdx.x;
    long r0 = (long)blockIdx.x * 32;
    int r = t >> 3;
    int hb = (t & 7) * 4;
    const float* Wdt = in_proj_w + (size_t)(D_INNER + CONV_DIM) * DIM;
    float acc[4] = {0.f, 0.f, 0.f, 0.f};
    for (int k0 = 0; k0 < DIM; k0 += 128) {
        #pragma unroll
        for (int i = 0; i < 4; i++) {
            int idx = t + i*256;
            int row = idx >> 5, c4 = (idx & 31) * 4;
            float4 v = *reinterpret_cast<const float4*>(&inputs[(r0+row)*DIM + k0 + c4]);
            xs[row][c4] = v.x; xs[row][c4+1] = v.y; xs[row][c4+2] = v.z; xs[row][c4+3] = v.w;
            float4 w = *reinterpret_cast<const float4*>(&Wdt[(size_t)row*DIM + k0 + c4]);
            ws[row][c4] = w.x; ws[row][c4+1] = w.y; ws[row][c4+2] = w.z; ws[row][c4+3] = w.w;
        }
        __syncthreads();
        #pragma unroll 8
        for (int k = 0; k < 128; k++) {
            float xv = xs[r][k];
            #pragma unroll
            for (int j = 0; j < 4; j++)
                acc[j] = fmaf(xv, ws[hb+j][k], acc[j]);
        }
        __syncthreads();
    }
    #pragma unroll
    for (int j = 0; j < 4; j++) {
        int h = hb + j;
        float x = acc[j] + in_proj_b[D_INNER + CONV_DIM + h] + dt_bias[h];
        g_dt[(r0 + r)*N_HEADS + h] = (x > 20.f) ? x : log1pf(expf(x));
    }
}

// ---------------- causal depthwise conv + SiLU ----------------------------
__global__ __launch_bounds__(256)
void k_conv(const float* __restrict__ conv_w, const float* __restrict__ conv_b)
{
    long i = (long)blockIdx.x * 256 + threadIdx.x;
    if (i >= (long)BATCH*SEQ*CONV_DIM) return;
    int c = (int)(i % CONV_DIM);
    long bs = i / CONV_DIM;
    int s = (int)(bs % SEQ);
    int b = (int)(bs / SEQ);
    float acc = conv_b[c];
    #pragma unroll
    for (int k = 0; k < D_CONV; k++) {
        int sp = s - (D_CONV-1) + k;
        if (sp >= 0)
            acc = fmaf(g_zxbcdt[((long)b*SEQ + sp)*D_IN_PROJ + D_INNER + c],
                       conv_w[c*D_CONV + k], acc);
    }
    float v = acc / (1.f + expf(-acc));
    g_xBC[i] = v;
    if (c >= D_INNER)
        g_bc_h[bs*(2*D_STATE) + (c - D_INNER)] = __float2half_rn(v);
}

// ---------------- chunk-local inclusive cumsum of A*dt --------------------
__global__ __launch_bounds__(CHUNK)
void k_cumsum(const float* __restrict__ A_log)
{
    int bz = blockIdx.x;
    int c = bz % NCHUNK; int bh = bz / NCHUNK;
    int h = bh % N_HEADS; int b = bh / N_HEADS;
    int l = threadIdx.x;
    int sg = c*CHUNK + l;
    float A = -expf(A_log[h]);
    float val = A * g_dt[((long)b*SEQ + sg)*N_HEADS + h];
    __shared__ float buf[CHUNK];
    buf[l] = val; __syncthreads();
    for (int off = 1; off < CHUNK; off <<= 1) {
        float t = (l >= off) ? buf[l-off] : 0.f;
        __syncthreads();
        buf[l] += t;
        __syncthreads();
    }
    g_dAcum[((long)b*N_HEADS + h)*SEQ + sg] = buf[l];
}

// ---------------- inter-chunk recurrence (-> Sin fp16) --------------------
__global__ __launch_bounds__(256)
void k_chunkrec()
{
    int bh = blockIdx.x;         // b*N_HEADS + h
    int h = bh % N_HEADS; int b = bh / N_HEADS;
    const float* cum = g_dAcum + (long)bh*SEQ;
    float csum[NCHUNK];
    #pragma unroll
    for (int c = 0; c < NCHUNK; c++) csum[c] = expf(cum[c*CHUNK + CHUNK-1]);
    for (int pn = threadIdx.x; pn < HEADDIM*D_STATE; pn += 256) {
        float carry = 0.f;
        #pragma unroll
        for (int c = 0; c < NCHUNK; c++) {
            long z = ((long)b*NCHUNK + c)*N_HEADS + h;
            long idx = z*HEADDIM*D_STATE + pn;
            g_sin_h[idx] = __float2half_rn(carry);
            carry = carry * csum[c] + g_states[idx];
        }
    }
}

// ---------------- gate (y + D*x) * silu(z) + RMSNorm -> fp16 --------------
__global__ __launch_bounds__(256)
void k_gatenorm(const float* __restrict__ norm_w, const float* __restrict__ Dv)
{
    long row = blockIdx.x;
    const float* zrow = g_zxbcdt + row*D_IN_PROJ;
    const float* xrow = g_xBC + row*CONV_DIM;
    float* yrow = g_y + row*D_INNER;
    __half* yh = g_y_h + row*D_INNER;
    float vals[16];
    float local = 0.f;
    #pragma unroll
    for (int i = 0; i < 16; i++) {
        int d = threadIdx.x + i*256;
        float z = zrow[d];
        float v = (yrow[d] + Dv[d >> 7] * xrow[d]) * (z / (1.f + expf(-z)));
        vals[i] = v;
        local += v * v;
    }
    __shared__ float red[256];
    red[threadIdx.x] = local; __syncthreads();
    for (int off = 128; off > 0; off >>= 1) {
        if (threadIdx.x < off) red[threadIdx.x] += red[threadIdx.x + off];
        __syncthreads();
    }
    float scale = rsqrtf(red[0] / D_INNER + EPS);
    #pragma unroll
    for (int i = 0; i < 16; i++) {
        int d = threadIdx.x + i*256;
        yh[d] = __float2half_rn(vals[i] * scale * norm_w[d]);
    }
}

// --------------------------------------------------------------------------
extern "C" void kernel_launch(void* const* d_in, const int* in_sizes, int n_in,
                              void* d_out, int out_size)
{
    const float* inputs     = (const float*)d_in[0];
    const float* in_proj_w  = (const float*)d_in[1];
    const float* in_proj_b  = (const float*)d_in[2];
    const float* out_proj_w = (const float*)d_in[3];
    const float* out_proj_b = (const float*)d_in[4];
    const float* conv_w     = (const float*)d_in[5];
    const float* conv_b     = (const float*)d_in[6];
    const float* dt_bias    = (const float*)d_in[7];
    const float* A_log      = (const float*)d_in[8];
    const float* Dv         = (const float*)d_in[9];
    const float* norm_w     = (const float*)d_in[10];
    float* out = (float*)d_out;

    float *zx, *Gp;
    __half *inh, *winh, *wouth, *yh, *bch;
    cudaGetSymbolAddress((void**)&zx,    g_zxbcdt);
    cudaGetSymbolAddress((void**)&Gp,    g_G);
    cudaGetSymbolAddress((void**)&inh,   g_in_h);
    cudaGetSymbolAddress((void**)&winh,  g_win_h);
    cudaGetSymbolAddress((void**)&wouth, g_wout_h);
    cudaGetSymbolAddress((void**)&yh,    g_y_h);
    cudaGetSymbolAddress((void**)&bch,   g_bc_h);

    const int M = BATCH * SEQ;     // 4096

    // 0) fp16 mirrors
    k_tohalf<<<2048, 256>>>(inputs,     inh,   (long)M*DIM/2);
    k_tohalf<<<2048, 256>>>(in_proj_w,  winh,  (long)D_IN_PROJ*DIM/2);
    k_tohalf<<<2048, 256>>>(out_proj_w, wouth, (long)DIM*D_INNER/2);

    // 1) in_proj
    {
        dim3 grid((D_IN_PROJ + 127)/128, M/128, 1);
        gemm_h<<<grid, 256>>>(inh, DIM, 0, winh, DIM, 0,
                              zx, D_IN_PROJ, 0, M, D_IN_PROJ, DIM, in_proj_b);
    }
    // 2) exact dt projection
    k_dtproj<<<M/32, 256>>>(inputs, in_proj_w, in_proj_b, dt_bias);
    // 3) conv + silu
    k_conv<<<(int)(((long)BATCH*SEQ*CONV_DIM + 255)/256), 256>>>(conv_w, conv_b);
    // 4) cumsum
    k_cumsum<<<BATCH*N_HEADS*NCHUNK, CHUNK>>>(A_log);
    // 5) G = C @ B^T per (b,c)
    {
        dim3 grid(CHUNK/128, CHUNK/128, BATCH*NCHUNK);
        gemm_h<<<grid, 256>>>(bch + D_STATE, 2*D_STATE, (long)CHUNK*2*D_STATE,
                              bch,           2*D_STATE, (long)CHUNK*2*D_STATE,
                              Gp, CHUNK, (long)CHUNK*CHUNK,
                              CHUNK, CHUNK, D_STATE, nullptr);
    }
    // 6) preps
    k_prep_xdt<<<2048, 256>>>();
    {
        dim3 grid(NBCH, CHUNK/64);
        k_prep_lg<<<grid, 256>>>();
    }
    k_prep_bc<<<NBCH, 256>>>();
    // 7) Y_diag (tensor)
    {
        dim3 grid(NBCH, CHUNK/128);
        k_ydiag2<<<grid, 256>>>();
    }
    // 8) states (tensor)
    k_states2<<<NBCH, 256>>>();
    // 9) inter-chunk recurrence -> Sin fp16
    k_chunkrec<<<BATCH*N_HEADS, 256>>>();
    // 10) Y_off += (tensor)
    {
        dim3 grid(NBCH, CHUNK/128);
        k_yoff2<<<grid, 256>>>();
    }
    // 11) gate + D*x + RMSNorm -> fp16
    k_gatenorm<<<BATCH*SEQ, 256>>>(norm_w, Dv);
    // 12) out_proj
    {
        dim3 grid(DIM/128, M/128, 1);
        gemm_h<<<grid, 256>>>(yh, D_INNER, 0, wouth, D_INNER, 0,
                              out, DIM, 0, M, DIM, D_INNER, out_proj_b);
    }
}

// round 9
// speedup vs baseline: 6.7170x; 1.0092x over previous
#include <cuda_runtime.h>
#include <cuda_fp16.h>
#include <math.h>
#include <stdint.h>

#define BATCH   2
#define SEQ     2048
#define DIM     2048
#define D_INNER 4096
#define D_STATE 128
#define N_HEADS 32
#define HEADDIM 128
#define D_CONV  4
#define CHUNK   256
#define NCHUNK  (SEQ/CHUNK)                       /* 8  */
#define NBCH    (BATCH*NCHUNK*N_HEADS)            /* 512 */
#define CONV_DIM (D_INNER + 2*D_STATE)            /* 4352 */
#define D_IN_PROJ (2*D_INNER + 2*D_STATE + N_HEADS) /* 8480 */
#define EPS 1e-5f

// ---------------- scratch (device globals, no allocation) ----------------
__device__ float g_zxbcdt[(size_t)BATCH*SEQ*D_IN_PROJ];
__device__ float g_xBC  [(size_t)BATCH*SEQ*CONV_DIM];
__device__ float g_dt   [(size_t)BATCH*SEQ*N_HEADS];
__device__ float g_dAcum[(size_t)BATCH*N_HEADS*SEQ];
__device__ float g_G    [(size_t)BATCH*NCHUNK*CHUNK*CHUNK];
__device__ float g_states[(size_t)NBCH*HEADDIM*D_STATE];
__device__ float g_y    [(size_t)BATCH*SEQ*D_INNER];
// fp16 operand mirrors
__device__ __half g_in_h  [(size_t)BATCH*SEQ*DIM];
__device__ __half g_win_h [(size_t)D_IN_PROJ*DIM];
__device__ __half g_wout_h[(size_t)DIM*D_INNER];
__device__ __half g_y_h   [(size_t)BATCH*SEQ*D_INNER];
__device__ __half g_bc_h  [(size_t)BATCH*SEQ*2*D_STATE];
// fp16 scan operands
__device__ __half g_xdt_h [(size_t)BATCH*SEQ*D_INNER];
__device__ __half g_LG    [(size_t)NBCH*CHUNK*CHUNK];
__device__ __half g_Bdec  [(size_t)NBCH*CHUNK*D_STATE];
__device__ __half g_Cexp  [(size_t)NBCH*CHUNK*D_STATE];
__device__ __half g_sin_h [(size_t)NBCH*HEADDIM*D_STATE];

__device__ __forceinline__ void cp16(uint32_t dst, const void* src, bool pred) {
    asm volatile("cp.async.cg.shared.global [%0], [%1], 16, %2;"
                 :: "r"(dst), "l"(src), "r"(pred ? 16 : 0));
}
__device__ __forceinline__ void ldsm4(uint32_t* r, uint32_t addr) {
    asm volatile("ldmatrix.sync.aligned.m8n8.x4.shared.b16 {%0,%1,%2,%3}, [%4];"
        : "=r"(r[0]), "=r"(r[1]), "=r"(r[2]), "=r"(r[3]) : "r"(addr));
}
// fast exp on FMA pipe: exp(x) for x<=0
__device__ __forceinline__ float fexp(float x) {
    float t = x * 1.4426950408889634f;
    t = fmaxf(t, -25.f);
    float fi = floorf(t);
    float f = t - fi;
    float p = 1.f + f*(0.69314718f + f*(0.24022651f + f*(0.05550411f
            + f*(0.00961813f + f*0.00133336f))));
    return p * __int_as_float(((int)fi + 127) << 23);
}

#define MMA16(acc, af, bf)                                                   \
    asm volatile(                                                            \
        "mma.sync.aligned.m16n8k16.row.col.f32.f16.f16.f32 "                 \
        "{%0,%1,%2,%3}, {%4,%5,%6,%7}, {%8,%9}, {%0,%1,%2,%3};"              \
        : "+f"(acc[0]), "+f"(acc[1]), "+f"(acc[2]), "+f"(acc[3])             \
        : "r"(af[0]), "r"(af[1]), "r"(af[2]), "r"(af[3]),                    \
          "r"(bf[0]), "r"(bf[1]))

// ================== fp16 mma.sync batched NT GEMM (projections) ===========
// ldmatrix fragment loads; HS=40 halves (80B row, 16B aligned, LDSM
// conflict-free: row*20 mod 32 distinct over 8 rows).
#define HS 40
__global__ __launch_bounds__(256)
void gemm_h(const __half* __restrict__ A, long lda, long sA,
            const __half* __restrict__ W, long ldb, long sB,
            float* __restrict__ C, long ldc, long sC,
            int M, int N, int K, const float* __restrict__ bias)
{
    __shared__ __half As[2][128][HS];
    __shared__ __half Bs[2][128][HS];
    int bz = blockIdx.z;
    const __half* Ab = A + (long)bz * sA;
    const __half* Wb = W + (long)bz * sB;
    float*        Cb = C + (long)bz * sC;
    int bm = blockIdx.y * 128, bn = blockIdx.x * 128;
    int tid  = threadIdx.x;
    int warp = tid >> 5, lane = tid & 31;
    int wm = warp >> 2, wn = warp & 3;
    int g  = lane >> 2, t4 = lane & 3;

    uint32_t sAu = (uint32_t)__cvta_generic_to_shared(&As[0][0][0]);
    uint32_t sBu = (uint32_t)__cvta_generic_to_shared(&Bs[0][0][0]);
    const uint32_t STG = 128*HS*2;

    // ldmatrix per-lane address components
    int arow = lane & 15;                 // row within 16-row A frag
    int acolsel = (lane >> 4) << 3;       // 0 or 8 (k-half select)
    int brow = ((lane >> 4) << 3) + (lane & 7);   // row within 16-row B pair
    int bcolsel = ((lane >> 3) & 1) << 3; // 0 or 8

    float acc[4][4][4];
    #pragma unroll
    for (int i = 0; i < 4; i++)
        #pragma unroll
        for (int j = 0; j < 4; j++)
            #pragma unroll
            for (int q = 0; q < 4; q++) acc[i][j][q] = 0.f;

    const int KT = K / 32;

    #define LOADTILE(st, k0)                                                  \
    do {                                                                      \
        _Pragma("unroll")                                                     \
        for (int it = 0; it < 2; it++) {                                      \
            int idx = tid + it*256;                                           \
            int row = idx >> 2, c8 = (idx & 3) * 8;                           \
            cp16(sAu + (st)*STG + (row*HS + c8)*2,                            \
                 &Ab[(long)(bm+row)*lda + (k0) + c8], true);                  \
        }                                                                     \
        _Pragma("unroll")                                                     \
        for (int it = 0; it < 2; it++) {                                      \
            int idx = tid + it*256;                                           \
            int row = idx >> 2, c8 = (idx & 3) * 8;                           \
            int gn = bn + row; bool p = gn < N;                               \
            cp16(sBu + (st)*STG + (row*HS + c8)*2,                            \
                 &Wb[(long)(p ? gn : 0)*ldb + (k0) + c8], p);                 \
        }                                                                     \
    } while (0)

    LOADTILE(0, 0);
    asm volatile("cp.async.commit_group;");

    for (int kt = 0; kt < KT; kt++) {
        asm volatile("cp.async.wait_group 0;" ::: "memory");
        __syncthreads();
        if (kt + 1 < KT) LOADTILE((kt+1) & 1, (kt+1)*32);
        asm volatile("cp.async.commit_group;");

        int st = kt & 1;
        #pragma unroll
        for (int ks = 0; ks < 2; ks++) {
            int kb = ks * 16;
            uint32_t af[4][4], bf[4][2];
            #pragma unroll
            for (int mt = 0; mt < 4; mt++) {
                int r0 = wm*64 + mt*16;
                ldsm4(af[mt], sAu + st*STG + ((r0 + arow)*HS + kb + acolsel)*2);
            }
            #pragma unroll
            for (int np = 0; np < 2; np++) {
                int cc0 = wn*32 + np*16;
                uint32_t t[4];
                ldsm4(t, sBu + st*STG + ((cc0 + brow)*HS + kb + bcolsel)*2);
                bf[np*2  ][0] = t[0]; bf[np*2  ][1] = t[1];
                bf[np*2+1][0] = t[2]; bf[np*2+1][1] = t[3];
            }
            #pragma unroll
            for (int mt = 0; mt < 4; mt++)
                #pragma unroll
                for (int nt = 0; nt < 4; nt++)
                    MMA16(acc[mt][nt], af[mt], bf[nt]);
        }
    }
    #undef LOADTILE

    #pragma unroll
    for (int mt = 0; mt < 4; mt++) {
        int row0 = bm + wm*64 + mt*16 + g;
        #pragma unroll
        for (int nt = 0; nt < 4; nt++) {
            int col0 = bn + wn*32 + nt*8 + 2*t4;
            if (col0 < N) {
                float b0 = bias ? bias[col0] : 0.f;
                Cb[(long)row0*ldc + col0] = acc[mt][nt][0] + b0;
                Cb[(long)(row0+8)*ldc + col0] = acc[mt][nt][2] + b0;
            }
            if (col0+1 < N) {
                float b1 = bias ? bias[col0+1] : 0.f;
                Cb[(long)row0*ldc + col0+1] = acc[mt][nt][1] + b1;
                Cb[(long)(row0+8)*ldc + col0+1] = acc[mt][nt][3] + b1;
            }
        }
    }
}

// =============== scan GEMMs: 128x128 tile, K-step 32, fp16 ================
#define SS 42

struct ZIdx { int b, c, h; };
__device__ __forceinline__ ZIdx zdec(int z) {
    ZIdx r; r.h = z % N_HEADS; int bc = z / N_HEADS;
    r.c = bc % NCHUNK; r.b = bc / NCHUNK; return r;
}

// ---- generic scan GEMM core ---------------------------------------------
template<int STAGEA, int STAGEB, int OUTMODE>
__device__ __forceinline__ void scan_gemm_core(
    const __half* Ag, long lda,
    const __half* Bg, long ldb,
    float* Cg, long ldc,
    int KT)
{
    __shared__ __half As[128][SS];
    __shared__ __half Bs[128][SS];
    int tid = threadIdx.x;
    int warp = tid >> 5, lane = tid & 31;
    int wm = warp >> 2, wn = warp & 3;
    int g = lane >> 2, t4 = lane & 3;

    float acc[4][4][4];
    #pragma unroll
    for (int i = 0; i < 4; i++)
        #pragma unroll
        for (int j = 0; j < 4; j++)
            #pragma unroll
            for (int q = 0; q < 4; q++) acc[i][j][q] = 0.f;

    for (int kt = 0; kt < KT; kt++) {
        int k0 = kt * 32;
        if (STAGEA == 0) {
            #pragma unroll
            for (int i = 0; i < 8; i++) {
                int idx = tid + i*256;
                int row = idx >> 4, c2 = (idx & 15) * 2;
                *(__half2*)&As[row][c2] = *(const __half2*)&Ag[(long)row*lda + k0 + c2];
            }
        } else {
            #pragma unroll
            for (int i = 0; i < 8; i++) {
                int idx = tid + i*256;
                int k = idx >> 6, m2 = (idx & 63) * 2;
                __half2 v = *(const __half2*)&Ag[(long)(k0+k)*lda + m2];
                As[m2  ][k] = __low2half(v);
                As[m2+1][k] = __high2half(v);
            }
        }
        if (STAGEB == 0) {
            #pragma unroll
            for (int i = 0; i < 8; i++) {
                int idx = tid + i*256;
                int row = idx >> 4, c2 = (idx & 15) * 2;
                *(__half2*)&Bs[row][c2] = *(const __half2*)&Bg[(long)row*ldb + k0 + c2];
            }
        } else {
            #pragma unroll
            for (int i = 0; i < 8; i++) {
                int idx = tid + i*256;
                int k = idx >> 6, n2 = (idx & 63) * 2;
                __half2 v = *(const __half2*)&Bg[(long)(k0+k)*ldb + n2];
                Bs[n2  ][k] = __low2half(v);
                Bs[n2+1][k] = __high2half(v);
            }
        }
        __syncthreads();
        #pragma unroll
        for (int ks = 0; ks < 2; ks++) {
            int kb = ks * 16;
            uint32_t af[4][4], bf[4][2];
            #pragma unroll
            for (int mt = 0; mt < 4; mt++) {
                int r0 = wm*64 + mt*16 + g;
                af[mt][0] = *(const uint32_t*)&As[r0  ][kb + t4*2    ];
                af[mt][1] = *(const uint32_t*)&As[r0+8][kb + t4*2    ];
                af[mt][2] = *(const uint32_t*)&As[r0  ][kb + t4*2 + 8];
                af[mt][3] = *(const uint32_t*)&As[r0+8][kb + t4*2 + 8];
            }
            #pragma unroll
            for (int nt = 0; nt < 4; nt++) {
                int cc = wn*32 + nt*8 + g;
                bf[nt][0] = *(const uint32_t*)&Bs[cc][kb + t4*2    ];
                bf[nt][1] = *(const uint32_t*)&Bs[cc][kb + t4*2 + 8];
            }
            #pragma unroll
            for (int mt = 0; mt < 4; mt++)
                #pragma unroll
                for (int nt = 0; nt < 4; nt++)
                    MMA16(acc[mt][nt], af[mt], bf[nt]);
        }
        __syncthreads();
    }
    #pragma unroll
    for (int mt = 0; mt < 4; mt++) {
        int row0 = wm*64 + mt*16 + g;
        #pragma unroll
        for (int nt = 0; nt < 4; nt++) {
            int col0 = wn*32 + nt*8 + 2*t4;
            if (OUTMODE == 2) {
                Cg[(long)row0*ldc + col0  ] += acc[mt][nt][0];
                Cg[(long)row0*ldc + col0+1] += acc[mt][nt][1];
                Cg[(long)(row0+8)*ldc + col0  ] += acc[mt][nt][2];
                Cg[(long)(row0+8)*ldc + col0+1] += acc[mt][nt][3];
            } else {
                Cg[(long)row0*ldc + col0  ] = acc[mt][nt][0];
                Cg[(long)row0*ldc + col0+1] = acc[mt][nt][1];
                Cg[(long)(row0+8)*ldc + col0  ] = acc[mt][nt][2];
                Cg[(long)(row0+8)*ldc + col0+1] = acc[mt][nt][3];
            }
        }
    }
}

// Y_diag: C[l][p] = sum_s LG[l][s] * xdt[s][p]
__global__ __launch_bounds__(256)
void k_ydiag2()
{
    int z = blockIdx.x, bm = blockIdx.y * 128;
    ZIdx zi = zdec(z);
    long brow = (long)zi.b*SEQ + zi.c*CHUNK;
    const __half* Ag = g_LG + (long)z*CHUNK*CHUNK + (long)bm*CHUNK;
    const __half* Bg = g_xdt_h + brow*D_INNER + zi.h*HEADDIM;
    float* Cg = g_y + (brow + bm)*D_INNER + zi.h*HEADDIM;
    int KT = (bm + 128) / 32;
    scan_gemm_core<0,1,0>(Ag, CHUNK, Bg, D_INNER, Cg, D_INNER, KT);
}

// states: C[p][n] = sum_l xdt[l][p] * Bdec[l][n]
__global__ __launch_bounds__(256)
void k_states2()
{
    int z = blockIdx.x;
    ZIdx zi = zdec(z);
    long brow = (long)zi.b*SEQ + zi.c*CHUNK;
    const __half* Ag = g_xdt_h + brow*D_INNER + zi.h*HEADDIM;
    const __half* Bg = g_Bdec + (long)z*CHUNK*D_STATE;
    float* Cg = g_states + (long)z*HEADDIM*D_STATE;
    scan_gemm_core<1,1,1>(Ag, D_INNER, Bg, D_STATE, Cg, D_STATE, CHUNK/32);
}

// Y_off: C[l][p] += sum_n Cexp[l][n] * Sin[p][n]
__global__ __launch_bounds__(256)
void k_yoff2()
{
    int z = blockIdx.x, bm = blockIdx.y * 128;
    ZIdx zi = zdec(z);
    long brow = (long)zi.b*SEQ + zi.c*CHUNK;
    const __half* Ag = g_Cexp + (long)z*CHUNK*D_STATE + (long)bm*D_STATE;
    const __half* Bg = g_sin_h + (long)z*HEADDIM*D_STATE;
    float* Cg = g_y + (brow + bm)*D_INNER + zi.h*HEADDIM;
    scan_gemm_core<0,0,2>(Ag, D_STATE, Bg, D_STATE, Cg, D_INNER, D_STATE/32);
}

// ---------------- prep kernels --------------------------------------------
__global__ __launch_bounds__(256)
void k_prep_xdt()
{
    long i = (long)blockIdx.x * 256 + threadIdx.x;
    long n2 = (long)BATCH*SEQ*D_INNER/2;
    long stride = (long)gridDim.x * 256;
    for (; i < n2; i += stride) {
        long d2 = i % (D_INNER/2);
        long bs = i / (D_INNER/2);
        int d = (int)d2 * 2;
        int h = d >> 7;
        float dt = g_dt[bs*N_HEADS + h];
        float v0 = g_xBC[bs*CONV_DIM + d]     * dt;
        float v1 = g_xBC[bs*CONV_DIM + d + 1] * dt;
        *(__half2*)&g_xdt_h[bs*D_INNER + d] = __floats2half2_rn(v0, v1);
    }
}

__global__ __launch_bounds__(256)
void k_prep_lg()
{
    int z = blockIdx.x, lt = blockIdx.y;
    ZIdx zi = zdec(z);
    int bc = z / N_HEADS;
    const float* cum = g_dAcum + ((long)zi.b*N_HEADS + zi.h)*SEQ + zi.c*CHUNK;
    __shared__ float cs[CHUNK];
    if (threadIdx.x < CHUNK) cs[threadIdx.x] = cum[threadIdx.x];
    __syncthreads();
    const float* G = g_G + (long)bc*CHUNK*CHUNK;
    __half* LG = g_LG + (long)z*CHUNK*CHUNK;
    int tid = threadIdx.x;
    #pragma unroll 4
    for (int j = 0; j < 64; j++) {
        int lin = tid + j*256;
        int l = lt*64 + (lin >> 8);
        int s = lin & 255;
        float v = 0.f;
        if (s <= l) v = G[l*CHUNK + s] * fexp(cs[l] - cs[s]);
        LG[l*CHUNK + s] = __float2half_rn(v);
    }
}

__global__ __launch_bounds__(256)
void k_prep_bc()
{
    int z = blockIdx.x;
    ZIdx zi = zdec(z);
    const float* cum = g_dAcum + ((long)zi.b*N_HEADS + zi.h)*SEQ + zi.c*CHUNK;
    __shared__ float fb[CHUNK], fc[CHUNK];
    if (threadIdx.x < CHUNK) {
        float cl = cum[threadIdx.x];
        fb[threadIdx.x] = fexp(cum[CHUNK-1] - cl);
        fc[threadIdx.x] = fexp(cl);
    }
    __syncthreads();
    long brow = (long)zi.b*SEQ + zi.c*CHUNK;
    __half* Bd = g_Bdec + (long)z*CHUNK*D_STATE;
    __half* Ce = g_Cexp + (long)z*CHUNK*D_STATE;
    int tid = threadIdx.x;
    #pragma unroll 4
    for (int j = 0; j < 128; j++) {
        int lin = tid + j*256;
        int l = lin >> 7, n = lin & 127;
        long bs = brow + l;
        float Bv = __half2float(g_bc_h[bs*(2*D_STATE) + n]);
        float Cv = __half2float(g_bc_h[bs*(2*D_STATE) + D_STATE + n]);
        Bd[lin] = __float2half_rn(Bv * fb[l]);
        Ce[lin] = __float2half_rn(Cv * fc[l]);
    }
}

__global__ __launch_bounds__(256)
void k_tohalf(const float* __restrict__ src, __half* __restrict__ dst, long n2)
{
    long i = (long)blockIdx.x * 256 + threadIdx.x;
    long stride = (long)gridDim.x * 256;
    for (; i < n2; i += stride) {
        float2 v = *reinterpret_cast<const float2*>(src + i*2);
        *reinterpret_cast<__half2*>(dst + i*2) = __floats2half2_rn(v.x, v.y);
    }
}

// ---------------- exact fp32 dt projection + softplus ---------------------
__global__ __launch_bounds__(256)
void k_dtproj(const float* __restrict__ inputs,
              const float* __restrict__ in_proj_w,
              const float* __restrict__ in_proj_b,
              const float* __restrict__ dt_bias)
{
    __shared__ float xs[32][133];
    __shared__ float ws[32][133];
    int t = threadIdx.x;
    long r0 = (long)blockIdx.x * 32;
    int r = t >> 3;
    int hb = (t & 7) * 4;
    const float* Wdt = in_proj_w + (size_t)(D_INNER + CONV_DIM) * DIM;
    float acc[4] = {0.f, 0.f, 0.f, 0.f};
    for (int k0 = 0; k0 < DIM; k0 += 128) {
        #pragma unroll
        for (int i = 0; i < 4; i++) {
            int idx = t + i*256;
            int row = idx >> 5, c4 = (idx & 31) * 4;
            float4 v = *reinterpret_cast<const float4*>(&inputs[(r0+row)*DIM + k0 + c4]);
            xs[row][c4] = v.x; xs[row][c4+1] = v.y; xs[row][c4+2] = v.z; xs[row][c4+3] = v.w;
            float4 w = *reinterpret_cast<const float4*>(&Wdt[(size_t)row*DIM + k0 + c4]);
            ws[row][c4] = w.x; ws[row][c4+1] = w.y; ws[row][c4+2] = w.z; ws[row][c4+3] = w.w;
        }
        __syncthreads();
        #pragma unroll 8
        for (int k = 0; k < 128; k++) {
            float xv = xs[r][k];
            #pragma unroll
            for (int j = 0; j < 4; j++)
                acc[j] = fmaf(xv, ws[hb+j][k], acc[j]);
        }
        __syncthreads();
    }
    #pragma unroll
    for (int j = 0; j < 4; j++) {
        int h = hb + j;
        float x = acc[j] + in_proj_b[D_INNER + CONV_DIM + h] + dt_bias[h];
        g_dt[(r0 + r)*N_HEADS + h] = (x > 20.f) ? x : log1pf(expf(x));
    }
}

// ---------------- causal depthwise conv + SiLU ----------------------------
__global__ __launch_bounds__(256)
void k_conv(const float* __restrict__ conv_w, const float* __restrict__ conv_b)
{
    long i = (long)blockIdx.x * 256 + threadIdx.x;
    if (i >= (long)BATCH*SEQ*CONV_DIM) return;
    int c = (int)(i % CONV_DIM);
    long bs = i / CONV_DIM;
    int s = (int)(bs % SEQ);
    int b = (int)(bs / SEQ);
    float acc = conv_b[c];
    #pragma unroll
    for (int k = 0; k < D_CONV; k++) {
        int sp = s - (D_CONV-1) + k;
        if (sp >= 0)
            acc = fmaf(g_zxbcdt[((long)b*SEQ + sp)*D_IN_PROJ + D_INNER + c],
                       conv_w[c*D_CONV + k], acc);
    }
    float v = acc / (1.f + expf(-acc));
    g_xBC[i] = v;
    if (c >= D_INNER)
        g_bc_h[bs*(2*D_STATE) + (c - D_INNER)] = __float2half_rn(v);
}

// ---------------- chunk-local inclusive cumsum of A*dt --------------------
__global__ __launch_bounds__(CHUNK)
void k_cumsum(const float* __restrict__ A_log)
{
    int bz = blockIdx.x;
    int c = bz % NCHUNK; int bh = bz / NCHUNK;
    int h = bh % N_HEADS; int b = bh / N_HEADS;
    int l = threadIdx.x;
    int sg = c*CHUNK + l;
    float A = -expf(A_log[h]);
    float val = A * g_dt[((long)b*SEQ + sg)*N_HEADS + h];
    __shared__ float buf[CHUNK];
    buf[l] = val; __syncthreads();
    for (int off = 1; off < CHUNK; off <<= 1) {
        float t = (l >= off) ? buf[l-off] : 0.f;
        __syncthreads();
        buf[l] += t;
        __syncthreads();
    }
    g_dAcum[((long)b*N_HEADS + h)*SEQ + sg] = buf[l];
}

// ---------------- inter-chunk recurrence (-> Sin fp16) --------------------
__global__ __launch_bounds__(256)
void k_chunkrec()
{
    int bh = blockIdx.x;
    int h = bh % N_HEADS; int b = bh / N_HEADS;
    const float* cum = g_dAcum + (long)bh*SEQ;
    float csum[NCHUNK];
    #pragma unroll
    for (int c = 0; c < NCHUNK; c++) csum[c] = expf(cum[c*CHUNK + CHUNK-1]);
    for (int pn = threadIdx.x; pn < HEADDIM*D_STATE; pn += 256) {
        float carry = 0.f;
        #pragma unroll
        for (int c = 0; c < NCHUNK; c++) {
            long z = ((long)b*NCHUNK + c)*N_HEADS + h;
            long idx = z*HEADDIM*D_STATE + pn;
            g_sin_h[idx] = __float2half_rn(carry);
            carry = carry * csum[c] + g_states[idx];
        }
    }
}

// ---------------- gate (y + D*x) * silu(z) + RMSNorm -> fp16 --------------
__global__ __launch_bounds__(256)
void k_gatenorm(const float* __restrict__ norm_w, const float* __restrict__ Dv)
{
    long row = blockIdx.x;
    const float* zrow = g_zxbcdt + row*D_IN_PROJ;
    const float* xrow = g_xBC + row*CONV_DIM;
    float* yrow = g_y + row*D_INNER;
    __half* yh = g_y_h + row*D_INNER;
    float vals[16];
    float local = 0.f;
    #pragma unroll
    for (int i = 0; i < 16; i++) {
        int d = threadIdx.x + i*256;
        float z = zrow[d];
        float v = (yrow[d] + Dv[d >> 7] * xrow[d]) * (z / (1.f + expf(-z)));
        vals[i] = v;
        local += v * v;
    }
    __shared__ float red[256];
    red[threadIdx.x] = local; __syncthreads();
    for (int off = 128; off > 0; off >>= 1) {
        if (threadIdx.x < off) red[threadIdx.x] += red[threadIdx.x + off];
        __syncthreads();
    }
    float scale = rsqrtf(red[0] / D_INNER + EPS);
    #pragma unroll
    for (int i = 0; i < 16; i++) {
        int d = threadIdx.x + i*256;
        yh[d] = __float2half_rn(vals[i] * scale * norm_w[d]);
    }
}

// --------------------------------------------------------------------------
extern "C" void kernel_launch(void* const* d_in, const int* in_sizes, int n_in,
                              void* d_out, int out_size)
{
    const float* inputs     = (const float*)d_in[0];
    const float* in_proj_w  = (const float*)d_in[1];
    const float* in_proj_b  = (const float*)d_in[2];
    const float* out_proj_w = (const float*)d_in[3];
    const float* out_proj_b = (const float*)d_in[4];
    const float* conv_w     = (const float*)d_in[5];
    const float* conv_b     = (const float*)d_in[6];
    const float* dt_bias    = (const float*)d_in[7];
    const float* A_log      = (const float*)d_in[8];
    const float* Dv         = (const float*)d_in[9];
    const float* norm_w     = (const float*)d_in[10];
    float* out = (float*)d_out;

    float *zx, *Gp;
    __half *inh, *winh, *wouth, *yh, *bch;
    cudaGetSymbolAddress((void**)&zx,    g_zxbcdt);
    cudaGetSymbolAddress((void**)&Gp,    g_G);
    cudaGetSymbolAddress((void**)&inh,   g_in_h);
    cudaGetSymbolAddress((void**)&winh,  g_win_h);
    cudaGetSymbolAddress((void**)&wouth, g_wout_h);
    cudaGetSymbolAddress((void**)&yh,    g_y_h);
    cudaGetSymbolAddress((void**)&bch,   g_bc_h);

    const int M = BATCH * SEQ;     // 4096

    // 0) fp16 mirrors
    k_tohalf<<<2048, 256>>>(inputs,     inh,   (long)M*DIM/2);
    k_tohalf<<<2048, 256>>>(in_proj_w,  winh,  (long)D_IN_PROJ*DIM/2);
    k_tohalf<<<2048, 256>>>(out_proj_w, wouth, (long)DIM*D_INNER/2);

    // 1) in_proj
    {
        dim3 grid((D_IN_PROJ + 127)/128, M/128, 1);
        gemm_h<<<grid, 256>>>(inh, DIM, 0, winh, DIM, 0,
                              zx, D_IN_PROJ, 0, M, D_IN_PROJ, DIM, in_proj_b);
    }
    // 2) exact dt projection
    k_dtproj<<<M/32, 256>>>(inputs, in_proj_w, in_proj_b, dt_bias);
    // 3) conv + silu
    k_conv<<<(int)(((long)BATCH*SEQ*CONV_DIM + 255)/256), 256>>>(conv_w, conv_b);
    // 4) cumsum
    k_cumsum<<<BATCH*N_HEADS*NCHUNK, CHUNK>>>(A_log);
    // 5) G = C @ B^T per (b,c)
    {
        dim3 grid(CHUNK/128, CHUNK/128, BATCH*NCHUNK);
        gemm_h<<<grid, 256>>>(bch + D_STATE, 2*D_STATE, (long)CHUNK*2*D_STATE,
                              bch,           2*D_STATE, (long)CHUNK*2*D_STATE,
                              Gp, CHUNK, (long)CHUNK*CHUNK,
                              CHUNK, CHUNK, D_STATE, nullptr);
    }
    // 6) preps
    k_prep_xdt<<<2048, 256>>>();
    {
        dim3 grid(NBCH, CHUNK/64);
        k_prep_lg<<<grid, 256>>>();
    }
    k_prep_bc<<<NBCH, 256>>>();
    // 7) Y_diag (tensor)
    {
        dim3 grid(NBCH, CHUNK/128);
        k_ydiag2<<<grid, 256>>>();
    }
    // 8) states (tensor)
    k_states2<<<NBCH, 256>>>();
    // 9) inter-chunk recurrence -> Sin fp16
    k_chunkrec<<<BATCH*N_HEADS, 256>>>();
    // 10) Y_off += (tensor)
    {
        dim3 grid(NBCH, CHUNK/128);
        k_yoff2<<<grid, 256>>>();
    }
    // 11) gate + D*x + RMSNorm -> fp16
    k_gatenorm<<<BATCH*SEQ, 256>>>(norm_w, Dv);
    // 12) out_proj
    {
        dim3 grid(DIM/128, M/128, 1);
        gemm_h<<<grid, 256>>>(yh, D_INNER, 0, wouth, D_INNER, 0,
                              out, DIM, 0, M, DIM, D_INNER, out_proj_b);
    }
}

// round 10
// speedup vs baseline: 6.9401x; 1.0332x over previous
#include <cuda_runtime.h>
#include <cuda_fp16.h>
#include <math.h>
#include <stdint.h>

#define BATCH   2
#define SEQ     2048
#define DIM     2048
#define D_INNER 4096
#define D_STATE 128
#define N_HEADS 32
#define HEADDIM 128
#define D_CONV  4
#define CHUNK   256
#define NCHUNK  (SEQ/CHUNK)                       /* 8  */
#define NBCH    (BATCH*NCHUNK*N_HEADS)            /* 512 */
#define CONV_DIM (D_INNER + 2*D_STATE)            /* 4352 */
#define D_IN_PROJ (2*D_INNER + 2*D_STATE + N_HEADS) /* 8480 */
#define EPS 1e-5f

// ---------------- scratch (device globals, no allocation) ----------------
__device__ float g_zxbcdt[(size_t)BATCH*SEQ*D_IN_PROJ];
__device__ float g_xBC  [(size_t)BATCH*SEQ*CONV_DIM];
__device__ float g_dt   [(size_t)BATCH*SEQ*N_HEADS];
__device__ float g_dAcum[(size_t)BATCH*N_HEADS*SEQ];
__device__ float g_G    [(size_t)BATCH*NCHUNK*CHUNK*CHUNK];
__device__ float g_states[(size_t)NBCH*HEADDIM*D_STATE];
__device__ float g_y    [(size_t)BATCH*SEQ*D_INNER];
// fp16 operand mirrors
__device__ __half g_in_h  [(size_t)BATCH*SEQ*DIM];
__device__ __half g_win_h [(size_t)D_IN_PROJ*DIM];
__device__ __half g_wout_h[(size_t)DIM*D_INNER];
__device__ __half g_y_h   [(size_t)BATCH*SEQ*D_INNER];
__device__ __half g_bc_h  [(size_t)BATCH*SEQ*2*D_STATE];
// fp16 scan operands
__device__ __half g_xdt_h [(size_t)BATCH*SEQ*D_INNER];
__device__ __half g_LG    [(size_t)NBCH*CHUNK*CHUNK];
__device__ __half g_Bdec  [(size_t)NBCH*CHUNK*D_STATE];
__device__ __half g_Cexp  [(size_t)NBCH*CHUNK*D_STATE];
__device__ __half g_sin_h [(size_t)NBCH*HEADDIM*D_STATE];

__device__ __forceinline__ void cp16(uint32_t dst, const void* src, bool pred) {
    asm volatile("cp.async.cg.shared.global [%0], [%1], 16, %2;"
                 :: "r"(dst), "l"(src), "r"(pred ? 16 : 0));
}
__device__ __forceinline__ void ldsm4(uint32_t* r, uint32_t addr) {
    asm volatile("ldmatrix.sync.aligned.m8n8.x4.shared.b16 {%0,%1,%2,%3}, [%4];"
        : "=r"(r[0]), "=r"(r[1]), "=r"(r[2]), "=r"(r[3]) : "r"(addr));
}
// fast exp on FMA pipe: exp(x) for x<=0
__device__ __forceinline__ float fexp(float x) {
    float t = x * 1.4426950408889634f;
    t = fmaxf(t, -25.f);
    float fi = floorf(t);
    float f = t - fi;
    float p = 1.f + f*(0.69314718f + f*(0.24022651f + f*(0.05550411f
            + f*(0.00961813f + f*0.00133336f))));
    return p * __int_as_float(((int)fi + 127) << 23);
}

#define MMA16(acc, af, bf)                                                   \
    asm volatile(                                                            \
        "mma.sync.aligned.m16n8k16.row.col.f32.f16.f16.f32 "                 \
        "{%0,%1,%2,%3}, {%4,%5,%6,%7}, {%8,%9}, {%0,%1,%2,%3};"              \
        : "+f"(acc[0]), "+f"(acc[1]), "+f"(acc[2]), "+f"(acc[3])             \
        : "r"(af[0]), "r"(af[1]), "r"(af[2]), "r"(af[3]),                    \
          "r"(bf[0]), "r"(bf[1]))

// ================== fp16 mma.sync batched NT GEMM (projections) ===========
// BK=64, 3-stage cp.async pipeline (wait_group 1), ldmatrix fragments.
// Dynamic smem: 2 operands x 3 stages x 128 rows x 72 halves = 110592 B.
#define HS 72                         /* 64 + 8 pad halves; 144B row stride */
#define GSTG (128*HS*2)               /* 18432 B per operand-stage */
#define GSMEM (6*GSTG)                /* 110592 */
__global__ __launch_bounds__(256)
void gemm_h(const __half* __restrict__ A, long lda, long sA,
            const __half* __restrict__ W, long ldb, long sB,
            float* __restrict__ C, long ldc, long sC,
            int M, int N, int K, const float* __restrict__ bias)
{
    extern __shared__ char smem[];
    int bz = blockIdx.z;
    const __half* Ab = A + (long)bz * sA;
    const __half* Wb = W + (long)bz * sB;
    float*        Cb = C + (long)bz * sC;
    int bm = blockIdx.y * 128, bn = blockIdx.x * 128;
    int tid  = threadIdx.x;
    int warp = tid >> 5, lane = tid & 31;
    int wm = warp >> 2, wn = warp & 3;
    int g  = lane >> 2, t4 = lane & 3;

    uint32_t sAu = (uint32_t)__cvta_generic_to_shared(smem);
    uint32_t sBu = sAu + 3*GSTG;

    // ldmatrix per-lane address components
    int arow = lane & 15;
    int acolsel = (lane >> 4) << 3;
    int brow = ((lane >> 4) << 3) + (lane & 7);
    int bcolsel = ((lane >> 3) & 1) << 3;

    float acc[4][4][4];
    #pragma unroll
    for (int i = 0; i < 4; i++)
        #pragma unroll
        for (int j = 0; j < 4; j++)
            #pragma unroll
            for (int q = 0; q < 4; q++) acc[i][j][q] = 0.f;

    const int KT = K / 64;

    // per stage: A 128x64 halves = 1024 x 8-half chunks (4/thread); B same
    #define LOADTILE(st, k0)                                                  \
    do {                                                                      \
        _Pragma("unroll")                                                     \
        for (int it = 0; it < 4; it++) {                                      \
            int idx = tid + it*256;                                           \
            int row = idx >> 3, c8 = (idx & 7) * 8;                           \
            cp16(sAu + (st)*GSTG + (row*HS + c8)*2,                           \
                 &Ab[(long)(bm+row)*lda + (k0) + c8], true);                  \
        }                                                                     \
        _Pragma("unroll")                                                     \
        for (int it = 0; it < 4; it++) {                                      \
            int idx = tid + it*256;                                           \
            int row = idx >> 3, c8 = (idx & 7) * 8;                           \
            int gn = bn + row; bool p = gn < N;                               \
            cp16(sBu + (st)*GSTG + (row*HS + c8)*2,                           \
                 &Wb[(long)(p ? gn : 0)*ldb + (k0) + c8], p);                 \
        }                                                                     \
    } while (0)

    // prologue: stages 0,1
    LOADTILE(0, 0);
    asm volatile("cp.async.commit_group;");
    if (KT > 1) LOADTILE(1, 64);
    asm volatile("cp.async.commit_group;");

    for (int kt = 0; kt < KT; kt++) {
        asm volatile("cp.async.wait_group 1;" ::: "memory");
        __syncthreads();
        if (kt + 2 < KT) LOADTILE((kt+2) % 3, (kt+2)*64);
        asm volatile("cp.async.commit_group;");

        int st = kt % 3;
        #pragma unroll
        for (int ks = 0; ks < 4; ks++) {
            int kb = ks * 16;
            uint32_t af[4][4], bf[4][2];
            #pragma unroll
            for (int mt = 0; mt < 4; mt++) {
                int r0 = wm*64 + mt*16;
                ldsm4(af[mt], sAu + st*GSTG + ((r0 + arow)*HS + kb + acolsel)*2);
            }
            #pragma unroll
            for (int np = 0; np < 2; np++) {
                int cc0 = wn*32 + np*16;
                uint32_t t[4];
                ldsm4(t, sBu + st*GSTG + ((cc0 + brow)*HS + kb + bcolsel)*2);
                bf[np*2  ][0] = t[0]; bf[np*2  ][1] = t[1];
                bf[np*2+1][0] = t[2]; bf[np*2+1][1] = t[3];
            }
            #pragma unroll
            for (int mt = 0; mt < 4; mt++)
                #pragma unroll
                for (int nt = 0; nt < 4; nt++)
                    MMA16(acc[mt][nt], af[mt], bf[nt]);
        }
        __syncthreads();
    }
    #undef LOADTILE

    #pragma unroll
    for (int mt = 0; mt < 4; mt++) {
        int row0 = bm + wm*64 + mt*16 + g;
        #pragma unroll
        for (int nt = 0; nt < 4; nt++) {
            int col0 = bn + wn*32 + nt*8 + 2*t4;
            if (col0 < N) {
                float b0 = bias ? bias[col0] : 0.f;
                Cb[(long)row0*ldc + col0] = acc[mt][nt][0] + b0;
                Cb[(long)(row0+8)*ldc + col0] = acc[mt][nt][2] + b0;
            }
            if (col0+1 < N) {
                float b1 = bias ? bias[col0+1] : 0.f;
                Cb[(long)row0*ldc + col0+1] = acc[mt][nt][1] + b1;
                Cb[(long)(row0+8)*ldc + col0+1] = acc[mt][nt][3] + b1;
            }
        }
    }
}

// =============== scan GEMMs: 128x128 tile, K-step 32, fp16 ================
#define SS 42

struct ZIdx { int b, c, h; };
__device__ __forceinline__ ZIdx zdec(int z) {
    ZIdx r; r.h = z % N_HEADS; int bc = z / N_HEADS;
    r.c = bc % NCHUNK; r.b = bc / NCHUNK; return r;
}

template<int STAGEA, int STAGEB, int OUTMODE>
__device__ __forceinline__ void scan_gemm_core(
    const __half* Ag, long lda,
    const __half* Bg, long ldb,
    float* Cg, long ldc,
    int KT)
{
    __shared__ __half As[128][SS];
    __shared__ __half Bs[128][SS];
    int tid = threadIdx.x;
    int warp = tid >> 5, lane = tid & 31;
    int wm = warp >> 2, wn = warp & 3;
    int g = lane >> 2, t4 = lane & 3;

    float acc[4][4][4];
    #pragma unroll
    for (int i = 0; i < 4; i++)
        #pragma unroll
        for (int j = 0; j < 4; j++)
            #pragma unroll
            for (int q = 0; q < 4; q++) acc[i][j][q] = 0.f;

    for (int kt = 0; kt < KT; kt++) {
        int k0 = kt * 32;
        if (STAGEA == 0) {
            #pragma unroll
            for (int i = 0; i < 8; i++) {
                int idx = tid + i*256;
                int row = idx >> 4, c2 = (idx & 15) * 2;
                *(__half2*)&As[row][c2] = *(const __half2*)&Ag[(long)row*lda + k0 + c2];
            }
        } else {
            #pragma unroll
            for (int i = 0; i < 8; i++) {
                int idx = tid + i*256;
                int k = idx >> 6, m2 = (idx & 63) * 2;
                __half2 v = *(const __half2*)&Ag[(long)(k0+k)*lda + m2];
                As[m2  ][k] = __low2half(v);
                As[m2+1][k] = __high2half(v);
            }
        }
        if (STAGEB == 0) {
            #pragma unroll
            for (int i = 0; i < 8; i++) {
                int idx = tid + i*256;
                int row = idx >> 4, c2 = (idx & 15) * 2;
                *(__half2*)&Bs[row][c2] = *(const __half2*)&Bg[(long)row*ldb + k0 + c2];
            }
        } else {
            #pragma unroll
            for (int i = 0; i < 8; i++) {
                int idx = tid + i*256;
                int k = idx >> 6, n2 = (idx & 63) * 2;
                __half2 v = *(const __half2*)&Bg[(long)(k0+k)*ldb + n2];
                Bs[n2  ][k] = __low2half(v);
                Bs[n2+1][k] = __high2half(v);
            }
        }
        __syncthreads();
        #pragma unroll
        for (int ks = 0; ks < 2; ks++) {
            int kb = ks * 16;
            uint32_t af[4][4], bf[4][2];
            #pragma unroll
            for (int mt = 0; mt < 4; mt++) {
                int r0 = wm*64 + mt*16 + g;
                af[mt][0] = *(const uint32_t*)&As[r0  ][kb + t4*2    ];
                af[mt][1] = *(const uint32_t*)&As[r0+8][kb + t4*2    ];
                af[mt][2] = *(const uint32_t*)&As[r0  ][kb + t4*2 + 8];
                af[mt][3] = *(const uint32_t*)&As[r0+8][kb + t4*2 + 8];
            }
            #pragma unroll
            for (int nt = 0; nt < 4; nt++) {
                int cc = wn*32 + nt*8 + g;
                bf[nt][0] = *(const uint32_t*)&Bs[cc][kb + t4*2    ];
                bf[nt][1] = *(const uint32_t*)&Bs[cc][kb + t4*2 + 8];
            }
            #pragma unroll
            for (int mt = 0; mt < 4; mt++)
                #pragma unroll
                for (int nt = 0; nt < 4; nt++)
                    MMA16(acc[mt][nt], af[mt], bf[nt]);
        }
        __syncthreads();
    }
    #pragma unroll
    for (int mt = 0; mt < 4; mt++) {
        int row0 = wm*64 + mt*16 + g;
        #pragma unroll
        for (int nt = 0; nt < 4; nt++) {
            int col0 = wn*32 + nt*8 + 2*t4;
            if (OUTMODE == 2) {
                Cg[(long)row0*ldc + col0  ] += acc[mt][nt][0];
                Cg[(long)row0*ldc + col0+1] += acc[mt][nt][1];
                Cg[(long)(row0+8)*ldc + col0  ] += acc[mt][nt][2];
                Cg[(long)(row0+8)*ldc + col0+1] += acc[mt][nt][3];
            } else {
                Cg[(long)row0*ldc + col0  ] = acc[mt][nt][0];
                Cg[(long)row0*ldc + col0+1] = acc[mt][nt][1];
                Cg[(long)(row0+8)*ldc + col0  ] = acc[mt][nt][2];
                Cg[(long)(row0+8)*ldc + col0+1] = acc[mt][nt][3];
            }
        }
    }
}

__global__ __launch_bounds__(256)
void k_ydiag2()
{
    int z = blockIdx.x, bm = blockIdx.y * 128;
    ZIdx zi = zdec(z);
    long brow = (long)zi.b*SEQ + zi.c*CHUNK;
    const __half* Ag = g_LG + (long)z*CHUNK*CHUNK + (long)bm*CHUNK;
    const __half* Bg = g_xdt_h + brow*D_INNER + zi.h*HEADDIM;
    float* Cg = g_y + (brow + bm)*D_INNER + zi.h*HEADDIM;
    int KT = (bm + 128) / 32;
    scan_gemm_core<0,1,0>(Ag, CHUNK, Bg, D_INNER, Cg, D_INNER, KT);
}

__global__ __launch_bounds__(256)
void k_states2()
{
    int z = blockIdx.x;
    ZIdx zi = zdec(z);
    long brow = (long)zi.b*SEQ + zi.c*CHUNK;
    const __half* Ag = g_xdt_h + brow*D_INNER + zi.h*HEADDIM;
    const __half* Bg = g_Bdec + (long)z*CHUNK*D_STATE;
    float* Cg = g_states + (long)z*HEADDIM*D_STATE;
    scan_gemm_core<1,1,1>(Ag, D_INNER, Bg, D_STATE, Cg, D_STATE, CHUNK/32);
}

__global__ __launch_bounds__(256)
void k_yoff2()
{
    int z = blockIdx.x, bm = blockIdx.y * 128;
    ZIdx zi = zdec(z);
    long brow = (long)zi.b*SEQ + zi.c*CHUNK;
    const __half* Ag = g_Cexp + (long)z*CHUNK*D_STATE + (long)bm*D_STATE;
    const __half* Bg = g_sin_h + (long)z*HEADDIM*D_STATE;
    float* Cg = g_y + (brow + bm)*D_INNER + zi.h*HEADDIM;
    scan_gemm_core<0,0,2>(Ag, D_STATE, Bg, D_STATE, Cg, D_INNER, D_STATE/32);
}

// ---------------- prep kernels --------------------------------------------
__global__ __launch_bounds__(256)
void k_prep_xdt()
{
    long i = (long)blockIdx.x * 256 + threadIdx.x;
    long n2 = (long)BATCH*SEQ*D_INNER/2;
    long stride = (long)gridDim.x * 256;
    for (; i < n2; i += stride) {
        long d2 = i % (D_INNER/2);
        long bs = i / (D_INNER/2);
        int d = (int)d2 * 2;
        int h = d >> 7;
        float dt = g_dt[bs*N_HEADS + h];
        float v0 = g_xBC[bs*CONV_DIM + d]     * dt;
        float v1 = g_xBC[bs*CONV_DIM + d + 1] * dt;
        *(__half2*)&g_xdt_h[bs*D_INNER + d] = __floats2half2_rn(v0, v1);
    }
}

__global__ __launch_bounds__(256)
void k_prep_lg()
{
    int z = blockIdx.x, lt = blockIdx.y;
    ZIdx zi = zdec(z);
    int bc = z / N_HEADS;
    const float* cum = g_dAcum + ((long)zi.b*N_HEADS + zi.h)*SEQ + zi.c*CHUNK;
    __shared__ float cs[CHUNK];
    if (threadIdx.x < CHUNK) cs[threadIdx.x] = cum[threadIdx.x];
    __syncthreads();
    const float* G = g_G + (long)bc*CHUNK*CHUNK;
    __half* LG = g_LG + (long)z*CHUNK*CHUNK;
    int tid = threadIdx.x;
    #pragma unroll 4
    for (int j = 0; j < 64; j++) {
        int lin = tid + j*256;
        int l = lt*64 + (lin >> 8);
        int s = lin & 255;
        float v = 0.f;
        if (s <= l) v = G[l*CHUNK + s] * fexp(cs[l] - cs[s]);
        LG[l*CHUNK + s] = __float2half_rn(v);
    }
}

__global__ __launch_bounds__(256)
void k_prep_bc()
{
    int z = blockIdx.x;
    ZIdx zi = zdec(z);
    const float* cum = g_dAcum + ((long)zi.b*N_HEADS + zi.h)*SEQ + zi.c*CHUNK;
    __shared__ float fb[CHUNK], fc[CHUNK];
    if (threadIdx.x < CHUNK) {
        float cl = cum[threadIdx.x];
        fb[threadIdx.x] = fexp(cum[CHUNK-1] - cl);
        fc[threadIdx.x] = fexp(cl);
    }
    __syncthreads();
    long brow = (long)zi.b*SEQ + zi.c*CHUNK;
    __half* Bd = g_Bdec + (long)z*CHUNK*D_STATE;
    __half* Ce = g_Cexp + (long)z*CHUNK*D_STATE;
    int tid = threadIdx.x;
    #pragma unroll 4
    for (int j = 0; j < 128; j++) {
        int lin = tid + j*256;
        int l = lin >> 7, n = lin & 127;
        long bs = brow + l;
        float Bv = __half2float(g_bc_h[bs*(2*D_STATE) + n]);
        float Cv = __half2float(g_bc_h[bs*(2*D_STATE) + D_STATE + n]);
        Bd[lin] = __float2half_rn(Bv * fb[l]);
        Ce[lin] = __float2half_rn(Cv * fc[l]);
    }
}

__global__ __launch_bounds__(256)
void k_tohalf(const float* __restrict__ src, __half* __restrict__ dst, long n2)
{
    long i = (long)blockIdx.x * 256 + threadIdx.x;
    long stride = (long)gridDim.x * 256;
    for (; i < n2; i += stride) {
        float2 v = *reinterpret_cast<const float2*>(src + i*2);
        *reinterpret_cast<__half2*>(dst + i*2) = __floats2half2_rn(v.x, v.y);
    }
}

// ---------------- exact fp32 dt projection + softplus ---------------------
__global__ __launch_bounds__(256)
void k_dtproj(const float* __restrict__ inputs,
              const float* __restrict__ in_proj_w,
              const float* __restrict__ in_proj_b,
              const float* __restrict__ dt_bias)
{
    __shared__ float xs[32][133];
    __shared__ float ws[32][133];
    int t = threadIdx.x;
    long r0 = (long)blockIdx.x * 32;
    int r = t >> 3;
    int hb = (t & 7) * 4;
    const float* Wdt = in_proj_w + (size_t)(D_INNER + CONV_DIM) * DIM;
    float acc[4] = {0.f, 0.f, 0.f, 0.f};
    for (int k0 = 0; k0 < DIM; k0 += 128) {
        #pragma unroll
        for (int i = 0; i < 4; i++) {
            int idx = t + i*256;
            int row = idx >> 5, c4 = (idx & 31) * 4;
            float4 v = *reinterpret_cast<const float4*>(&inputs[(r0+row)*DIM + k0 + c4]);
            xs[row][c4] = v.x; xs[row][c4+1] = v.y; xs[row][c4+2] = v.z; xs[row][c4+3] = v.w;
            float4 w = *reinterpret_cast<const float4*>(&Wdt[(size_t)row*DIM + k0 + c4]);
            ws[row][c4] = w.x; ws[row][c4+1] = w.y; ws[row][c4+2] = w.z; ws[row][c4+3] = w.w;
        }
        __syncthreads();
        #pragma unroll 8
        for (int k = 0; k < 128; k++) {
            float xv = xs[r][k];
            #pragma unroll
            for (int j = 0; j < 4; j++)
                acc[j] = fmaf(xv, ws[hb+j][k], acc[j]);
        }
        __syncthreads();
    }
    #pragma unroll
    for (int j = 0; j < 4; j++) {
        int h = hb + j;
        float x = acc[j] + in_proj_b[D_INNER + CONV_DIM + h] + dt_bias[h];
        g_dt[(r0 + r)*N_HEADS + h] = (x > 20.f) ? x : log1pf(expf(x));
    }
}

// ---------------- causal depthwise conv + SiLU ----------------------------
__global__ __launch_bounds__(256)
void k_conv(const float* __restrict__ conv_w, const float* __restrict__ conv_b)
{
    long i = (long)blockIdx.x * 256 + threadIdx.x;
    if (i >= (long)BATCH*SEQ*CONV_DIM) return;
    int c = (int)(i % CONV_DIM);
    long bs = i / CONV_DIM;
    int s = (int)(bs % SEQ);
    int b = (int)(bs / SEQ);
    float acc = conv_b[c];
    #pragma unroll
    for (int k = 0; k < D_CONV; k++) {
        int sp = s - (D_CONV-1) + k;
        if (sp >= 0)
            acc = fmaf(g_zxbcdt[((long)b*SEQ + sp)*D_IN_PROJ + D_INNER + c],
                       conv_w[c*D_CONV + k], acc);
    }
    float v = acc / (1.f + expf(-acc));
    g_xBC[i] = v;
    if (c >= D_INNER)
        g_bc_h[bs*(2*D_STATE) + (c - D_INNER)] = __float2half_rn(v);
}

// ---------------- chunk-local inclusive cumsum of A*dt --------------------
__global__ __launch_bounds__(CHUNK)
void k_cumsum(const float* __restrict__ A_log)
{
    int bz = blockIdx.x;
    int c = bz % NCHUNK; int bh = bz / NCHUNK;
    int h = bh % N_HEADS; int b = bh / N_HEADS;
    int l = threadIdx.x;
    int sg = c*CHUNK + l;
    float A = -expf(A_log[h]);
    float val = A * g_dt[((long)b*SEQ + sg)*N_HEADS + h];
    __shared__ float buf[CHUNK];
    buf[l] = val; __syncthreads();
    for (int off = 1; off < CHUNK; off <<= 1) {
        float t = (l >= off) ? buf[l-off] : 0.f;
        __syncthreads();
        buf[l] += t;
        __syncthreads();
    }
    g_dAcum[((long)b*N_HEADS + h)*SEQ + sg] = buf[l];
}

// ---------------- inter-chunk recurrence (-> Sin fp16) --------------------
__global__ __launch_bounds__(256)
void k_chunkrec()
{
    int bh = blockIdx.x;
    int h = bh % N_HEADS; int b = bh / N_HEADS;
    const float* cum = g_dAcum + (long)bh*SEQ;
    float csum[NCHUNK];
    #pragma unroll
    for (int c = 0; c < NCHUNK; c++) csum[c] = expf(cum[c*CHUNK + CHUNK-1]);
    for (int pn = threadIdx.x; pn < HEADDIM*D_STATE; pn += 256) {
        float carry = 0.f;
        #pragma unroll
        for (int c = 0; c < NCHUNK; c++) {
            long z = ((long)b*NCHUNK + c)*N_HEADS + h;
            long idx = z*HEADDIM*D_STATE + pn;
            g_sin_h[idx] = __float2half_rn(carry);
            carry = carry * csum[c] + g_states[idx];
        }
    }
}

// ---------------- gate (y + D*x) * silu(z) + RMSNorm -> fp16 --------------
__global__ __launch_bounds__(256)
void k_gatenorm(const float* __restrict__ norm_w, const float* __restrict__ Dv)
{
    long row = blockIdx.x;
    const float* zrow = g_zxbcdt + row*D_IN_PROJ;
    const float* xrow = g_xBC + row*CONV_DIM;
    float* yrow = g_y + row*D_INNER;
    __half* yh = g_y_h + row*D_INNER;
    float vals[16];
    float local = 0.f;
    #pragma unroll
    for (int i = 0; i < 16; i++) {
        int d = threadIdx.x + i*256;
        float z = zrow[d];
        float v = (yrow[d] + Dv[d >> 7] * xrow[d]) * (z / (1.f + expf(-z)));
        vals[i] = v;
        local += v * v;
    }
    __shared__ float red[256];
    red[threadIdx.x] = local; __syncthreads();
    for (int off = 128; off > 0; off >>= 1) {
        if (threadIdx.x < off) red[threadIdx.x] += red[threadIdx.x + off];
        __syncthreads();
    }
    float scale = rsqrtf(red[0] / D_INNER + EPS);
    #pragma unroll
    for (int i = 0; i < 16; i++) {
        int d = threadIdx.x + i*256;
        yh[d] = __float2half_rn(vals[i] * scale * norm_w[d]);
    }
}

// --------------------------------------------------------------------------
extern "C" void kernel_launch(void* const* d_in, const int* in_sizes, int n_in,
                              void* d_out, int out_size)
{
    const float* inputs     = (const float*)d_in[0];
    const float* in_proj_w  = (const float*)d_in[1];
    const float* in_proj_b  = (const float*)d_in[2];
    const float* out_proj_w = (const float*)d_in[3];
    const float* out_proj_b = (const float*)d_in[4];
    const float* conv_w     = (const float*)d_in[5];
    const float* conv_b     = (const float*)d_in[6];
    const float* dt_bias    = (const float*)d_in[7];
    const float* A_log      = (const float*)d_in[8];
    const float* Dv         = (const float*)d_in[9];
    const float* norm_w     = (const float*)d_in[10];
    float* out = (float*)d_out;

    float *zx, *Gp;
    __half *inh, *winh, *wouth, *yh, *bch;
    cudaGetSymbolAddress((void**)&zx,    g_zxbcdt);
    cudaGetSymbolAddress((void**)&Gp,    g_G);
    cudaGetSymbolAddress((void**)&inh,   g_in_h);
    cudaGetSymbolAddress((void**)&winh,  g_win_h);
    cudaGetSymbolAddress((void**)&wouth, g_wout_h);
    cudaGetSymbolAddress((void**)&yh,    g_y_h);
    cudaGetSymbolAddress((void**)&bch,   g_bc_h);

    cudaFuncSetAttribute(gemm_h, cudaFuncAttributeMaxDynamicSharedMemorySize, GSMEM);

    const int M = BATCH * SEQ;     // 4096

    // 0) fp16 mirrors
    k_tohalf<<<2048, 256>>>(inputs,     inh,   (long)M*DIM/2);
    k_tohalf<<<2048, 256>>>(in_proj_w,  winh,  (long)D_IN_PROJ*DIM/2);
    k_tohalf<<<2048, 256>>>(out_proj_w, wouth, (long)DIM*D_INNER/2);

    // 1) in_proj
    {
        dim3 grid((D_IN_PROJ + 127)/128, M/128, 1);
        gemm_h<<<grid, 256, GSMEM>>>(inh, DIM, 0, winh, DIM, 0,
                              zx, D_IN_PROJ, 0, M, D_IN_PROJ, DIM, in_proj_b);
    }
    // 2) exact dt projection
    k_dtproj<<<M/32, 256>>>(inputs, in_proj_w, in_proj_b, dt_bias);
    // 3) conv + silu
    k_conv<<<(int)(((long)BATCH*SEQ*CONV_DIM + 255)/256), 256>>>(conv_w, conv_b);
    // 4) cumsum
    k_cumsum<<<BATCH*N_HEADS*NCHUNK, CHUNK>>>(A_log);
    // 5) G = C @ B^T per (b,c)
    {
        dim3 grid(CHUNK/128, CHUNK/128, BATCH*NCHUNK);
        gemm_h<<<grid, 256, GSMEM>>>(bch + D_STATE, 2*D_STATE, (long)CHUNK*2*D_STATE,
                              bch,           2*D_STATE, (long)CHUNK*2*D_STATE,
                              Gp, CHUNK, (long)CHUNK*CHUNK,
                              CHUNK, CHUNK, D_STATE, nullptr);
    }
    // 6) preps
    k_prep_xdt<<<2048, 256>>>();
    {
        dim3 grid(NBCH, CHUNK/64);
        k_prep_lg<<<grid, 256>>>();
    }
    k_prep_bc<<<NBCH, 256>>>();
    // 7) Y_diag (tensor)
    {
        dim3 grid(NBCH, CHUNK/128);
        k_ydiag2<<<grid, 256>>>();
    }
    // 8) states (tensor)
    k_states2<<<NBCH, 256>>>();
    // 9) inter-chunk recurrence -> Sin fp16
    k_chunkrec<<<BATCH*N_HEADS, 256>>>();
    // 10) Y_off += (tensor)
    {
        dim3 grid(NBCH, CHUNK/128);
        k_yoff2<<<grid, 256>>>();
    }
    // 11) gate + D*x + RMSNorm -> fp16
    k_gatenorm<<<BATCH*SEQ, 256>>>(norm_w, Dv);
    // 12) out_proj
    {
        dim3 grid(DIM/128, M/128, 1);
        gemm_h<<<grid, 256, GSMEM>>>(yh, D_INNER, 0, wouth, D_INNER, 0,
                              out, DIM, 0, M, DIM, D_INNER, out_proj_b);
    }
}

// round 11
// speedup vs baseline: 7.9046x; 1.1390x over previous
#include <cuda_runtime.h>
#include <cuda_fp16.h>
#include <math.h>
#include <stdint.h>

#define BATCH   2
#define SEQ     2048
#define DIM     2048
#define D_INNER 4096
#define D_STATE 128
#define N_HEADS 32
#define HEADDIM 128
#define D_CONV  4
#define CHUNK   256
#define NCHUNK  (SEQ/CHUNK)                       /* 8  */
#define NBCH    (BATCH*NCHUNK*N_HEADS)            /* 512 */
#define CONV_DIM (D_INNER + 2*D_STATE)            /* 4352 */
#define D_IN_PROJ (2*D_INNER + 2*D_STATE + N_HEADS) /* 8480 */
#define EPS 1e-5f

// ---------------- scratch (device globals, no allocation) ----------------
__device__ float g_zxbcdt[(size_t)BATCH*SEQ*D_IN_PROJ];
__device__ float g_xBC  [(size_t)BATCH*SEQ*CONV_DIM];
__device__ float g_dt   [(size_t)BATCH*SEQ*N_HEADS];
__device__ float g_dAcum[(size_t)BATCH*N_HEADS*SEQ];
__device__ float g_G    [(size_t)BATCH*NCHUNK*CHUNK*CHUNK];
__device__ float g_states[(size_t)NBCH*HEADDIM*D_STATE];
__device__ float g_y    [(size_t)BATCH*SEQ*D_INNER];
// fp16 operand mirrors
__device__ __half g_in_h  [(size_t)BATCH*SEQ*DIM];
__device__ __half g_win_h [(size_t)D_IN_PROJ*DIM];
__device__ __half g_wout_h[(size_t)DIM*D_INNER];
__device__ __half g_y_h   [(size_t)BATCH*SEQ*D_INNER];
__device__ __half g_bc_h  [(size_t)BATCH*SEQ*2*D_STATE];
// fp16 scan operands
__device__ __half g_xdt_h [(size_t)BATCH*SEQ*D_INNER];
__device__ __half g_LG    [(size_t)NBCH*CHUNK*CHUNK];
__device__ __half g_Bdec  [(size_t)NBCH*CHUNK*D_STATE];
__device__ __half g_Cexp  [(size_t)NBCH*CHUNK*D_STATE];
__device__ __half g_sin_h [(size_t)NBCH*HEADDIM*D_STATE];

__device__ __forceinline__ void cp16(uint32_t dst, const void* src, bool pred) {
    asm volatile("cp.async.cg.shared.global [%0], [%1], 16, %2;"
                 :: "r"(dst), "l"(src), "r"(pred ? 16 : 0));
}
__device__ __forceinline__ void ldsm4(uint32_t* r, uint32_t addr) {
    asm volatile("ldmatrix.sync.aligned.m8n8.x4.shared.b16 {%0,%1,%2,%3}, [%4];"
        : "=r"(r[0]), "=r"(r[1]), "=r"(r[2]), "=r"(r[3]) : "r"(addr));
}
// fast exp on FMA pipe: exp(x) for x<=0
__device__ __forceinline__ float fexp(float x) {
    float t = x * 1.4426950408889634f;
    t = fmaxf(t, -25.f);
    float fi = floorf(t);
    float f = t - fi;
    float p = 1.f + f*(0.69314718f + f*(0.24022651f + f*(0.05550411f
            + f*(0.00961813f + f*0.00133336f))));
    return p * __int_as_float(((int)fi + 127) << 23);
}

#define MMA16(acc, af, bf)                                                   \
    asm volatile(                                                            \
        "mma.sync.aligned.m16n8k16.row.col.f32.f16.f16.f32 "                 \
        "{%0,%1,%2,%3}, {%4,%5,%6,%7}, {%8,%9}, {%0,%1,%2,%3};"              \
        : "+f"(acc[0]), "+f"(acc[1]), "+f"(acc[2]), "+f"(acc[3])             \
        : "r"(af[0]), "r"(af[1]), "r"(af[2]), "r"(af[3]),                    \
          "r"(bf[0]), "r"(bf[1]))

// ================== fp16 mma.sync batched NT GEMM (projections) ===========
// BK=64, 3-stage cp.async, XOR-swizzled smem (no pad), ldmatrix fragments.
// Row = 128B (64 halves); 16B chunk index swizzled by (row & 7).
// Smem: 2 ops x 3 stages x 16384 B = 98304 B -> 2 CTAs/SM.
#define GSTG (128*64*2)               /* 16384 B per operand-stage */
#define GSMEM (6*GSTG)                /* 98304 */
__global__ __launch_bounds__(256, 2)
void gemm_h(const __half* __restrict__ A, long lda, long sA,
            const __half* __restrict__ W, long ldb, long sB,
            float* __restrict__ C, long ldc, long sC,
            int M, int N, int K, const float* __restrict__ bias)
{
    extern __shared__ char smem[];
    int bz = blockIdx.z;
    const __half* Ab = A + (long)bz * sA;
    const __half* Wb = W + (long)bz * sB;
    float*        Cb = C + (long)bz * sC;
    int bm = blockIdx.y * 128, bn = blockIdx.x * 128;
    int tid  = threadIdx.x;
    int warp = tid >> 5, lane = tid & 31;
    int wm = warp >> 2, wn = warp & 3;
    int g  = lane >> 2, t4 = lane & 3;

    uint32_t sAu = (uint32_t)__cvta_generic_to_shared(smem);
    uint32_t sBu = sAu + 3*GSTG;

    // ldmatrix per-lane row / column-chunk components
    int arow = lane & 15;
    int achk = lane >> 4;                  // 0/1: k-half select (16B chunk)
    int brow = ((lane >> 4) << 3) + (lane & 7);
    int bchk = (lane >> 3) & 1;

    float acc[4][4][4];
    #pragma unroll
    for (int i = 0; i < 4; i++)
        #pragma unroll
        for (int j = 0; j < 4; j++)
            #pragma unroll
            for (int q = 0; q < 4; q++) acc[i][j][q] = 0.f;

    const int KT = K / 64;

    // per stage: each operand 128 rows x 8 chunks of 16B; 4 cp/thread each
    #define LOADTILE(st, k0)                                                  \
    do {                                                                      \
        _Pragma("unroll")                                                     \
        for (int it = 0; it < 4; it++) {                                      \
            int idx = tid + it*256;                                           \
            int row = idx >> 3, c8 = idx & 7;                                 \
            int sc = c8 ^ (row & 7);                                          \
            cp16(sAu + (st)*GSTG + row*128 + sc*16,                           \
                 &Ab[(long)(bm+row)*lda + (k0) + c8*8], true);                \
        }                                                                     \
        _Pragma("unroll")                                                     \
        for (int it = 0; it < 4; it++) {                                      \
            int idx = tid + it*256;                                           \
            int row = idx >> 3, c8 = idx & 7;                                 \
            int sc = c8 ^ (row & 7);                                          \
            int gn = bn + row; bool p = gn < N;                               \
            cp16(sBu + (st)*GSTG + row*128 + sc*16,                           \
                 &Wb[(long)(p ? gn : 0)*ldb + (k0) + c8*8], p);               \
        }                                                                     \
    } while (0)

    LOADTILE(0, 0);
    asm volatile("cp.async.commit_group;");
    if (KT > 1) LOADTILE(1, 64);
    asm volatile("cp.async.commit_group;");

    for (int kt = 0; kt < KT; kt++) {
        asm volatile("cp.async.wait_group 1;" ::: "memory");
        __syncthreads();
        if (kt + 2 < KT) LOADTILE((kt+2) % 3, (kt+2)*64);
        asm volatile("cp.async.commit_group;");

        int st = kt % 3;
        #pragma unroll
        for (int ks = 0; ks < 4; ks++) {
            uint32_t af[4][4], bf[4][2];
            #pragma unroll
            for (int mt = 0; mt < 4; mt++) {
                int r = wm*64 + mt*16 + arow;
                int chk = (ks*2 + achk) ^ (r & 7);
                ldsm4(af[mt], sAu + st*GSTG + r*128 + chk*16);
            }
            #pragma unroll
            for (int np = 0; np < 2; np++) {
                int r = wn*32 + np*16 + brow;
                int chk = (ks*2 + bchk) ^ (r & 7);
                uint32_t t[4];
                ldsm4(t, sBu + st*GSTG + r*128 + chk*16);
                bf[np*2  ][0] = t[0]; bf[np*2  ][1] = t[1];
                bf[np*2+1][0] = t[2]; bf[np*2+1][1] = t[3];
            }
            #pragma unroll
            for (int mt = 0; mt < 4; mt++)
                #pragma unroll
                for (int nt = 0; nt < 4; nt++)
                    MMA16(acc[mt][nt], af[mt], bf[nt]);
        }
        __syncthreads();
    }
    #undef LOADTILE

    #pragma unroll
    for (int mt = 0; mt < 4; mt++) {
        int row0 = bm + wm*64 + mt*16 + g;
        #pragma unroll
        for (int nt = 0; nt < 4; nt++) {
            int col0 = bn + wn*32 + nt*8 + 2*t4;
            if (col0 < N) {
                float b0 = bias ? bias[col0] : 0.f;
                Cb[(long)row0*ldc + col0] = acc[mt][nt][0] + b0;
                Cb[(long)(row0+8)*ldc + col0] = acc[mt][nt][2] + b0;
            }
            if (col0+1 < N) {
                float b1 = bias ? bias[col0+1] : 0.f;
                Cb[(long)row0*ldc + col0+1] = acc[mt][nt][1] + b1;
                Cb[(long)(row0+8)*ldc + col0+1] = acc[mt][nt][3] + b1;
            }
        }
    }
}

// =============== scan GEMMs: 128x128 tile, K-step 32, fp16 ================
#define SS 42

struct ZIdx { int b, c, h; };
__device__ __forceinline__ ZIdx zdec(int z) {
    ZIdx r; r.h = z % N_HEADS; int bc = z / N_HEADS;
    r.c = bc % NCHUNK; r.b = bc / NCHUNK; return r;
}

template<int STAGEA, int STAGEB, int OUTMODE>
__device__ __forceinline__ void scan_gemm_core(
    const __half* Ag, long lda,
    const __half* Bg, long ldb,
    float* Cg, long ldc,
    int KT)
{
    __shared__ __half As[128][SS];
    __shared__ __half Bs[128][SS];
    int tid = threadIdx.x;
    int warp = tid >> 5, lane = tid & 31;
    int wm = warp >> 2, wn = warp & 3;
    int g = lane >> 2, t4 = lane & 3;

    float acc[4][4][4];
    #pragma unroll
    for (int i = 0; i < 4; i++)
        #pragma unroll
        for (int j = 0; j < 4; j++)
            #pragma unroll
            for (int q = 0; q < 4; q++) acc[i][j][q] = 0.f;

    for (int kt = 0; kt < KT; kt++) {
        int k0 = kt * 32;
        if (STAGEA == 0) {
            #pragma unroll
            for (int i = 0; i < 8; i++) {
                int idx = tid + i*256;
                int row = idx >> 4, c2 = (idx & 15) * 2;
                *(__half2*)&As[row][c2] = *(const __half2*)&Ag[(long)row*lda + k0 + c2];
            }
        } else {
            #pragma unroll
            for (int i = 0; i < 8; i++) {
                int idx = tid + i*256;
                int k = idx >> 6, m2 = (idx & 63) * 2;
                __half2 v = *(const __half2*)&Ag[(long)(k0+k)*lda + m2];
                As[m2  ][k] = __low2half(v);
                As[m2+1][k] = __high2half(v);
            }
        }
        if (STAGEB == 0) {
            #pragma unroll
            for (int i = 0; i < 8; i++) {
                int idx = tid + i*256;
                int row = idx >> 4, c2 = (idx & 15) * 2;
                *(__half2*)&Bs[row][c2] = *(const __half2*)&Bg[(long)row*ldb + k0 + c2];
            }
        } else {
            #pragma unroll
            for (int i = 0; i < 8; i++) {
                int idx = tid + i*256;
                int k = idx >> 6, n2 = (idx & 63) * 2;
                __half2 v = *(const __half2*)&Bg[(long)(k0+k)*ldb + n2];
                Bs[n2  ][k] = __low2half(v);
                Bs[n2+1][k] = __high2half(v);
            }
        }
        __syncthreads();
        #pragma unroll
        for (int ks = 0; ks < 2; ks++) {
            int kb = ks * 16;
            uint32_t af[4][4], bf[4][2];
            #pragma unroll
            for (int mt = 0; mt < 4; mt++) {
                int r0 = wm*64 + mt*16 + g;
                af[mt][0] = *(const uint32_t*)&As[r0  ][kb + t4*2    ];
                af[mt][1] = *(const uint32_t*)&As[r0+8][kb + t4*2    ];
                af[mt][2] = *(const uint32_t*)&As[r0  ][kb + t4*2 + 8];
                af[mt][3] = *(const uint32_t*)&As[r0+8][kb + t4*2 + 8];
            }
            #pragma unroll
            for (int nt = 0; nt < 4; nt++) {
                int cc = wn*32 + nt*8 + g;
                bf[nt][0] = *(const uint32_t*)&Bs[cc][kb + t4*2    ];
                bf[nt][1] = *(const uint32_t*)&Bs[cc][kb + t4*2 + 8];
            }
            #pragma unroll
            for (int mt = 0; mt < 4; mt++)
                #pragma unroll
                for (int nt = 0; nt < 4; nt++)
                    MMA16(acc[mt][nt], af[mt], bf[nt]);
        }
        __syncthreads();
    }
    #pragma unroll
    for (int mt = 0; mt < 4; mt++) {
        int row0 = wm*64 + mt*16 + g;
        #pragma unroll
        for (int nt = 0; nt < 4; nt++) {
            int col0 = wn*32 + nt*8 + 2*t4;
            if (OUTMODE == 2) {
                Cg[(long)row0*ldc + col0  ] += acc[mt][nt][0];
                Cg[(long)row0*ldc + col0+1] += acc[mt][nt][1];
                Cg[(long)(row0+8)*ldc + col0  ] += acc[mt][nt][2];
                Cg[(long)(row0+8)*ldc + col0+1] += acc[mt][nt][3];
            } else {
                Cg[(long)row0*ldc + col0  ] = acc[mt][nt][0];
                Cg[(long)row0*ldc + col0+1] = acc[mt][nt][1];
                Cg[(long)(row0+8)*ldc + col0  ] = acc[mt][nt][2];
                Cg[(long)(row0+8)*ldc + col0+1] = acc[mt][nt][3];
            }
        }
    }
}

__global__ __launch_bounds__(256)
void k_ydiag2()
{
    int z = blockIdx.x, bm = blockIdx.y * 128;
    ZIdx zi = zdec(z);
    long brow = (long)zi.b*SEQ + zi.c*CHUNK;
    const __half* Ag = g_LG + (long)z*CHUNK*CHUNK + (long)bm*CHUNK;
    const __half* Bg = g_xdt_h + brow*D_INNER + zi.h*HEADDIM;
    float* Cg = g_y + (brow + bm)*D_INNER + zi.h*HEADDIM;
    int KT = (bm + 128) / 32;
    scan_gemm_core<0,1,0>(Ag, CHUNK, Bg, D_INNER, Cg, D_INNER, KT);
}

__global__ __launch_bounds__(256)
void k_states2()
{
    int z = blockIdx.x;
    ZIdx zi = zdec(z);
    long brow = (long)zi.b*SEQ + zi.c*CHUNK;
    const __half* Ag = g_xdt_h + brow*D_INNER + zi.h*HEADDIM;
    const __half* Bg = g_Bdec + (long)z*CHUNK*D_STATE;
    float* Cg = g_states + (long)z*HEADDIM*D_STATE;
    scan_gemm_core<1,1,1>(Ag, D_INNER, Bg, D_STATE, Cg, D_STATE, CHUNK/32);
}

__global__ __launch_bounds__(256)
void k_yoff2()
{
    int z = blockIdx.x, bm = blockIdx.y * 128;
    ZIdx zi = zdec(z);
    long brow = (long)zi.b*SEQ + zi.c*CHUNK;
    const __half* Ag = g_Cexp + (long)z*CHUNK*D_STATE + (long)bm*D_STATE;
    const __half* Bg = g_sin_h + (long)z*HEADDIM*D_STATE;
    float* Cg = g_y + (brow + bm)*D_INNER + zi.h*HEADDIM;
    scan_gemm_core<0,0,2>(Ag, D_STATE, Bg, D_STATE, Cg, D_INNER, D_STATE/32);
}

// ---------------- prep kernels --------------------------------------------
__global__ __launch_bounds__(256)
void k_prep_xdt()
{
    long i = (long)blockIdx.x * 256 + threadIdx.x;
    long n2 = (long)BATCH*SEQ*D_INNER/2;
    long stride = (long)gridDim.x * 256;
    for (; i < n2; i += stride) {
        long d2 = i % (D_INNER/2);
        long bs = i / (D_INNER/2);
        int d = (int)d2 * 2;
        int h = d >> 7;
        float dt = g_dt[bs*N_HEADS + h];
        float v0 = g_xBC[bs*CONV_DIM + d]     * dt;
        float v1 = g_xBC[bs*CONV_DIM + d + 1] * dt;
        *(__half2*)&g_xdt_h[bs*D_INNER + d] = __floats2half2_rn(v0, v1);
    }
}

__global__ __launch_bounds__(256)
void k_prep_lg()
{
    int z = blockIdx.x, lt = blockIdx.y;
    ZIdx zi = zdec(z);
    int bc = z / N_HEADS;
    const float* cum = g_dAcum + ((long)zi.b*N_HEADS + zi.h)*SEQ + zi.c*CHUNK;
    __shared__ float cs[CHUNK];
    if (threadIdx.x < CHUNK) cs[threadIdx.x] = cum[threadIdx.x];
    __syncthreads();
    const float* G = g_G + (long)bc*CHUNK*CHUNK;
    __half* LG = g_LG + (long)z*CHUNK*CHUNK;
    int tid = threadIdx.x;
    #pragma unroll 4
    for (int j = 0; j < 64; j++) {
        int lin = tid + j*256;
        int l = lt*64 + (lin >> 8);
        int s = lin & 255;
        float v = 0.f;
        if (s <= l) v = G[l*CHUNK + s] * fexp(cs[l] - cs[s]);
        LG[l*CHUNK + s] = __float2half_rn(v);
    }
}

__global__ __launch_bounds__(256)
void k_prep_bc()
{
    int z = blockIdx.x;
    ZIdx zi = zdec(z);
    const float* cum = g_dAcum + ((long)zi.b*N_HEADS + zi.h)*SEQ + zi.c*CHUNK;
    __shared__ float fb[CHUNK], fc[CHUNK];
    if (threadIdx.x < CHUNK) {
        float cl = cum[threadIdx.x];
        fb[threadIdx.x] = fexp(cum[CHUNK-1] - cl);
        fc[threadIdx.x] = fexp(cl);
    }
    __syncthreads();
    long brow = (long)zi.b*SEQ + zi.c*CHUNK;
    __half* Bd = g_Bdec + (long)z*CHUNK*D_STATE;
    __half* Ce = g_Cexp + (long)z*CHUNK*D_STATE;
    int tid = threadIdx.x;
    #pragma unroll 4
    for (int j = 0; j < 128; j++) {
        int lin = tid + j*256;
        int l = lin >> 7, n = lin & 127;
        long bs = brow + l;
        float Bv = __half2float(g_bc_h[bs*(2*D_STATE) + n]);
        float Cv = __half2float(g_bc_h[bs*(2*D_STATE) + D_STATE + n]);
        Bd[lin] = __float2half_rn(Bv * fb[l]);
        Ce[lin] = __float2half_rn(Cv * fc[l]);
    }
}

__global__ __launch_bounds__(256)
void k_tohalf(const float* __restrict__ src, __half* __restrict__ dst, long n2)
{
    long i = (long)blockIdx.x * 256 + threadIdx.x;
    long stride = (long)gridDim.x * 256;
    for (; i < n2; i += stride) {
        float2 v = *reinterpret_cast<const float2*>(src + i*2);
        *reinterpret_cast<__half2*>(dst + i*2) = __floats2half2_rn(v.x, v.y);
    }
}

// ---------------- exact fp32 dt projection + softplus ---------------------
__global__ __launch_bounds__(256)
void k_dtproj(const float* __restrict__ inputs,
              const float* __restrict__ in_proj_w,
              const float* __restrict__ in_proj_b,
              const float* __restrict__ dt_bias)
{
    __shared__ float xs[32][133];
    __shared__ float ws[32][133];
    int t = threadIdx.x;
    long r0 = (long)blockIdx.x * 32;
    int r = t >> 3;
    int hb = (t & 7) * 4;
    const float* Wdt = in_proj_w + (size_t)(D_INNER + CONV_DIM) * DIM;
    float acc[4] = {0.f, 0.f, 0.f, 0.f};
    for (int k0 = 0; k0 < DIM; k0 += 128) {
        #pragma unroll
        for (int i = 0; i < 4; i++) {
            int idx = t + i*256;
            int row = idx >> 5, c4 = (idx & 31) * 4;
            float4 v = *reinterpret_cast<const float4*>(&inputs[(r0+row)*DIM + k0 + c4]);
            xs[row][c4] = v.x; xs[row][c4+1] = v.y; xs[row][c4+2] = v.z; xs[row][c4+3] = v.w;
            float4 w = *reinterpret_cast<const float4*>(&Wdt[(size_t)row*DIM + k0 + c4]);
            ws[row][c4] = w.x; ws[row][c4+1] = w.y; ws[row][c4+2] = w.z; ws[row][c4+3] = w.w;
        }
        __syncthreads();
        #pragma unroll 8
        for (int k = 0; k < 128; k++) {
            float xv = xs[r][k];
            #pragma unroll
            for (int j = 0; j < 4; j++)
                acc[j] = fmaf(xv, ws[hb+j][k], acc[j]);
        }
        __syncthreads();
    }
    #pragma unroll
    for (int j = 0; j < 4; j++) {
        int h = hb + j;
        float x = acc[j] + in_proj_b[D_INNER + CONV_DIM + h] + dt_bias[h];
        g_dt[(r0 + r)*N_HEADS + h] = (x > 20.f) ? x : log1pf(expf(x));
    }
}

// ---------------- causal depthwise conv + SiLU ----------------------------
__global__ __launch_bounds__(256)
void k_conv(const float* __restrict__ conv_w, const float* __restrict__ conv_b)
{
    long i = (long)blockIdx.x * 256 + threadIdx.x;
    if (i >= (long)BATCH*SEQ*CONV_DIM) return;
    int c = (int)(i % CONV_DIM);
    long bs = i / CONV_DIM;
    int s = (int)(bs % SEQ);
    int b = (int)(bs / SEQ);
    float acc = conv_b[c];
    #pragma unroll
    for (int k = 0; k < D_CONV; k++) {
        int sp = s - (D_CONV-1) + k;
        if (sp >= 0)
            acc = fmaf(g_zxbcdt[((long)b*SEQ + sp)*D_IN_PROJ + D_INNER + c],
                       conv_w[c*D_CONV + k], acc);
    }
    float v = acc / (1.f + expf(-acc));
    g_xBC[i] = v;
    if (c >= D_INNER)
        g_bc_h[bs*(2*D_STATE) + (c - D_INNER)] = __float2half_rn(v);
}

// ---------------- chunk-local inclusive cumsum of A*dt --------------------
__global__ __launch_bounds__(CHUNK)
void k_cumsum(const float* __restrict__ A_log)
{
    int bz = blockIdx.x;
    int c = bz % NCHUNK; int bh = bz / NCHUNK;
    int h = bh % N_HEADS; int b = bh / N_HEADS;
    int l = threadIdx.x;
    int sg = c*CHUNK + l;
    float A = -expf(A_log[h]);
    float val = A * g_dt[((long)b*SEQ + sg)*N_HEADS + h];
    __shared__ float buf[CHUNK];
    buf[l] = val; __syncthreads();
    for (int off = 1; off < CHUNK; off <<= 1) {
        float t = (l >= off) ? buf[l-off] : 0.f;
        __syncthreads();
        buf[l] += t;
        __syncthreads();
    }
    g_dAcum[((long)b*N_HEADS + h)*SEQ + sg] = buf[l];
}

// ---------------- inter-chunk recurrence (-> Sin fp16) --------------------
__global__ __launch_bounds__(256)
void k_chunkrec()
{
    int bh = blockIdx.x;
    int h = bh % N_HEADS; int b = bh / N_HEADS;
    const float* cum = g_dAcum + (long)bh*SEQ;
    float csum[NCHUNK];
    #pragma unroll
    for (int c = 0; c < NCHUNK; c++) csum[c] = expf(cum[c*CHUNK + CHUNK-1]);
    for (int pn = threadIdx.x; pn < HEADDIM*D_STATE; pn += 256) {
        float carry = 0.f;
        #pragma unroll
        for (int c = 0; c < NCHUNK; c++) {
            long z = ((long)b*NCHUNK + c)*N_HEADS + h;
            long idx = z*HEADDIM*D_STATE + pn;
            g_sin_h[idx] = __float2half_rn(carry);
            carry = carry * csum[c] + g_states[idx];
        }
    }
}

// ---------------- gate (y + D*x) * silu(z) + RMSNorm -> fp16 --------------
__global__ __launch_bounds__(256)
void k_gatenorm(const float* __restrict__ norm_w, const float* __restrict__ Dv)
{
    long row = blockIdx.x;
    const float* zrow = g_zxbcdt + row*D_IN_PROJ;
    const float* xrow = g_xBC + row*CONV_DIM;
    float* yrow = g_y + row*D_INNER;
    __half* yh = g_y_h + row*D_INNER;
    float vals[16];
    float local = 0.f;
    #pragma unroll
    for (int i = 0; i < 16; i++) {
        int d = threadIdx.x + i*256;
        float z = zrow[d];
        float v = (yrow[d] + Dv[d >> 7] * xrow[d]) * (z / (1.f + expf(-z)));
        vals[i] = v;
        local += v * v;
    }
    __shared__ float red[256];
    red[threadIdx.x] = local; __syncthreads();
    for (int off = 128; off > 0; off >>= 1) {
        if (threadIdx.x < off) red[threadIdx.x] += red[threadIdx.x + off];
        __syncthreads();
    }
    float scale = rsqrtf(red[0] / D_INNER + EPS);
    #pragma unroll
    for (int i = 0; i < 16; i++) {
        int d = threadIdx.x + i*256;
        yh[d] = __float2half_rn(vals[i] * scale * norm_w[d]);
    }
}

// --------------------------------------------------------------------------
extern "C" void kernel_launch(void* const* d_in, const int* in_sizes, int n_in,
                              void* d_out, int out_size)
{
    const float* inputs     = (const float*)d_in[0];
    const float* in_proj_w  = (const float*)d_in[1];
    const float* in_proj_b  = (const float*)d_in[2];
    const float* out_proj_w = (const float*)d_in[3];
    const float* out_proj_b = (const float*)d_in[4];
    const float* conv_w     = (const float*)d_in[5];
    const float* conv_b     = (const float*)d_in[6];
    const float* dt_bias    = (const float*)d_in[7];
    const float* A_log      = (const float*)d_in[8];
    const float* Dv         = (const float*)d_in[9];
    const float* norm_w     = (const float*)d_in[10];
    float* out = (float*)d_out;

    float *zx, *Gp;
    __half *inh, *winh, *wouth, *yh, *bch;
    cudaGetSymbolAddress((void**)&zx,    g_zxbcdt);
    cudaGetSymbolAddress((void**)&Gp,    g_G);
    cudaGetSymbolAddress((void**)&inh,   g_in_h);
    cudaGetSymbolAddress((void**)&winh,  g_win_h);
    cudaGetSymbolAddress((void**)&wouth, g_wout_h);
    cudaGetSymbolAddress((void**)&yh,    g_y_h);
    cudaGetSymbolAddress((void**)&bch,   g_bc_h);

    cudaFuncSetAttribute(gemm_h, cudaFuncAttributeMaxDynamicSharedMemorySize, GSMEM);

    const int M = BATCH * SEQ;     // 4096

    // 0) fp16 mirrors
    k_tohalf<<<2048, 256>>>(inputs,     inh,   (long)M*DIM/2);
    k_tohalf<<<2048, 256>>>(in_proj_w,  winh,  (long)D_IN_PROJ*DIM/2);
    k_tohalf<<<2048, 256>>>(out_proj_w, wouth, (long)DIM*D_INNER/2);

    // 1) in_proj
    {
        dim3 grid((D_IN_PROJ + 127)/128, M/128, 1);
        gemm_h<<<grid, 256, GSMEM>>>(inh, DIM, 0, winh, DIM, 0,
                              zx, D_IN_PROJ, 0, M, D_IN_PROJ, DIM, in_proj_b);
    }
    // 2) exact dt projection
    k_dtproj<<<M/32, 256>>>(inputs, in_proj_w, in_proj_b, dt_bias);
    // 3) conv + silu
    k_conv<<<(int)(((long)BATCH*SEQ*CONV_DIM + 255)/256), 256>>>(conv_w, conv_b);
    // 4) cumsum
    k_cumsum<<<BATCH*N_HEADS*NCHUNK, CHUNK>>>(A_log);
    // 5) G = C @ B^T per (b,c)
    {
        dim3 grid(CHUNK/128, CHUNK/128, BATCH*NCHUNK);
        gemm_h<<<grid, 256, GSMEM>>>(bch + D_STATE, 2*D_STATE, (long)CHUNK*2*D_STATE,
                              bch,           2*D_STATE, (long)CHUNK*2*D_STATE,
                              Gp, CHUNK, (long)CHUNK*CHUNK,
                              CHUNK, CHUNK, D_STATE, nullptr);
    }
    // 6) preps
    k_prep_xdt<<<2048, 256>>>();
    {
        dim3 grid(NBCH, CHUNK/64);
        k_prep_lg<<<grid, 256>>>();
    }
    k_prep_bc<<<NBCH, 256>>>();
    // 7) Y_diag (tensor)
    {
        dim3 grid(NBCH, CHUNK/128);
        k_ydiag2<<<grid, 256>>>();
    }
    // 8) states (tensor)
    k_states2<<<NBCH, 256>>>();
    // 9) inter-chunk recurrence -> Sin fp16
    k_chunkrec<<<BATCH*N_HEADS, 256>>>();
    // 10) Y_off += (tensor)
    {
        dim3 grid(NBCH, CHUNK/128);
        k_yoff2<<<grid, 256>>>();
    }
    // 11) gate + D*x + RMSNorm -> fp16
    k_gatenorm<<<BATCH*SEQ, 256>>>(norm_w, Dv);
    // 12) out_proj
    {
        dim3 grid(DIM/128, M/128, 1);
        gemm_h<<<grid, 256, GSMEM>>>(yh, D_INNER, 0, wouth, D_INNER, 0,
                              out, DIM, 0, M, DIM, D_INNER, out_proj_b);
    }
}